// round 1
// baseline (speedup 1.0000x reference)
#include <cuda_runtime.h>
#include <cuda_bf16.h>
#include <math.h>

#define B_  2
#define S_  2048
#define D_  1024
#define H_  16
#define DH_ 64
#define NEGV -1000000000.0f

// ---------------- scratch (no allocations allowed) ----------------
__device__ float g_Q[B_ * S_ * D_];
__device__ float g_K[B_ * S_ * D_];
__device__ float g_V[B_ * S_ * D_];
__device__ float g_ctx[B_ * S_ * D_];

// ---------------- SGEMM: C[m,n] = sum_k A[m,k] * Bw[n,k] ----------------
// A: [M,K] row-major, Bw: [N,K] row-major (i.e. y = x @ W^T), C: [M,N]
// 128x128 block tile, 16 k-slice, 256 threads, 8x8 per-thread micro-tile.
__global__ __launch_bounds__(256) void sgemm_nt(
    const float* __restrict__ A, const float* __restrict__ Bw,
    float* __restrict__ C, int M, int N, int K)
{
    __shared__ float As[16][128];
    __shared__ float Bs[16][128];

    const int tid = threadIdx.x;
    const int tx = tid & 15;       // 0..15 -> N dir
    const int ty = tid >> 4;       // 0..15 -> M dir
    const int bm = blockIdx.y * 128;
    const int bn = blockIdx.x * 128;

    const float* Aptr = A + (size_t)bm * K;
    const float* Bptr = Bw + (size_t)bn * K;

    float acc[8][8];
#pragma unroll
    for (int i = 0; i < 8; i++)
#pragma unroll
        for (int j = 0; j < 8; j++) acc[i][j] = 0.0f;

    for (int k0 = 0; k0 < K; k0 += 16) {
        // load 128x16 tiles of A and B, transposed into smem
#pragma unroll
        for (int p = 0; p < 2; p++) {
            int i = tid + p * 256;          // 0..511
            int row = i >> 2;               // 0..127
            int c4 = (i & 3) * 4;           // 0,4,8,12
            float4 av = *(const float4*)(Aptr + (size_t)row * K + k0 + c4);
            As[c4 + 0][row] = av.x;
            As[c4 + 1][row] = av.y;
            As[c4 + 2][row] = av.z;
            As[c4 + 3][row] = av.w;
            float4 bv = *(const float4*)(Bptr + (size_t)row * K + k0 + c4);
            Bs[c4 + 0][row] = bv.x;
            Bs[c4 + 1][row] = bv.y;
            Bs[c4 + 2][row] = bv.z;
            Bs[c4 + 3][row] = bv.w;
        }
        __syncthreads();

#pragma unroll
        for (int kk = 0; kk < 16; kk++) {
            float ar[8], br[8];
            *(float4*)(ar)     = *(const float4*)&As[kk][ty * 8];
            *(float4*)(ar + 4) = *(const float4*)&As[kk][ty * 8 + 4];
            *(float4*)(br)     = *(const float4*)&Bs[kk][tx * 8];
            *(float4*)(br + 4) = *(const float4*)&Bs[kk][tx * 8 + 4];
#pragma unroll
            for (int i = 0; i < 8; i++)
#pragma unroll
                for (int j = 0; j < 8; j++)
                    acc[i][j] = fmaf(ar[i], br[j], acc[i][j]);
        }
        __syncthreads();
    }

#pragma unroll
    for (int i = 0; i < 8; i++) {
        float* cp = C + (size_t)(bm + ty * 8 + i) * N + bn + tx * 8;
        float4 v0 = make_float4(acc[i][0], acc[i][1], acc[i][2], acc[i][3]);
        float4 v1 = make_float4(acc[i][4], acc[i][5], acc[i][6], acc[i][7]);
        *(float4*)(cp)     = v0;
        *(float4*)(cp + 4) = v1;
    }
}

// ---------------- Flash attention ----------------
// grid: (S/64, H, B), block: 64 threads (1 query per thread).
// Q row held in registers; K/V tiles + scores in dynamic smem.
// All threads read the same K/V row element at a time -> smem broadcast.
#define ATTN_SMEM_FLOATS (4096 + 4096 + 64 * 65 + 64)
__global__ __launch_bounds__(64) void attn_kernel(
    const float* __restrict__ Qp, const float* __restrict__ Kp,
    const float* __restrict__ Vp, const int* __restrict__ mask,
    float* __restrict__ ctx)
{
    extern __shared__ float sm[];
    float* Ks = sm;                 // [64][64]
    float* Vs = sm + 4096;          // [64][64]
    float* Ss = sm + 8192;          // [64][65] (padded rows)
    int*   ms = (int*)(sm + 8192 + 64 * 65);  // [64]

    const int qt = blockIdx.x;
    const int h  = blockIdx.y;
    const int b  = blockIdx.z;
    const int r  = threadIdx.x;     // query within tile
    const int q  = qt * 64 + r;

    // load this thread's query row (64 floats) into registers
    float4 qreg[16];
    const float* qptr = Qp + ((size_t)b * S_ + q) * D_ + h * DH_;
#pragma unroll
    for (int i = 0; i < 16; i++)
        qreg[i] = *(const float4*)(qptr + 4 * i);

    float o[64];
#pragma unroll
    for (int d = 0; d < 64; d++) o[d] = 0.0f;
    float mrow = -1e30f;
    float lrow = 0.0f;

    const float* Kbase = Kp + (size_t)b * S_ * D_ + h * DH_;
    const float* Vbase = Vp + (size_t)b * S_ * D_ + h * DH_;
    const int* mbase = mask + b * S_;

    for (int kt = 0; kt <= qt; kt++) {
        const int k0 = kt * 64;
        __syncthreads();   // protect previous Vs reads
        // cooperative load of K/V tile: 1024 float4 each, 16 per thread
#pragma unroll
        for (int i = 0; i < 16; i++) {
            int idx = r + i * 64;          // 0..1023
            int row = idx >> 4;            // 0..63
            int c = (idx & 15) * 4;        // 0..60
            *(float4*)&Ks[row * 64 + c] =
                *(const float4*)(Kbase + (size_t)(k0 + row) * D_ + c);
            *(float4*)&Vs[row * 64 + c] =
                *(const float4*)(Vbase + (size_t)(k0 + row) * D_ + c);
        }
        ms[r] = mbase[k0 + r];
        __syncthreads();

        // scores for this thread's query row
        float tmax = -1e30f;
#pragma unroll 4
        for (int j = 0; j < 64; j++) {
            float s = 0.0f;
            const float* krow = &Ks[j * 64];
#pragma unroll
            for (int i = 0; i < 16; i++) {
                float4 kv = *(const float4*)(krow + 4 * i);
                s = fmaf(qreg[i].x, kv.x, s);
                s = fmaf(qreg[i].y, kv.y, s);
                s = fmaf(qreg[i].z, kv.z, s);
                s = fmaf(qreg[i].w, kv.w, s);
            }
            s *= 0.125f;                     // 1/sqrt(DH)
            if (ms[j] == 0) s += NEGV;       // padding mask
            if (k0 + j > q) s += NEGV;       // causal
            Ss[r * 65 + j] = s;
            tmax = fmaxf(tmax, s);
        }

        float mnew = fmaxf(mrow, tmax);
        float alpha = __expf(mrow - mnew);
        lrow *= alpha;
#pragma unroll
        for (int d = 0; d < 64; d++) o[d] *= alpha;

#pragma unroll 2
        for (int j = 0; j < 64; j++) {
            float p = __expf(Ss[r * 65 + j] - mnew);
            lrow += p;
            const float* vrow = &Vs[j * 64];
#pragma unroll
            for (int i = 0; i < 16; i++) {
                float4 vv = *(const float4*)(vrow + 4 * i);
                o[4 * i + 0] = fmaf(p, vv.x, o[4 * i + 0]);
                o[4 * i + 1] = fmaf(p, vv.y, o[4 * i + 1]);
                o[4 * i + 2] = fmaf(p, vv.z, o[4 * i + 2]);
                o[4 * i + 3] = fmaf(p, vv.w, o[4 * i + 3]);
            }
        }
        mrow = mnew;
    }

    const float inv = 1.0f / lrow;
    float* optr = ctx + ((size_t)b * S_ + q) * D_ + h * DH_;
#pragma unroll
    for (int i = 0; i < 16; i++) {
        float4 v = make_float4(o[4 * i] * inv, o[4 * i + 1] * inv,
                               o[4 * i + 2] * inv, o[4 * i + 3] * inv);
        *(float4*)(optr + 4 * i) = v;
    }
}

// ---------------- launch ----------------
extern "C" void kernel_launch(void* const* d_in, const int* in_sizes, int n_in,
                              void* d_out, int out_size)
{
    const float* q    = (const float*)d_in[0];
    const float* k    = (const float*)d_in[1];
    const float* v    = (const float*)d_in[2];
    const int*   mask = (const int*)d_in[3];
    const float* Wq   = (const float*)d_in[4];
    const float* Wk   = (const float*)d_in[5];
    const float* Wv   = (const float*)d_in[6];
    const float* Wo   = (const float*)d_in[7];
    float* out = (float*)d_out;

    float *gq, *gk, *gv, *gctx;
    cudaGetSymbolAddress((void**)&gq,  g_Q);
    cudaGetSymbolAddress((void**)&gk,  g_K);
    cudaGetSymbolAddress((void**)&gv,  g_V);
    cudaGetSymbolAddress((void**)&gctx, g_ctx);

    const int M = B_ * S_;   // 4096
    const int N = D_;        // 1024
    const int K = D_;        // 1024

    dim3 gg(N / 128, M / 128);
    sgemm_nt<<<gg, 256>>>(q, Wq, gq, M, N, K);
    sgemm_nt<<<gg, 256>>>(k, Wk, gk, M, N, K);
    sgemm_nt<<<gg, 256>>>(v, Wv, gv, M, N, K);

    const int smem_bytes = ATTN_SMEM_FLOATS * 4;
    cudaFuncSetAttribute(attn_kernel,
                         cudaFuncAttributeMaxDynamicSharedMemorySize,
                         smem_bytes);
    dim3 ga(S_ / 64, H_, B_);
    attn_kernel<<<ga, 64, smem_bytes>>>(gq, gk, gv, mask, gctx);

    sgemm_nt<<<gg, 256>>>(gctx, Wo, out, M, N, K);
}

// round 2
// speedup vs baseline: 1.0418x; 1.0418x over previous
#include <cuda_runtime.h>
#include <cuda_bf16.h>
#include <math.h>

#define B_  2
#define S_  2048
#define D_  1024
#define H_  16
#define DH_ 64
#define NEGV -1000000000.0f

// ---------------- scratch (no allocations allowed) ----------------
__device__ float g_Q[B_ * S_ * D_];
__device__ float g_K[B_ * S_ * D_];
__device__ float g_V[B_ * S_ * D_];
__device__ float g_ctx[B_ * S_ * D_];

// ---------------- SGEMM core (double-buffered) ----------------
// C[m,n] = sum_k A[m,k] * Bw[n,k]   (y = x @ W^T)
// 128x128 tile, 16-k slice, 256 threads, 8x8 micro-tile, 2-stage smem.
__device__ __forceinline__ void sgemm_body(
    const float* __restrict__ A, const float* __restrict__ Bw,
    float* __restrict__ C, int M, int N, int Kd,
    int bm, int bn,
    float (*As)[16][128], float (*Bs)[16][128])
{
    const int tid = threadIdx.x;
    const int tx = tid & 15;       // N dir
    const int ty = tid >> 4;       // M dir

    const float* Aptr = A + (size_t)bm * Kd;
    const float* Bptr = Bw + (size_t)bn * Kd;

    float acc[8][8];
#pragma unroll
    for (int i = 0; i < 8; i++)
#pragma unroll
        for (int j = 0; j < 8; j++) acc[i][j] = 0.0f;

    float4 sa[2], sb[2];

    // prologue: load slice 0
#pragma unroll
    for (int p = 0; p < 2; p++) {
        int i = tid + p * 256;
        int row = i >> 2;
        int c4 = (i & 3) * 4;
        sa[p] = *(const float4*)(Aptr + (size_t)row * Kd + c4);
        sb[p] = *(const float4*)(Bptr + (size_t)row * Kd + c4);
    }
#pragma unroll
    for (int p = 0; p < 2; p++) {
        int i = tid + p * 256;
        int row = i >> 2;
        int c4 = (i & 3) * 4;
        As[0][c4 + 0][row] = sa[p].x; As[0][c4 + 1][row] = sa[p].y;
        As[0][c4 + 2][row] = sa[p].z; As[0][c4 + 3][row] = sa[p].w;
        Bs[0][c4 + 0][row] = sb[p].x; Bs[0][c4 + 1][row] = sb[p].y;
        Bs[0][c4 + 2][row] = sb[p].z; Bs[0][c4 + 3][row] = sb[p].w;
    }
    __syncthreads();

    int buf = 0;
    for (int k0 = 0; k0 < Kd; k0 += 16) {
        const bool more = (k0 + 16) < Kd;
        if (more) {
#pragma unroll
            for (int p = 0; p < 2; p++) {
                int i = tid + p * 256;
                int row = i >> 2;
                int c4 = (i & 3) * 4;
                sa[p] = *(const float4*)(Aptr + (size_t)row * Kd + k0 + 16 + c4);
                sb[p] = *(const float4*)(Bptr + (size_t)row * Kd + k0 + 16 + c4);
            }
        }

#pragma unroll
        for (int kk = 0; kk < 16; kk++) {
            float ar[8], br[8];
            *(float4*)(ar)     = *(const float4*)&As[buf][kk][ty * 8];
            *(float4*)(ar + 4) = *(const float4*)&As[buf][kk][ty * 8 + 4];
            *(float4*)(br)     = *(const float4*)&Bs[buf][kk][tx * 8];
            *(float4*)(br + 4) = *(const float4*)&Bs[buf][kk][tx * 8 + 4];
#pragma unroll
            for (int i = 0; i < 8; i++)
#pragma unroll
                for (int j = 0; j < 8; j++)
                    acc[i][j] = fmaf(ar[i], br[j], acc[i][j]);
        }

        if (more) {
            int nb = buf ^ 1;
#pragma unroll
            for (int p = 0; p < 2; p++) {
                int i = tid + p * 256;
                int row = i >> 2;
                int c4 = (i & 3) * 4;
                As[nb][c4 + 0][row] = sa[p].x; As[nb][c4 + 1][row] = sa[p].y;
                As[nb][c4 + 2][row] = sa[p].z; As[nb][c4 + 3][row] = sa[p].w;
                Bs[nb][c4 + 0][row] = sb[p].x; Bs[nb][c4 + 1][row] = sb[p].y;
                Bs[nb][c4 + 2][row] = sb[p].z; Bs[nb][c4 + 3][row] = sb[p].w;
            }
            __syncthreads();
            buf = nb;
        }
    }

#pragma unroll
    for (int i = 0; i < 8; i++) {
        float* cp = C + (size_t)(bm + ty * 8 + i) * N + bn + tx * 8;
        *(float4*)(cp)     = make_float4(acc[i][0], acc[i][1], acc[i][2], acc[i][3]);
        *(float4*)(cp + 4) = make_float4(acc[i][4], acc[i][5], acc[i][6], acc[i][7]);
    }
}

// fused Q/K/V projections: blockIdx.z selects which projection
__global__ __launch_bounds__(256) void sgemm_qkv(
    const float* __restrict__ xq, const float* __restrict__ xk,
    const float* __restrict__ xv,
    const float* __restrict__ Wq, const float* __restrict__ Wk,
    const float* __restrict__ Wv,
    float* __restrict__ oq, float* __restrict__ ok, float* __restrict__ ov,
    int M, int N, int Kd)
{
    __shared__ float As[2][16][128];
    __shared__ float Bs[2][16][128];
    const int z = blockIdx.z;
    const float* A  = (z == 0) ? xq : (z == 1) ? xk : xv;
    const float* Bw = (z == 0) ? Wq : (z == 1) ? Wk : Wv;
    float* C        = (z == 0) ? oq : (z == 1) ? ok : ov;
    sgemm_body(A, Bw, C, M, N, Kd, blockIdx.y * 128, blockIdx.x * 128, As, Bs);
}

__global__ __launch_bounds__(256) void sgemm_nt(
    const float* __restrict__ A, const float* __restrict__ Bw,
    float* __restrict__ C, int M, int N, int Kd)
{
    __shared__ float As[2][16][128];
    __shared__ float Bs[2][16][128];
    sgemm_body(A, Bw, C, M, N, Kd, blockIdx.y * 128, blockIdx.x * 128, As, Bs);
}

// ---------------- Flash attention ----------------
// grid: (S/64, H, B), block: 64 threads (1 query per thread).
// Heavy blocks (large qt) scheduled first via reversed qt mapping.
#define ATTN_SMEM_FLOATS (4096 + 4096 + 64 * 65 + 64)
__global__ __launch_bounds__(64) void attn_kernel(
    const float* __restrict__ Qp, const float* __restrict__ Kp,
    const float* __restrict__ Vp, const int* __restrict__ mask,
    float* __restrict__ ctx)
{
    extern __shared__ float sm[];
    float* Ks = sm;                 // [64][64]
    float* Vs = sm + 4096;          // [64][64]
    float* Ss = sm + 8192;          // [64][65]
    int*   ms = (int*)(sm + 8192 + 64 * 65);

    const int qt = (gridDim.x - 1) - blockIdx.x;   // heavy first
    const int h  = blockIdx.y;
    const int b  = blockIdx.z;
    const int r  = threadIdx.x;
    const int q  = qt * 64 + r;

    float4 qreg[16];
    const float* qptr = Qp + ((size_t)b * S_ + q) * D_ + h * DH_;
#pragma unroll
    for (int i = 0; i < 16; i++)
        qreg[i] = *(const float4*)(qptr + 4 * i);

    float o[64];
#pragma unroll
    for (int d = 0; d < 64; d++) o[d] = 0.0f;
    float mrow = -1e30f;
    float lrow = 0.0f;

    const float* Kbase = Kp + (size_t)b * S_ * D_ + h * DH_;
    const float* Vbase = Vp + (size_t)b * S_ * D_ + h * DH_;
    const int* mbase = mask + b * S_;

    for (int kt = 0; kt <= qt; kt++) {
        const int k0 = kt * 64;
        __syncthreads();
#pragma unroll
        for (int i = 0; i < 16; i++) {
            int idx = r + i * 64;
            int row = idx >> 4;
            int c = (idx & 15) * 4;
            *(float4*)&Ks[row * 64 + c] =
                *(const float4*)(Kbase + (size_t)(k0 + row) * D_ + c);
            *(float4*)&Vs[row * 64 + c] =
                *(const float4*)(Vbase + (size_t)(k0 + row) * D_ + c);
        }
        ms[r] = mbase[k0 + r];
        __syncthreads();

        // scores: 4 independent FFMA chains (ILP 4)
        float tmax = -1e30f;
#pragma unroll 2
        for (int j = 0; j < 64; j++) {
            const float* krow = &Ks[j * 64];
            float a0 = 0.f, a1 = 0.f, a2 = 0.f, a3 = 0.f;
#pragma unroll
            for (int i = 0; i < 16; i += 4) {
                float4 k0v = *(const float4*)(krow + 4 * (i + 0));
                float4 k1v = *(const float4*)(krow + 4 * (i + 1));
                float4 k2v = *(const float4*)(krow + 4 * (i + 2));
                float4 k3v = *(const float4*)(krow + 4 * (i + 3));
                a0 = fmaf(qreg[i + 0].x, k0v.x, a0);
                a0 = fmaf(qreg[i + 0].y, k0v.y, a0);
                a0 = fmaf(qreg[i + 0].z, k0v.z, a0);
                a0 = fmaf(qreg[i + 0].w, k0v.w, a0);
                a1 = fmaf(qreg[i + 1].x, k1v.x, a1);
                a1 = fmaf(qreg[i + 1].y, k1v.y, a1);
                a1 = fmaf(qreg[i + 1].z, k1v.z, a1);
                a1 = fmaf(qreg[i + 1].w, k1v.w, a1);
                a2 = fmaf(qreg[i + 2].x, k2v.x, a2);
                a2 = fmaf(qreg[i + 2].y, k2v.y, a2);
                a2 = fmaf(qreg[i + 2].z, k2v.z, a2);
                a2 = fmaf(qreg[i + 2].w, k2v.w, a2);
                a3 = fmaf(qreg[i + 3].x, k3v.x, a3);
                a3 = fmaf(qreg[i + 3].y, k3v.y, a3);
                a3 = fmaf(qreg[i + 3].z, k3v.z, a3);
                a3 = fmaf(qreg[i + 3].w, k3v.w, a3);
            }
            float s = ((a0 + a1) + (a2 + a3)) * 0.125f;
            if (ms[j] == 0) s += NEGV;
            if (k0 + j > q) s += NEGV;
            Ss[r * 65 + j] = s;
            tmax = fmaxf(tmax, s);
        }

        float mnew = fmaxf(mrow, tmax);
        float alpha = __expf(mrow - mnew);
        lrow *= alpha;
#pragma unroll
        for (int d = 0; d < 64; d++) o[d] *= alpha;

#pragma unroll 2
        for (int j = 0; j < 64; j++) {
            float p = __expf(Ss[r * 65 + j] - mnew);
            lrow += p;
            const float* vrow = &Vs[j * 64];
#pragma unroll
            for (int i = 0; i < 16; i++) {
                float4 vv = *(const float4*)(vrow + 4 * i);
                o[4 * i + 0] = fmaf(p, vv.x, o[4 * i + 0]);
                o[4 * i + 1] = fmaf(p, vv.y, o[4 * i + 1]);
                o[4 * i + 2] = fmaf(p, vv.z, o[4 * i + 2]);
                o[4 * i + 3] = fmaf(p, vv.w, o[4 * i + 3]);
            }
        }
        mrow = mnew;
    }

    const float inv = 1.0f / lrow;
    float* optr = ctx + ((size_t)b * S_ + q) * D_ + h * DH_;
#pragma unroll
    for (int i = 0; i < 16; i++) {
        *(float4*)(optr + 4 * i) =
            make_float4(o[4 * i] * inv, o[4 * i + 1] * inv,
                        o[4 * i + 2] * inv, o[4 * i + 3] * inv);
    }
}

// ---------------- launch ----------------
extern "C" void kernel_launch(void* const* d_in, const int* in_sizes, int n_in,
                              void* d_out, int out_size)
{
    const float* q    = (const float*)d_in[0];
    const float* k    = (const float*)d_in[1];
    const float* v    = (const float*)d_in[2];
    const int*   mask = (const int*)d_in[3];
    const float* Wq   = (const float*)d_in[4];
    const float* Wk   = (const float*)d_in[5];
    const float* Wv   = (const float*)d_in[6];
    const float* Wo   = (const float*)d_in[7];
    float* out = (float*)d_out;

    float *gq, *gk, *gv, *gctx;
    cudaGetSymbolAddress((void**)&gq,  g_Q);
    cudaGetSymbolAddress((void**)&gk,  g_K);
    cudaGetSymbolAddress((void**)&gv,  g_V);
    cudaGetSymbolAddress((void**)&gctx, g_ctx);

    const int M = B_ * S_;   // 4096
    const int N = D_;        // 1024
    const int K = D_;        // 1024

    dim3 gqkv(N / 128, M / 128, 3);
    sgemm_qkv<<<gqkv, 256>>>(q, k, v, Wq, Wk, Wv, gq, gk, gv, M, N, K);

    const int smem_bytes = ATTN_SMEM_FLOATS * 4;
    cudaFuncSetAttribute(attn_kernel,
                         cudaFuncAttributeMaxDynamicSharedMemorySize,
                         smem_bytes);
    dim3 ga(S_ / 64, H_, B_);
    attn_kernel<<<ga, 64, smem_bytes>>>(gq, gk, gv, mask, gctx);

    dim3 gg(N / 128, M / 128);
    sgemm_nt<<<gg, 256>>>(gctx, Wo, out, M, N, K);
}

// round 4
// speedup vs baseline: 1.3943x; 1.3384x over previous
#include <cuda_runtime.h>
#include <cuda_bf16.h>
#include <cstdint>
#include <math.h>

#define B_  2
#define S_  2048
#define D_  1024
#define H_  16
#define DH_ 64
#define NEGV -1000000000.0f

// ================= helpers =================
__device__ __forceinline__ uint32_t smem_to_u32(const void* p) {
    uint32_t a;
    asm("{ .reg .u64 t; cvta.to.shared.u64 t, %1; cvt.u32.u64 %0, t; }"
        : "=r"(a) : "l"(p));
    return a;
}
__device__ __forceinline__ void ldsm4(uint32_t* r, uint32_t addr) {
    asm volatile("ldmatrix.sync.aligned.m8n8.x4.shared.b16 {%0,%1,%2,%3}, [%4];"
        : "=r"(r[0]), "=r"(r[1]), "=r"(r[2]), "=r"(r[3]) : "r"(addr));
}
__device__ __forceinline__ void mma16816(float* d, const uint32_t* a, const uint32_t* b) {
    asm volatile("mma.sync.aligned.m16n8k16.row.col.f32.bf16.bf16.f32 "
        "{%0,%1,%2,%3}, {%4,%5,%6,%7}, {%8,%9}, {%0,%1,%2,%3};"
        : "+f"(d[0]), "+f"(d[1]), "+f"(d[2]), "+f"(d[3])
        : "r"(a[0]), "r"(a[1]), "r"(a[2]), "r"(a[3]), "r"(b[0]), "r"(b[1]));
}
__device__ __forceinline__ void cp16(uint32_t smem, const void* g) {
    asm volatile("cp.async.cg.shared.global [%0], [%1], 16;" :: "r"(smem), "l"(g));
}
#define CP_COMMIT() asm volatile("cp.async.commit_group;" ::: "memory")
#define CP_WAIT0()  asm volatile("cp.async.wait_group 0;" ::: "memory")

// ================= scratch =================
__device__ float g_Q[B_ * S_ * D_];
__device__ float g_K[B_ * S_ * D_];
__device__ float g_V[B_ * S_ * D_];
__device__ float g_ctx[B_ * S_ * D_];

__device__ __nv_bfloat16 g_qhi[B_ * S_ * D_], g_qlo[B_ * S_ * D_];
__device__ __nv_bfloat16 g_khi[B_ * S_ * D_], g_klo[B_ * S_ * D_];
__device__ __nv_bfloat16 g_vhi[B_ * S_ * D_], g_vlo[B_ * S_ * D_];
__device__ __nv_bfloat16 g_chi[B_ * S_ * D_], g_clo[B_ * S_ * D_];
__device__ __nv_bfloat16 g_wqhi[D_ * D_], g_wqlo[D_ * D_];
__device__ __nv_bfloat16 g_wkhi[D_ * D_], g_wklo[D_ * D_];
__device__ __nv_bfloat16 g_wvhi[D_ * D_], g_wvlo[D_ * D_];
__device__ __nv_bfloat16 g_wohi[D_ * D_], g_wolo[D_ * D_];

// ================= fp32 -> bf16 hi/lo split =================
struct ConvArgs { const float* s; __nv_bfloat16* h; __nv_bfloat16* l; };

__global__ __launch_bounds__(256) void convert_hilo(ConvArgs a0, ConvArgs a1,
                                                    ConvArgs a2, ConvArgs a3) {
    ConvArgs a = (blockIdx.z == 0) ? a0 : (blockIdx.z == 1) ? a1
               : (blockIdx.z == 2) ? a2 : a3;
    size_t i4 = (size_t)blockIdx.x * 256 + threadIdx.x;
    float4 x = ((const float4*)a.s)[i4];
    __nv_bfloat16 h0 = __float2bfloat16_rn(x.x);
    __nv_bfloat16 h1 = __float2bfloat16_rn(x.y);
    __nv_bfloat16 h2 = __float2bfloat16_rn(x.z);
    __nv_bfloat16 h3 = __float2bfloat16_rn(x.w);
    float r0 = x.x - __bfloat162float(h0);
    float r1 = x.y - __bfloat162float(h1);
    float r2 = x.z - __bfloat162float(h2);
    float r3 = x.w - __bfloat162float(h3);
    __nv_bfloat162 hp0 = __halves2bfloat162(h0, h1);
    __nv_bfloat162 hp1 = __halves2bfloat162(h2, h3);
    __nv_bfloat162 lp0 = __halves2bfloat162(__float2bfloat16_rn(r0), __float2bfloat16_rn(r1));
    __nv_bfloat162 lp1 = __halves2bfloat162(__float2bfloat16_rn(r2), __float2bfloat16_rn(r3));
    uint2 hv, lv;
    hv.x = reinterpret_cast<uint32_t&>(hp0); hv.y = reinterpret_cast<uint32_t&>(hp1);
    lv.x = reinterpret_cast<uint32_t&>(lp0); lv.y = reinterpret_cast<uint32_t&>(lp1);
    ((uint2*)a.h)[i4] = hv;
    ((uint2*)a.l)[i4] = lv;
}

// ================= mma.sync GEMM (bf16 hi/lo, 3 passes) =================
// C[m,n] = sum_k A[m,k]*B[n,k] (fp32 via hi/lo bf16). K=1024.
// CTA: 128x128, 8 warps (4x2), warp tile 32x64. K-chunk 32, cp.async double buffer.
// smem per stage: 4 arrays (Ah,Al,Bh,Bl) of [128 rows][32 bf16 + 8 pad] = 10240B.
struct GemmArgs {
    const __nv_bfloat16 *ah, *al, *bh, *bl;
    float* c;
};

#define GEMM_SMEM_BYTES (2 * 4 * 10240)   // 81920
#define ROWB 80                            // padded row stride in bytes

__global__ __launch_bounds__(256) void gemm_mma(GemmArgs ga0, GemmArgs ga1, GemmArgs ga2) {
    extern __shared__ char smx[];
    const GemmArgs g = (blockIdx.z == 0) ? ga0 : (blockIdx.z == 1) ? ga1 : ga2;

    const int tid  = threadIdx.x;
    const int lane = tid & 31;
    const int wid  = tid >> 5;
    const int bm = blockIdx.y * 128;
    const int bn = blockIdx.x * 128;
    const uint32_t sbase = smem_to_u32(smx);

    const int m0 = (wid >> 1) * 32;
    const int n0 = (wid & 1) * 64;

    float acc[2][8][4];
#pragma unroll
    for (int mt = 0; mt < 2; mt++)
#pragma unroll
        for (int nt = 0; nt < 8; nt++)
#pragma unroll
            for (int i = 0; i < 4; i++) acc[mt][nt][i] = 0.0f;

    // lane-dependent ldmatrix offsets
    const uint32_t aRow = lane & 15;
    const uint32_t aK   = (lane >> 4) * 8;
    const uint32_t bN   = (lane & 7) + ((lane >> 4) & 1) * 8;
    const uint32_t bK   = ((lane >> 3) & 1) * 8;

    // issue cp.async for chunk c into stage st
    auto load_chunk = [&](int c, int st) {
        const int k0 = c * 32;
#pragma unroll
        for (int p = 0; p < 8; p++) {
            int idx = tid + p * 256;          // 0..2047
            int arr = idx >> 9;               // 0..3
            int r   = (idx >> 2) & 127;
            int c8  = (idx & 3) * 8;
            const __nv_bfloat16* src = (arr == 0) ? g.ah : (arr == 1) ? g.al
                                    : (arr == 2) ? g.bh : g.bl;
            int grow = ((arr < 2) ? bm : bn) + r;
            cp16(sbase + (uint32_t)(st * 4 + arr) * 10240 + r * ROWB + c8 * 2,
                 src + (size_t)grow * 1024 + k0 + c8);
        }
        CP_COMMIT();
    };

    load_chunk(0, 0);

    for (int c = 0; c < 32; c++) {
        const int st = c & 1;
        CP_WAIT0();
        __syncthreads();
        if (c < 31) load_chunk(c + 1, st ^ 1);

        const uint32_t aH = sbase + (uint32_t)(st * 4 + 0) * 10240;
        const uint32_t aL = aH + 10240;
        const uint32_t bH = aL + 10240;
        const uint32_t bL = bH + 10240;

#pragma unroll
        for (int pass = 0; pass < 3; pass++) {
            const uint32_t ab = (pass == 2) ? aL : aH;
            const uint32_t bb = (pass == 1) ? bL : bH;
#pragma unroll
            for (int ks = 0; ks < 2; ks++) {
                uint32_t af[2][4], bf[4][4];
#pragma unroll
                for (int mt = 0; mt < 2; mt++)
                    ldsm4(af[mt], ab + (m0 + mt * 16 + aRow) * ROWB + (ks * 16 + aK) * 2);
#pragma unroll
                for (int np = 0; np < 4; np++)
                    ldsm4(bf[np], bb + (n0 + np * 16 + bN) * ROWB + (ks * 16 + bK) * 2);
#pragma unroll
                for (int mt = 0; mt < 2; mt++)
#pragma unroll
                    for (int nt = 0; nt < 8; nt++)
                        mma16816(acc[mt][nt], af[mt], &bf[nt >> 1][(nt & 1) * 2]);
            }
        }
    }

    // epilogue
#pragma unroll
    for (int mt = 0; mt < 2; mt++)
#pragma unroll
        for (int nt = 0; nt < 8; nt++) {
            int row = bm + m0 + mt * 16 + (lane >> 2);
            int col = bn + n0 + nt * 8 + (lane & 3) * 2;
            float2 v0 = make_float2(acc[mt][nt][0], acc[mt][nt][1]);
            float2 v1 = make_float2(acc[mt][nt][2], acc[mt][nt][3]);
            *(float2*)(g.c + (size_t)row * 1024 + col) = v0;
            *(float2*)(g.c + (size_t)(row + 8) * 1024 + col) = v1;
        }
}

// ================= Flash attention (SIMT, from best passing kernel) =================
#define ATTN_SMEM_FLOATS (4096 + 4096 + 64 * 65 + 64)
__global__ __launch_bounds__(64) void attn_kernel(
    const float* __restrict__ Qp, const float* __restrict__ Kp,
    const float* __restrict__ Vp, const int* __restrict__ mask,
    float* __restrict__ ctx)
{
    extern __shared__ float smf[];
    float* Ks = smf;
    float* Vs = smf + 4096;
    float* Ss = smf + 8192;
    int*   ms = (int*)(smf + 8192 + 64 * 65);

    const int qt = (gridDim.x - 1) - blockIdx.x;
    const int h  = blockIdx.y;
    const int b  = blockIdx.z;
    const int r  = threadIdx.x;
    const int q  = qt * 64 + r;

    float4 qreg[16];
    const float* qptr = Qp + ((size_t)b * S_ + q) * D_ + h * DH_;
#pragma unroll
    for (int i = 0; i < 16; i++)
        qreg[i] = *(const float4*)(qptr + 4 * i);

    float o[64];
#pragma unroll
    for (int d = 0; d < 64; d++) o[d] = 0.0f;
    float mrow = -1e30f;
    float lrow = 0.0f;

    const float* Kbase = Kp + (size_t)b * S_ * D_ + h * DH_;
    const float* Vbase = Vp + (size_t)b * S_ * D_ + h * DH_;
    const int* mbase = mask + b * S_;

    for (int kt = 0; kt <= qt; kt++) {
        const int k0 = kt * 64;
        __syncthreads();
#pragma unroll
        for (int i = 0; i < 16; i++) {
            int idx = r + i * 64;
            int row = idx >> 4;
            int c = (idx & 15) * 4;
            *(float4*)&Ks[row * 64 + c] =
                *(const float4*)(Kbase + (size_t)(k0 + row) * D_ + c);
            *(float4*)&Vs[row * 64 + c] =
                *(const float4*)(Vbase + (size_t)(k0 + row) * D_ + c);
        }
        ms[r] = mbase[k0 + r];
        __syncthreads();

        float tmax = -1e30f;
#pragma unroll 2
        for (int j = 0; j < 64; j++) {
            const float* krow = &Ks[j * 64];
            float a0 = 0.f, a1 = 0.f, a2 = 0.f, a3 = 0.f;
#pragma unroll
            for (int i = 0; i < 16; i += 4) {
                float4 k0v = *(const float4*)(krow + 4 * (i + 0));
                float4 k1v = *(const float4*)(krow + 4 * (i + 1));
                float4 k2v = *(const float4*)(krow + 4 * (i + 2));
                float4 k3v = *(const float4*)(krow + 4 * (i + 3));
                a0 = fmaf(qreg[i + 0].x, k0v.x, a0);
                a0 = fmaf(qreg[i + 0].y, k0v.y, a0);
                a0 = fmaf(qreg[i + 0].z, k0v.z, a0);
                a0 = fmaf(qreg[i + 0].w, k0v.w, a0);
                a1 = fmaf(qreg[i + 1].x, k1v.x, a1);
                a1 = fmaf(qreg[i + 1].y, k1v.y, a1);
                a1 = fmaf(qreg[i + 1].z, k1v.z, a1);
                a1 = fmaf(qreg[i + 1].w, k1v.w, a1);
                a2 = fmaf(qreg[i + 2].x, k2v.x, a2);
                a2 = fmaf(qreg[i + 2].y, k2v.y, a2);
                a2 = fmaf(qreg[i + 2].z, k2v.z, a2);
                a2 = fmaf(qreg[i + 2].w, k2v.w, a2);
                a3 = fmaf(qreg[i + 3].x, k3v.x, a3);
                a3 = fmaf(qreg[i + 3].y, k3v.y, a3);
                a3 = fmaf(qreg[i + 3].z, k3v.z, a3);
                a3 = fmaf(qreg[i + 3].w, k3v.w, a3);
            }
            float s = ((a0 + a1) + (a2 + a3)) * 0.125f;
            if (ms[j] == 0) s += NEGV;
            if (k0 + j > q) s += NEGV;
            Ss[r * 65 + j] = s;
            tmax = fmaxf(tmax, s);
        }

        float mnew = fmaxf(mrow, tmax);
        float alpha = __expf(mrow - mnew);
        lrow *= alpha;
#pragma unroll
        for (int d = 0; d < 64; d++) o[d] *= alpha;

#pragma unroll 2
        for (int j = 0; j < 64; j++) {
            float p = __expf(Ss[r * 65 + j] - mnew);
            lrow += p;
            const float* vrow = &Vs[j * 64];
#pragma unroll
            for (int i = 0; i < 16; i++) {
                float4 vv = *(const float4*)(vrow + 4 * i);
                o[4 * i + 0] = fmaf(p, vv.x, o[4 * i + 0]);
                o[4 * i + 1] = fmaf(p, vv.y, o[4 * i + 1]);
                o[4 * i + 2] = fmaf(p, vv.z, o[4 * i + 2]);
                o[4 * i + 3] = fmaf(p, vv.w, o[4 * i + 3]);
            }
        }
        mrow = mnew;
    }

    const float inv = 1.0f / lrow;
    float* optr = ctx + ((size_t)b * S_ + q) * D_ + h * DH_;
#pragma unroll
    for (int i = 0; i < 16; i++) {
        *(float4*)(optr + 4 * i) =
            make_float4(o[4 * i] * inv, o[4 * i + 1] * inv,
                        o[4 * i + 2] * inv, o[4 * i + 3] * inv);
    }
}

// ================= launch =================
extern "C" void kernel_launch(void* const* d_in, const int* in_sizes, int n_in,
                              void* d_out, int out_size)
{
    const float* q    = (const float*)d_in[0];
    const float* k    = (const float*)d_in[1];
    const float* v    = (const float*)d_in[2];
    const int*   mask = (const int*)d_in[3];
    const float* Wq   = (const float*)d_in[4];
    const float* Wk   = (const float*)d_in[5];
    const float* Wv   = (const float*)d_in[6];
    const float* Wo   = (const float*)d_in[7];
    float* out = (float*)d_out;

    float *gQ, *gK, *gV, *gctx;
    cudaGetSymbolAddress((void**)&gQ,  g_Q);
    cudaGetSymbolAddress((void**)&gK,  g_K);
    cudaGetSymbolAddress((void**)&gV,  g_V);
    cudaGetSymbolAddress((void**)&gctx, g_ctx);

    __nv_bfloat16 *qh,*ql,*kh,*kl,*vh,*vl,*ch,*cl;
    __nv_bfloat16 *wqh,*wql,*wkh,*wkl,*wvh,*wvl,*woh,*wol;
    cudaGetSymbolAddress((void**)&qh, g_qhi); cudaGetSymbolAddress((void**)&ql, g_qlo);
    cudaGetSymbolAddress((void**)&kh, g_khi); cudaGetSymbolAddress((void**)&kl, g_klo);
    cudaGetSymbolAddress((void**)&vh, g_vhi); cudaGetSymbolAddress((void**)&vl, g_vlo);
    cudaGetSymbolAddress((void**)&ch, g_chi); cudaGetSymbolAddress((void**)&cl, g_clo);
    cudaGetSymbolAddress((void**)&wqh, g_wqhi); cudaGetSymbolAddress((void**)&wql, g_wqlo);
    cudaGetSymbolAddress((void**)&wkh, g_wkhi); cudaGetSymbolAddress((void**)&wkl, g_wklo);
    cudaGetSymbolAddress((void**)&wvh, g_wvhi); cudaGetSymbolAddress((void**)&wvl, g_wvlo);
    cudaGetSymbolAddress((void**)&woh, g_wohi); cudaGetSymbolAddress((void**)&wol, g_wolo);

    const int ME = B_ * S_ * D_;   // 4 M elts
    const int WE = D_ * D_;        // 1 M elts

    // convert inputs (q, k, v)
    {
        ConvArgs a0{q, qh, ql}, a1{k, kh, kl}, a2{v, vh, vl};
        dim3 gr(ME / 1024, 1, 3);
        convert_hilo<<<gr, 256>>>(a0, a1, a2, a2);
    }
    // convert weights
    {
        ConvArgs a0{Wq, wqh, wql}, a1{Wk, wkh, wkl}, a2{Wv, wvh, wvl}, a3{Wo, woh, wol};
        dim3 gr(WE / 1024, 1, 4);
        convert_hilo<<<gr, 256>>>(a0, a1, a2, a3);
    }

    cudaFuncSetAttribute(gemm_mma, cudaFuncAttributeMaxDynamicSharedMemorySize,
                         GEMM_SMEM_BYTES);

    // QKV projections
    {
        GemmArgs g0{qh, ql, wqh, wql, gQ};
        GemmArgs g1{kh, kl, wkh, wkl, gK};
        GemmArgs g2{vh, vl, wvh, wvl, gV};
        dim3 gr(D_ / 128, (B_ * S_) / 128, 3);
        gemm_mma<<<gr, 256, GEMM_SMEM_BYTES>>>(g0, g1, g2);
    }

    // attention
    {
        const int smem_bytes = ATTN_SMEM_FLOATS * 4;
        cudaFuncSetAttribute(attn_kernel,
                             cudaFuncAttributeMaxDynamicSharedMemorySize, smem_bytes);
        dim3 ga(S_ / 64, H_, B_);
        attn_kernel<<<ga, 64, smem_bytes>>>(gQ, gK, gV, mask, gctx);
    }

    // convert ctx
    {
        ConvArgs a{gctx, ch, cl};
        dim3 gr(ME / 1024, 1, 1);
        convert_hilo<<<gr, 256>>>(a, a, a, a);
    }

    // output projection
    {
        GemmArgs g0{ch, cl, woh, wol, out};
        dim3 gr(D_ / 128, (B_ * S_) / 128, 1);
        gemm_mma<<<gr, 256, GEMM_SMEM_BYTES>>>(g0, g0, g0);
    }
}

// round 11
// speedup vs baseline: 2.9431x; 2.1108x over previous
#include <cuda_runtime.h>
#include <cuda_bf16.h>
#include <cuda_fp16.h>
#include <cstdint>
#include <math.h>

#define B_  2
#define S_  2048
#define D_  1024
#define H_  16
#define DH_ 64
#define NEGV -1000000000.0f

// ================= helpers =================
__device__ __forceinline__ uint32_t smem_to_u32(const void* p) {
    uint32_t a;
    asm("{ .reg .u64 t; cvta.to.shared.u64 t, %1; cvt.u32.u64 %0, t; }"
        : "=r"(a) : "l"(p));
    return a;
}
__device__ __forceinline__ void ldsm4(uint32_t* r, uint32_t addr) {
    asm volatile("ldmatrix.sync.aligned.m8n8.x4.shared.b16 {%0,%1,%2,%3}, [%4];"
        : "=r"(r[0]), "=r"(r[1]), "=r"(r[2]), "=r"(r[3]) : "r"(addr));
}
__device__ __forceinline__ void ldsm4_t(uint32_t* r, uint32_t addr) {
    asm volatile("ldmatrix.sync.aligned.m8n8.x4.trans.shared.b16 {%0,%1,%2,%3}, [%4];"
        : "=r"(r[0]), "=r"(r[1]), "=r"(r[2]), "=r"(r[3]) : "r"(addr));
}
// bf16 mma (projection GEMMs)
__device__ __forceinline__ void mma16816(float* d, const uint32_t* a, const uint32_t* b) {
    asm volatile("mma.sync.aligned.m16n8k16.row.col.f32.bf16.bf16.f32 "
        "{%0,%1,%2,%3}, {%4,%5,%6,%7}, {%8,%9}, {%0,%1,%2,%3};"
        : "+f"(d[0]), "+f"(d[1]), "+f"(d[2]), "+f"(d[3])
        : "r"(a[0]), "r"(a[1]), "r"(a[2]), "r"(a[3]), "r"(b[0]), "r"(b[1]));
}
// fp16 mma (attention)
__device__ __forceinline__ void mma16816h(float* d, const uint32_t* a, const uint32_t* b) {
    asm volatile("mma.sync.aligned.m16n8k16.row.col.f32.f16.f16.f32 "
        "{%0,%1,%2,%3}, {%4,%5,%6,%7}, {%8,%9}, {%0,%1,%2,%3};"
        : "+f"(d[0]), "+f"(d[1]), "+f"(d[2]), "+f"(d[3])
        : "r"(a[0]), "r"(a[1]), "r"(a[2]), "r"(a[3]), "r"(b[0]), "r"(b[1]));
}
__device__ __forceinline__ void cp16(uint32_t smem, const void* g) {
    asm volatile("cp.async.cg.shared.global [%0], [%1], 16;" :: "r"(smem), "l"(g));
}
#define CP_COMMIT() asm volatile("cp.async.commit_group;" ::: "memory")
#define CP_WAIT0()  asm volatile("cp.async.wait_group 0;" ::: "memory")
#define CP_WAIT1()  asm volatile("cp.async.wait_group 1;" ::: "memory")

// ================= scratch =================
__device__ float g_Q[B_ * S_ * D_];
__device__ float g_K[B_ * S_ * D_];
__device__ float g_V[B_ * S_ * D_];
__device__ float g_ctx[B_ * S_ * D_];

__device__ __nv_bfloat16 g_qhi[B_ * S_ * D_], g_qlo[B_ * S_ * D_];
__device__ __nv_bfloat16 g_khi[B_ * S_ * D_], g_klo[B_ * S_ * D_];
__device__ __nv_bfloat16 g_vhi[B_ * S_ * D_], g_vlo[B_ * S_ * D_];
__device__ __nv_bfloat16 g_wqhi[D_ * D_], g_wqlo[D_ * D_];
__device__ __nv_bfloat16 g_wkhi[D_ * D_], g_wklo[D_ * D_];
__device__ __nv_bfloat16 g_wvhi[D_ * D_], g_wvlo[D_ * D_];
__device__ __nv_bfloat16 g_wohi[D_ * D_], g_wolo[D_ * D_];

// ================= fp32 -> bf16 hi/lo split =================
struct ConvArgs { const float* s; __nv_bfloat16* h; __nv_bfloat16* l; };

__global__ __launch_bounds__(256) void convert_hilo(ConvArgs a0, ConvArgs a1,
                                                    ConvArgs a2, ConvArgs a3) {
    ConvArgs a = (blockIdx.z == 0) ? a0 : (blockIdx.z == 1) ? a1
               : (blockIdx.z == 2) ? a2 : a3;
    size_t i4 = (size_t)blockIdx.x * 256 + threadIdx.x;
    float4 x = ((const float4*)a.s)[i4];
    __nv_bfloat16 h0 = __float2bfloat16_rn(x.x);
    __nv_bfloat16 h1 = __float2bfloat16_rn(x.y);
    __nv_bfloat16 h2 = __float2bfloat16_rn(x.z);
    __nv_bfloat16 h3 = __float2bfloat16_rn(x.w);
    float r0 = x.x - __bfloat162float(h0);
    float r1 = x.y - __bfloat162float(h1);
    float r2 = x.z - __bfloat162float(h2);
    float r3 = x.w - __bfloat162float(h3);
    __nv_bfloat162 hp0 = __halves2bfloat162(h0, h1);
    __nv_bfloat162 hp1 = __halves2bfloat162(h2, h3);
    __nv_bfloat162 lp0 = __halves2bfloat162(__float2bfloat16_rn(r0), __float2bfloat16_rn(r1));
    __nv_bfloat162 lp1 = __halves2bfloat162(__float2bfloat16_rn(r2), __float2bfloat16_rn(r3));
    uint2 hv, lv;
    hv.x = reinterpret_cast<uint32_t&>(hp0); hv.y = reinterpret_cast<uint32_t&>(hp1);
    lv.x = reinterpret_cast<uint32_t&>(lp0); lv.y = reinterpret_cast<uint32_t&>(lp1);
    ((uint2*)a.h)[i4] = hv;
    ((uint2*)a.l)[i4] = lv;
}

// ================= mma.sync GEMM (bf16 hi/lo, 3 passes) =================
// headmajor mode writes fp16 hi/lo (attention operands); mode 0 writes fp32.
struct GemmArgs {
    const __nv_bfloat16 *ah, *al, *bh, *bl;
    float* c;
    __half *chi, *clo;
    int headmajor;
};

#define GEMM_SMEM_BYTES (2 * 4 * 10240)
#define ROWB 80

__global__ __launch_bounds__(256) void gemm_mma(GemmArgs ga0, GemmArgs ga1, GemmArgs ga2) {
    extern __shared__ char smx[];
    const GemmArgs g = (blockIdx.z == 0) ? ga0 : (blockIdx.z == 1) ? ga1 : ga2;

    const int tid  = threadIdx.x;
    const int lane = tid & 31;
    const int wid  = tid >> 5;
    const int bm = blockIdx.y * 128;
    const int bn = blockIdx.x * 128;
    const uint32_t sbase = smem_to_u32(smx);

    const int m0 = (wid >> 1) * 32;
    const int n0 = (wid & 1) * 64;

    float acc[2][8][4];
#pragma unroll
    for (int mt = 0; mt < 2; mt++)
#pragma unroll
        for (int nt = 0; nt < 8; nt++)
#pragma unroll
            for (int i = 0; i < 4; i++) acc[mt][nt][i] = 0.0f;

    const uint32_t aRow = lane & 15;
    const uint32_t aK   = (lane >> 4) * 8;
    const uint32_t bN   = (lane & 7) + ((lane >> 4) & 1) * 8;
    const uint32_t bK   = ((lane >> 3) & 1) * 8;

    auto load_chunk = [&](int c, int st) {
        const int k0 = c * 32;
#pragma unroll
        for (int p = 0; p < 8; p++) {
            int idx = tid + p * 256;
            int arr = idx >> 9;
            int r   = (idx >> 2) & 127;
            int c8  = (idx & 3) * 8;
            const __nv_bfloat16* src = (arr == 0) ? g.ah : (arr == 1) ? g.al
                                    : (arr == 2) ? g.bh : g.bl;
            int grow = ((arr < 2) ? bm : bn) + r;
            cp16(sbase + (uint32_t)(st * 4 + arr) * 10240 + r * ROWB + c8 * 2,
                 src + (size_t)grow * 1024 + k0 + c8);
        }
        CP_COMMIT();
    };

    load_chunk(0, 0);

    for (int c = 0; c < 32; c++) {
        const int st = c & 1;
        CP_WAIT0();
        __syncthreads();
        if (c < 31) load_chunk(c + 1, st ^ 1);

        const uint32_t aH = sbase + (uint32_t)(st * 4 + 0) * 10240;
        const uint32_t aL = aH + 10240;
        const uint32_t bH = aL + 10240;
        const uint32_t bL = bH + 10240;

#pragma unroll
        for (int pass = 0; pass < 3; pass++) {
            const uint32_t ab = (pass == 2) ? aL : aH;
            const uint32_t bb = (pass == 1) ? bL : bH;
#pragma unroll
            for (int ks = 0; ks < 2; ks++) {
                uint32_t af[2][4], bf[4][4];
#pragma unroll
                for (int mt = 0; mt < 2; mt++)
                    ldsm4(af[mt], ab + (m0 + mt * 16 + aRow) * ROWB + (ks * 16 + aK) * 2);
#pragma unroll
                for (int np = 0; np < 4; np++)
                    ldsm4(bf[np], bb + (n0 + np * 16 + bN) * ROWB + (ks * 16 + bK) * 2);
#pragma unroll
                for (int mt = 0; mt < 2; mt++)
#pragma unroll
                    for (int nt = 0; nt < 8; nt++)
                        mma16816(acc[mt][nt], af[mt], &bf[nt >> 1][(nt & 1) * 2]);
            }
        }
    }

    if (!g.headmajor) {
#pragma unroll
        for (int mt = 0; mt < 2; mt++)
#pragma unroll
            for (int nt = 0; nt < 8; nt++) {
                int row = bm + m0 + mt * 16 + (lane >> 2);
                int col = bn + n0 + nt * 8 + (lane & 3) * 2;
                *(float2*)(g.c + (size_t)row * 1024 + col) =
                    make_float2(acc[mt][nt][0], acc[mt][nt][1]);
                *(float2*)(g.c + (size_t)(row + 8) * 1024 + col) =
                    make_float2(acc[mt][nt][2], acc[mt][nt][3]);
            }
    } else {
#pragma unroll
        for (int mt = 0; mt < 2; mt++)
#pragma unroll
            for (int nt = 0; nt < 8; nt++) {
                int row = bm + m0 + mt * 16 + (lane >> 2);
                int col = bn + n0 + nt * 8 + (lane & 3) * 2;
                int bb2 = row >> 11, s = row & 2047, hh = col >> 6, dh = col & 63;
                size_t dst = ((size_t)(bb2 * H_ + hh) * S_ + s) * 64 + dh;
#pragma unroll
                for (int half = 0; half < 2; half++) {
                    float x = acc[mt][nt][half * 2], y = acc[mt][nt][half * 2 + 1];
                    __half hx = __float2half_rn(x), hy = __float2half_rn(y);
                    size_t d2 = dst + half * 8 * 64;
                    *(__half2*)(g.chi + d2) = __halves2half2(hx, hy);
                    *(__half2*)(g.clo + d2) = __halves2half2(
                        __float2half_rn(x - __half2float(hx)),
                        __float2half_rn(y - __half2float(hy)));
                }
            }
    }
}

// ================= tensor-core flash attention (fp16 operands) =================
#define KROWB 144
#define PROWB 272
#define OFF_KH 0
#define OFF_KL 18432
#define OFF_VH 36864
#define OFF_VL 55296
#define OFF_P  73728
#define OFF_PM 108544
#define OFF_MS 109056
#define OFF_LS 109568
#define OFF_RMAX 110080
#define OFF_RSUM 111104
#define ATTN_SMEM 112128

__global__ __launch_bounds__(256, 1) void attn_tc(
    const __half* __restrict__ Qh, const __half* __restrict__ Ql,
    const __half* __restrict__ Kh, const __half* __restrict__ Kl,
    const __half* __restrict__ Vh, const __half* __restrict__ Vl,
    const int* __restrict__ mask,
    __nv_bfloat16* __restrict__ ctxh, __nv_bfloat16* __restrict__ ctxl)
{
    extern __shared__ char sm[];
    const uint32_t sb = smem_to_u32(sm);
    const int qt = (gridDim.x - 1) - blockIdx.x;
    const int h = blockIdx.y, b = blockIdx.z;
    const int tid = threadIdx.x, lane = tid & 31, wid = tid >> 5;
    const int m0  = (wid >> 1) * 32;
    const int n0q = (wid & 1) * 64;
    const int n0v = (wid & 1) * 32;
    const int q0 = qt * 128;
    const size_t bh = (size_t)(b * H_ + h) * S_;

    float* msm  = (float*)(sm + OFF_MS);
    float* lsm  = (float*)(sm + OFF_LS);
    float* pmm  = (float*)(sm + OFF_PM);
    float* rmax = (float*)(sm + OFF_RMAX);
    float* rsum = (float*)(sm + OFF_RSUM);

    if (tid < 128) { msm[tid] = -1e30f; lsm[tid] = 0.0f; }

    // stage Q hi -> OFF_P, Q lo -> OFF_KH
#pragma unroll
    for (int p = 0; p < 8; p++) {
        int i = tid + p * 256;
        int half = i >> 10;
        int j = i & 1023;
        int row = j >> 3, c16 = j & 7;
        cp16(sb + (half ? OFF_KH : OFF_P) + row * KROWB + c16 * 16,
             (half ? Ql : Qh) + (bh + q0 + row) * 64 + c16 * 8);
    }
    CP_COMMIT(); CP_WAIT0();
    __syncthreads();

    uint32_t qfh[2][4][4], qfl[2][4][4];
    {
        const uint32_t arow = lane & 15, akk = (lane >> 4) * 8;
#pragma unroll
        for (int mt = 0; mt < 2; mt++)
#pragma unroll
            for (int kc = 0; kc < 4; kc++) {
                ldsm4(qfh[mt][kc], sb + OFF_P  + (m0 + mt * 16 + arow) * KROWB + (kc * 16 + akk) * 2);
                ldsm4(qfl[mt][kc], sb + OFF_KH + (m0 + mt * 16 + arow) * KROWB + (kc * 16 + akk) * 2);
            }
    }

    float accO[2][4][4];
#pragma unroll
    for (int mt = 0; mt < 2; mt++)
#pragma unroll
        for (int nt = 0; nt < 4; nt++)
#pragma unroll
            for (int e = 0; e < 4; e++) accO[mt][nt][e] = 0.0f;

    const int* mbase = mask + b * S_;

    for (int kt = 0; kt <= qt; kt++) {
        const int k0 = kt * 128;
        __syncthreads();
#pragma unroll
        for (int p = 0; p < 8; p++) {
            int i = tid + p * 256;
            int half = i >> 10;
            int j = i & 1023;
            int row = j >> 3, c16 = j & 7;
            cp16(sb + (half ? OFF_KL : OFF_KH) + row * KROWB + c16 * 16,
                 (half ? Kl : Kh) + (bh + k0 + row) * 64 + c16 * 8);
        }
        CP_COMMIT();
#pragma unroll
        for (int p = 0; p < 8; p++) {
            int i = tid + p * 256;
            int half = i >> 10;
            int j = i & 1023;
            int row = j >> 3, c16 = j & 7;
            cp16(sb + (half ? OFF_VL : OFF_VH) + row * KROWB + c16 * 16,
                 (half ? Vl : Vh) + (bh + k0 + row) * 64 + c16 * 8);
        }
        CP_COMMIT();
        if (tid < 128) pmm[tid] = (mbase[k0 + tid] == 0) ? NEGV : 0.0f;
        CP_WAIT1();
        __syncthreads();

        // ---- QK (3 passes: QhKh, QhKl, QlKh) ----
        float accS[2][8][4];
#pragma unroll
        for (int mt = 0; mt < 2; mt++)
#pragma unroll
            for (int nt = 0; nt < 8; nt++)
#pragma unroll
                for (int e = 0; e < 4; e++) accS[mt][nt][e] = 0.0f;

        const uint32_t bN = (lane & 7) + ((lane >> 4) & 1) * 8;
        const uint32_t bK = ((lane >> 3) & 1) * 8;
#pragma unroll
        for (int pass = 0; pass < 3; pass++) {
            const uint32_t kbase = sb + ((pass == 1) ? OFF_KL : OFF_KH);
#pragma unroll
            for (int kc = 0; kc < 4; kc++) {
                uint32_t bf[4][4];
#pragma unroll
                for (int np = 0; np < 4; np++)
                    ldsm4(bf[np], kbase + (n0q + np * 16 + bN) * KROWB + (kc * 16 + bK) * 2);
#pragma unroll
                for (int mt = 0; mt < 2; mt++) {
                    const uint32_t* af = (pass == 2) ? qfl[mt][kc] : qfh[mt][kc];
#pragma unroll
                    for (int nt = 0; nt < 8; nt++)
                        mma16816h(accS[mt][nt], af, &bf[nt >> 1][(nt & 1) * 2]);
                }
            }
        }

        // ---- mask + scale ----
        const bool diag = (kt == qt);
#pragma unroll
        for (int mt = 0; mt < 2; mt++)
#pragma unroll
            for (int nt = 0; nt < 8; nt++)
#pragma unroll
                for (int e = 0; e < 4; e++) {
                    int rl = m0 + mt * 16 + (lane >> 2) + (e >> 1) * 8;
                    int cl = n0q + nt * 8 + (lane & 3) * 2 + (e & 1);
                    float s = accS[mt][nt][e] * 0.125f + pmm[cl];
                    if (diag && cl > rl) s = NEGV;
                    accS[mt][nt][e] = s;
                }

        // ---- row max ----
#pragma unroll
        for (int mt = 0; mt < 2; mt++)
#pragma unroll
            for (int hh = 0; hh < 2; hh++) {
                float mx = -1e30f;
#pragma unroll
                for (int nt = 0; nt < 8; nt++) {
                    mx = fmaxf(mx, accS[mt][nt][hh * 2]);
                    mx = fmaxf(mx, accS[mt][nt][hh * 2 + 1]);
                }
                mx = fmaxf(mx, __shfl_xor_sync(0xffffffff, mx, 1));
                mx = fmaxf(mx, __shfl_xor_sync(0xffffffff, mx, 2));
                if ((lane & 3) == 0)
                    rmax[(wid & 1) * 128 + m0 + mt * 16 + (lane >> 2) + hh * 8] = mx;
            }
        __syncthreads();

        // ---- softmax + P (fp16) write + O rescale ----
        float alpha[2][2], mnew[2][2];
#pragma unroll
        for (int mt = 0; mt < 2; mt++)
#pragma unroll
            for (int hh = 0; hh < 2; hh++) {
                int rl = m0 + mt * 16 + (lane >> 2) + hh * 8;
                float mo = msm[rl];
                float mx = fmaxf(fmaxf(rmax[rl], rmax[128 + rl]), mo);
                mnew[mt][hh] = mx;
                alpha[mt][hh] = __expf(mo - mx);
                float ps = 0.0f;
#pragma unroll
                for (int nt = 0; nt < 8; nt++) {
                    float p0 = __expf(accS[mt][nt][hh * 2] - mx);
                    float p1 = __expf(accS[mt][nt][hh * 2 + 1] - mx);
                    ps += p0 + p1;
                    int cl = n0q + nt * 8 + (lane & 3) * 2;
                    *(__half2*)(sm + OFF_P + rl * PROWB + cl * 2) =
                        __halves2half2(__float2half_rn(p0), __float2half_rn(p1));
                }
                ps += __shfl_xor_sync(0xffffffff, ps, 1);
                ps += __shfl_xor_sync(0xffffffff, ps, 2);
                if ((lane & 3) == 0) rsum[(wid & 1) * 128 + rl] = ps;
#pragma unroll
                for (int nt = 0; nt < 4; nt++) {
                    accO[mt][nt][hh * 2]     *= alpha[mt][hh];
                    accO[mt][nt][hh * 2 + 1] *= alpha[mt][hh];
                }
            }
        CP_WAIT0();
        __syncthreads();

        if ((wid & 1) == 0 && (lane & 3) == 0) {
#pragma unroll
            for (int mt = 0; mt < 2; mt++)
#pragma unroll
                for (int hh = 0; hh < 2; hh++) {
                    int rl = m0 + mt * 16 + (lane >> 2) + hh * 8;
                    lsm[rl] = lsm[rl] * alpha[mt][hh] + rsum[rl] + rsum[128 + rl];
                    msm[rl] = mnew[mt][hh];
                }
        }

        // ---- PV (2 passes: Vhi, Vlo) ----
        const uint32_t arow = lane & 15, akk = (lane >> 4) * 8;
#pragma unroll
        for (int pass = 0; pass < 2; pass++) {
            const uint32_t vbase = sb + (pass ? OFF_VL : OFF_VH);
#pragma unroll
            for (int kc = 0; kc < 8; kc++) {
                uint32_t pf[2][4], vf[2][4];
#pragma unroll
                for (int mt = 0; mt < 2; mt++)
                    ldsm4(pf[mt], sb + OFF_P + (m0 + mt * 16 + arow) * PROWB + (kc * 16 + akk) * 2);
#pragma unroll
                for (int ng = 0; ng < 2; ng++)
                    ldsm4_t(vf[ng], vbase + (kc * 16 + arow) * KROWB + (n0v + ng * 16 + akk) * 2);
#pragma unroll
                for (int mt = 0; mt < 2; mt++)
#pragma unroll
                    for (int nt = 0; nt < 4; nt++)
                        mma16816h(accO[mt][nt], pf[mt], &vf[nt >> 1][(nt & 1) * 2]);
            }
        }
    }

    __syncthreads();
#pragma unroll
    for (int mt = 0; mt < 2; mt++)
#pragma unroll
        for (int hh = 0; hh < 2; hh++) {
            int rl = m0 + mt * 16 + (lane >> 2) + hh * 8;
            float inv = 1.0f / lsm[rl];
            size_t orow = (size_t)(b * S_ + q0 + rl) * 1024 + h * 64;
#pragma unroll
            for (int nt = 0; nt < 4; nt++) {
                float x = accO[mt][nt][hh * 2] * inv;
                float y = accO[mt][nt][hh * 2 + 1] * inv;
                int col = n0v + nt * 8 + (lane & 3) * 2;
                __nv_bfloat16 hx = __float2bfloat16_rn(x), hy = __float2bfloat16_rn(y);
                *(__nv_bfloat162*)(ctxh + orow + col) = __halves2bfloat162(hx, hy);
                *(__nv_bfloat162*)(ctxl + orow + col) = __halves2bfloat162(
                    __float2bfloat16_rn(x - __bfloat162float(hx)),
                    __float2bfloat16_rn(y - __bfloat162float(hy)));
            }
        }
}

// ================= launch =================
extern "C" void kernel_launch(void* const* d_in, const int* in_sizes, int n_in,
                              void* d_out, int out_size)
{
    const float* q    = (const float*)d_in[0];
    const float* k    = (const float*)d_in[1];
    const float* v    = (const float*)d_in[2];
    const int*   mask = (const int*)d_in[3];
    const float* Wq   = (const float*)d_in[4];
    const float* Wk   = (const float*)d_in[5];
    const float* Wv   = (const float*)d_in[6];
    const float* Wo   = (const float*)d_in[7];
    float* out = (float*)d_out;

    const int ME = B_ * S_ * D_;
    const int WE = D_ * D_;

    float *gQ, *gK, *gV, *gctx;
    cudaGetSymbolAddress((void**)&gQ,  g_Q);
    cudaGetSymbolAddress((void**)&gK,  g_K);
    cudaGetSymbolAddress((void**)&gV,  g_V);
    cudaGetSymbolAddress((void**)&gctx, g_ctx);
    __half* Qhd = (__half*)gQ;  __half* Qld = Qhd + ME;
    __half* Khd = (__half*)gK;  __half* Kld = Khd + ME;
    __half* Vhd = (__half*)gV;  __half* Vld = Vhd + ME;
    __nv_bfloat16* Chd = (__nv_bfloat16*)gctx; __nv_bfloat16* Cld = Chd + ME;

    __nv_bfloat16 *qh,*ql,*kh,*kl,*vh,*vl;
    __nv_bfloat16 *wqh,*wql,*wkh,*wkl,*wvh,*wvl,*woh,*wol;
    cudaGetSymbolAddress((void**)&qh, g_qhi); cudaGetSymbolAddress((void**)&ql, g_qlo);
    cudaGetSymbolAddress((void**)&kh, g_khi); cudaGetSymbolAddress((void**)&kl, g_klo);
    cudaGetSymbolAddress((void**)&vh, g_vhi); cudaGetSymbolAddress((void**)&vl, g_vlo);
    cudaGetSymbolAddress((void**)&wqh, g_wqhi); cudaGetSymbolAddress((void**)&wql, g_wqlo);
    cudaGetSymbolAddress((void**)&wkh, g_wkhi); cudaGetSymbolAddress((void**)&wkl, g_wklo);
    cudaGetSymbolAddress((void**)&wvh, g_wvhi); cudaGetSymbolAddress((void**)&wvl, g_wvlo);
    cudaGetSymbolAddress((void**)&woh, g_wohi); cudaGetSymbolAddress((void**)&wol, g_wolo);

    {
        ConvArgs a0{q, qh, ql}, a1{k, kh, kl}, a2{v, vh, vl};
        dim3 gr(ME / 1024, 1, 3);
        convert_hilo<<<gr, 256>>>(a0, a1, a2, a2);
    }
    {
        ConvArgs a0{Wq, wqh, wql}, a1{Wk, wkh, wkl}, a2{Wv, wvh, wvl}, a3{Wo, woh, wol};
        dim3 gr(WE / 1024, 1, 4);
        convert_hilo<<<gr, 256>>>(a0, a1, a2, a3);
    }

    cudaFuncSetAttribute(gemm_mma, cudaFuncAttributeMaxDynamicSharedMemorySize,
                         GEMM_SMEM_BYTES);

    {
        GemmArgs g0{qh, ql, wqh, wql, nullptr, Qhd, Qld, 1};
        GemmArgs g1{kh, kl, wkh, wkl, nullptr, Khd, Kld, 1};
        GemmArgs g2{vh, vl, wvh, wvl, nullptr, Vhd, Vld, 1};
        dim3 gr(D_ / 128, (B_ * S_) / 128, 3);
        gemm_mma<<<gr, 256, GEMM_SMEM_BYTES>>>(g0, g1, g2);
    }

    {
        cudaFuncSetAttribute(attn_tc, cudaFuncAttributeMaxDynamicSharedMemorySize,
                             ATTN_SMEM);
        dim3 ga(S_ / 128, H_, B_);
        attn_tc<<<ga, 256, ATTN_SMEM>>>(Qhd, Qld, Khd, Kld, Vhd, Vld, mask, Chd, Cld);
    }

    {
        GemmArgs g0{(const __nv_bfloat16*)Chd, (const __nv_bfloat16*)Cld, woh, wol,
                    out, nullptr, nullptr, 0};
        dim3 gr(D_ / 128, (B_ * S_) / 128, 1);
        gemm_mma<<<gr, 256, GEMM_SMEM_BYTES>>>(g0, g0, g0);
    }
}

// round 12
// speedup vs baseline: 4.3558x; 1.4800x over previous
#include <cuda_runtime.h>
#include <cuda_bf16.h>
#include <cuda_fp16.h>
#include <cstdint>
#include <math.h>

#define B_  2
#define S_  2048
#define D_  1024
#define H_  16
#define DH_ 64
#define NEGV -1000000000.0f

// ================= helpers =================
__device__ __forceinline__ uint32_t smem_to_u32(const void* p) {
    uint32_t a;
    asm("{ .reg .u64 t; cvta.to.shared.u64 t, %1; cvt.u32.u64 %0, t; }"
        : "=r"(a) : "l"(p));
    return a;
}
__device__ __forceinline__ void ldsm4(uint32_t* r, uint32_t addr) {
    asm volatile("ldmatrix.sync.aligned.m8n8.x4.shared.b16 {%0,%1,%2,%3}, [%4];"
        : "=r"(r[0]), "=r"(r[1]), "=r"(r[2]), "=r"(r[3]) : "r"(addr));
}
__device__ __forceinline__ void ldsm4_t(uint32_t* r, uint32_t addr) {
    asm volatile("ldmatrix.sync.aligned.m8n8.x4.trans.shared.b16 {%0,%1,%2,%3}, [%4];"
        : "=r"(r[0]), "=r"(r[1]), "=r"(r[2]), "=r"(r[3]) : "r"(addr));
}
__device__ __forceinline__ void mma16816h(float* d, const uint32_t* a, const uint32_t* b) {
    asm volatile("mma.sync.aligned.m16n8k16.row.col.f32.f16.f16.f32 "
        "{%0,%1,%2,%3}, {%4,%5,%6,%7}, {%8,%9}, {%0,%1,%2,%3};"
        : "+f"(d[0]), "+f"(d[1]), "+f"(d[2]), "+f"(d[3])
        : "r"(a[0]), "r"(a[1]), "r"(a[2]), "r"(a[3]), "r"(b[0]), "r"(b[1]));
}
__device__ __forceinline__ void cp16(uint32_t smem, const void* g) {
    asm volatile("cp.async.cg.shared.global [%0], [%1], 16;" :: "r"(smem), "l"(g));
}
#define CP_COMMIT() asm volatile("cp.async.commit_group;" ::: "memory")
#define CP_WAIT0()  asm volatile("cp.async.wait_group 0;" ::: "memory")
#define CP_WAIT1()  asm volatile("cp.async.wait_group 1;" ::: "memory")

// ================= scratch =================
__device__ float g_Q[B_ * S_ * D_];     // Q head-major fp16 hi+lo
__device__ float g_K[B_ * S_ * D_];     // K head-major fp16 hi+lo
__device__ float g_V[B_ * S_ * D_];     // V head-major fp16 hi+lo
__device__ float g_ctx[B_ * S_ * D_];   // ctx fp16 (half used)

__device__ __nv_bfloat16 g_qhi[B_ * S_ * D_];   // q fp16 (cast)
__device__ __nv_bfloat16 g_khi[B_ * S_ * D_];
__device__ __nv_bfloat16 g_vhi[B_ * S_ * D_];
__device__ __nv_bfloat16 g_wqhi[D_ * D_], g_wqlo[D_ * D_];
__device__ __nv_bfloat16 g_wkhi[D_ * D_], g_wklo[D_ * D_];
__device__ __nv_bfloat16 g_wvhi[D_ * D_], g_wvlo[D_ * D_];
__device__ __nv_bfloat16 g_wohi[D_ * D_], g_wolo[D_ * D_];

// ================= fp32 -> fp16 cast (inputs) =================
struct CastArgs { const float* s; __half* d; };

__global__ __launch_bounds__(256) void convert_f16(CastArgs a0, CastArgs a1, CastArgs a2) {
    CastArgs a = (blockIdx.z == 0) ? a0 : (blockIdx.z == 1) ? a1 : a2;
    size_t i4 = (size_t)blockIdx.x * 256 + threadIdx.x;
    float4 x = ((const float4*)a.s)[i4];
    __half2 p0 = __halves2half2(__float2half_rn(x.x), __float2half_rn(x.y));
    __half2 p1 = __halves2half2(__float2half_rn(x.z), __float2half_rn(x.w));
    uint2 v;
    v.x = reinterpret_cast<uint32_t&>(p0); v.y = reinterpret_cast<uint32_t&>(p1);
    ((uint2*)a.d)[i4] = v;
}

// ================= fp32 -> fp16 hi/lo (weights) =================
struct ConvW { const float* s; __half* h; __half* l; };

__global__ __launch_bounds__(256) void convert_hilo16(ConvW a0, ConvW a1,
                                                      ConvW a2, ConvW a3) {
    ConvW a = (blockIdx.z == 0) ? a0 : (blockIdx.z == 1) ? a1
            : (blockIdx.z == 2) ? a2 : a3;
    size_t i4 = (size_t)blockIdx.x * 256 + threadIdx.x;
    float4 x = ((const float4*)a.s)[i4];
    __half h0 = __float2half_rn(x.x), h1 = __float2half_rn(x.y);
    __half h2 = __float2half_rn(x.z), h3 = __float2half_rn(x.w);
    __half2 hp0 = __halves2half2(h0, h1);
    __half2 hp1 = __halves2half2(h2, h3);
    __half2 lp0 = __halves2half2(__float2half_rn(x.x - __half2float(h0)),
                                 __float2half_rn(x.y - __half2float(h1)));
    __half2 lp1 = __halves2half2(__float2half_rn(x.z - __half2float(h2)),
                                 __float2half_rn(x.w - __half2float(h3)));
    uint2 hv, lv;
    hv.x = reinterpret_cast<uint32_t&>(hp0); hv.y = reinterpret_cast<uint32_t&>(hp1);
    lv.x = reinterpret_cast<uint32_t&>(lp0); lv.y = reinterpret_cast<uint32_t&>(lp1);
    ((uint2*)a.h)[i4] = hv;
    ((uint2*)a.l)[i4] = lv;
}

// ================= mma.sync GEMM (fp16, 2 passes: Ah*Bh + Ah*Bl) =================
struct GemmArgs {
    const __half *ah, *bh, *bl;
    float* c;
    __half *chi, *clo;
    int headmajor;
};

#define GEMM_SMEM_BYTES (2 * 3 * 10240)   // 61440
#define ROWB 80

__global__ __launch_bounds__(256) void gemm_mma(GemmArgs ga0, GemmArgs ga1, GemmArgs ga2) {
    extern __shared__ char smx[];
    const GemmArgs g = (blockIdx.z == 0) ? ga0 : (blockIdx.z == 1) ? ga1 : ga2;

    const int tid  = threadIdx.x;
    const int lane = tid & 31;
    const int wid  = tid >> 5;
    const int bm = blockIdx.y * 128;
    const int bn = blockIdx.x * 128;
    const uint32_t sbase = smem_to_u32(smx);

    const int m0 = (wid >> 1) * 32;
    const int n0 = (wid & 1) * 64;

    float acc[2][8][4];
#pragma unroll
    for (int mt = 0; mt < 2; mt++)
#pragma unroll
        for (int nt = 0; nt < 8; nt++)
#pragma unroll
            for (int i = 0; i < 4; i++) acc[mt][nt][i] = 0.0f;

    const uint32_t aRow = lane & 15;
    const uint32_t aK   = (lane >> 4) * 8;
    const uint32_t bN   = (lane & 7) + ((lane >> 4) & 1) * 8;
    const uint32_t bK   = ((lane >> 3) & 1) * 8;

    auto load_chunk = [&](int c, int st) {
        const int k0 = c * 32;
#pragma unroll
        for (int p = 0; p < 6; p++) {
            int idx = tid + p * 256;          // 0..1535
            int arr = idx >> 9;               // 0..2
            int r   = (idx >> 2) & 127;
            int c8  = (idx & 3) * 8;
            const __half* src = (arr == 0) ? g.ah : (arr == 1) ? g.bh : g.bl;
            int grow = ((arr == 0) ? bm : bn) + r;
            cp16(sbase + (uint32_t)(st * 3 + arr) * 10240 + r * ROWB + c8 * 2,
                 src + (size_t)grow * 1024 + k0 + c8);
        }
        CP_COMMIT();
    };

    load_chunk(0, 0);

    for (int c = 0; c < 32; c++) {
        const int st = c & 1;
        CP_WAIT0();
        __syncthreads();
        if (c < 31) load_chunk(c + 1, st ^ 1);

        const uint32_t aH = sbase + (uint32_t)(st * 3) * 10240;
        const uint32_t bH = aH + 10240;
        const uint32_t bL = bH + 10240;

#pragma unroll
        for (int ks = 0; ks < 2; ks++) {
            uint32_t af[2][4];
#pragma unroll
            for (int mt = 0; mt < 2; mt++)
                ldsm4(af[mt], aH + (m0 + mt * 16 + aRow) * ROWB + (ks * 16 + aK) * 2);
#pragma unroll
            for (int pass = 0; pass < 2; pass++) {
                const uint32_t bb = pass ? bL : bH;
                uint32_t bf[4][4];
#pragma unroll
                for (int np = 0; np < 4; np++)
                    ldsm4(bf[np], bb + (n0 + np * 16 + bN) * ROWB + (ks * 16 + bK) * 2);
#pragma unroll
                for (int mt = 0; mt < 2; mt++)
#pragma unroll
                    for (int nt = 0; nt < 8; nt++)
                        mma16816h(acc[mt][nt], af[mt], &bf[nt >> 1][(nt & 1) * 2]);
            }
        }
    }

    if (!g.headmajor) {
#pragma unroll
        for (int mt = 0; mt < 2; mt++)
#pragma unroll
            for (int nt = 0; nt < 8; nt++) {
                int row = bm + m0 + mt * 16 + (lane >> 2);
                int col = bn + n0 + nt * 8 + (lane & 3) * 2;
                *(float2*)(g.c + (size_t)row * 1024 + col) =
                    make_float2(acc[mt][nt][0], acc[mt][nt][1]);
                *(float2*)(g.c + (size_t)(row + 8) * 1024 + col) =
                    make_float2(acc[mt][nt][2], acc[mt][nt][3]);
            }
    } else {
#pragma unroll
        for (int mt = 0; mt < 2; mt++)
#pragma unroll
            for (int nt = 0; nt < 8; nt++) {
                int row = bm + m0 + mt * 16 + (lane >> 2);
                int col = bn + n0 + nt * 8 + (lane & 3) * 2;
                int bb2 = row >> 11, s = row & 2047, hh = col >> 6, dh = col & 63;
                size_t dst = ((size_t)(bb2 * H_ + hh) * S_ + s) * 64 + dh;
#pragma unroll
                for (int half = 0; half < 2; half++) {
                    float x = acc[mt][nt][half * 2], y = acc[mt][nt][half * 2 + 1];
                    __half hx = __float2half_rn(x), hy = __float2half_rn(y);
                    size_t d2 = dst + half * 8 * 64;
                    *(__half2*)(g.chi + d2) = __halves2half2(hx, hy);
                    *(__half2*)(g.clo + d2) = __halves2half2(
                        __float2half_rn(x - __half2float(hx)),
                        __float2half_rn(y - __half2float(hy)));
                }
            }
    }
}

// ================= tensor-core flash attention (fp16) =================
// QK: Qh*(Kh + Kl) 2-pass. PV: P*Vh 1-pass. ctx: fp16.
#define KROWB 144
#define PROWB 272
#define OFF_KH 0
#define OFF_KL 18432
#define OFF_VH 36864
#define OFF_P  55296
#define OFF_PM 90112
#define OFF_MS 90624
#define OFF_LS 91136
#define OFF_RMAX 91648
#define OFF_RSUM 92672
#define ATTN_SMEM 93696

__global__ __launch_bounds__(256, 1) void attn_tc(
    const __half* __restrict__ Qh,
    const __half* __restrict__ Kh, const __half* __restrict__ Kl,
    const __half* __restrict__ Vh,
    const int* __restrict__ mask,
    __half* __restrict__ ctx)
{
    extern __shared__ char sm[];
    const uint32_t sb = smem_to_u32(sm);
    const int qt = (gridDim.x - 1) - blockIdx.x;
    const int h = blockIdx.y, b = blockIdx.z;
    const int tid = threadIdx.x, lane = tid & 31, wid = tid >> 5;
    const int m0  = (wid >> 1) * 32;
    const int n0q = (wid & 1) * 64;
    const int n0v = (wid & 1) * 32;
    const int q0 = qt * 128;
    const size_t bh = (size_t)(b * H_ + h) * S_;

    float* msm  = (float*)(sm + OFF_MS);
    float* lsm  = (float*)(sm + OFF_LS);
    float* pmm  = (float*)(sm + OFF_PM);
    float* rmax = (float*)(sm + OFF_RMAX);
    float* rsum = (float*)(sm + OFF_RSUM);

    if (tid < 128) { msm[tid] = -1e30f; lsm[tid] = 0.0f; }

    // stage Q hi into OFF_P
#pragma unroll
    for (int p = 0; p < 4; p++) {
        int i = tid + p * 256;            // 0..1023
        int row = i >> 3, c16 = i & 7;
        cp16(sb + OFF_P + row * KROWB + c16 * 16,
             Qh + (bh + q0 + row) * 64 + c16 * 8);
    }
    CP_COMMIT(); CP_WAIT0();
    __syncthreads();

    uint32_t qfh[2][4][4];
    {
        const uint32_t arow = lane & 15, akk = (lane >> 4) * 8;
#pragma unroll
        for (int mt = 0; mt < 2; mt++)
#pragma unroll
            for (int kc = 0; kc < 4; kc++)
                ldsm4(qfh[mt][kc], sb + OFF_P + (m0 + mt * 16 + arow) * KROWB + (kc * 16 + akk) * 2);
    }

    float accO[2][4][4];
#pragma unroll
    for (int mt = 0; mt < 2; mt++)
#pragma unroll
        for (int nt = 0; nt < 4; nt++)
#pragma unroll
            for (int e = 0; e < 4; e++) accO[mt][nt][e] = 0.0f;

    const int* mbase = mask + b * S_;

    for (int kt = 0; kt <= qt; kt++) {
        const int k0 = kt * 128;
        __syncthreads();
        // K hi + lo
#pragma unroll
        for (int p = 0; p < 8; p++) {
            int i = tid + p * 256;
            int half = i >> 10;
            int j = i & 1023;
            int row = j >> 3, c16 = j & 7;
            cp16(sb + (half ? OFF_KL : OFF_KH) + row * KROWB + c16 * 16,
                 (half ? Kl : Kh) + (bh + k0 + row) * 64 + c16 * 8);
        }
        CP_COMMIT();
        // V hi
#pragma unroll
        for (int p = 0; p < 4; p++) {
            int i = tid + p * 256;
            int row = i >> 3, c16 = i & 7;
            cp16(sb + OFF_VH + row * KROWB + c16 * 16,
                 Vh + (bh + k0 + row) * 64 + c16 * 8);
        }
        CP_COMMIT();
        if (tid < 128) pmm[tid] = (mbase[k0 + tid] == 0) ? NEGV : 0.0f;
        CP_WAIT1();
        __syncthreads();

        // ---- QK: Qh*Kh + Qh*Kl ----
        float accS[2][8][4];
#pragma unroll
        for (int mt = 0; mt < 2; mt++)
#pragma unroll
            for (int nt = 0; nt < 8; nt++)
#pragma unroll
                for (int e = 0; e < 4; e++) accS[mt][nt][e] = 0.0f;

        const uint32_t bN = (lane & 7) + ((lane >> 4) & 1) * 8;
        const uint32_t bK = ((lane >> 3) & 1) * 8;
#pragma unroll
        for (int pass = 0; pass < 2; pass++) {
            const uint32_t kbase = sb + (pass ? OFF_KL : OFF_KH);
#pragma unroll
            for (int kc = 0; kc < 4; kc++) {
                uint32_t bf[4][4];
#pragma unroll
                for (int np = 0; np < 4; np++)
                    ldsm4(bf[np], kbase + (n0q + np * 16 + bN) * KROWB + (kc * 16 + bK) * 2);
#pragma unroll
                for (int mt = 0; mt < 2; mt++)
#pragma unroll
                    for (int nt = 0; nt < 8; nt++)
                        mma16816h(accS[mt][nt], qfh[mt][kc], &bf[nt >> 1][(nt & 1) * 2]);
            }
        }

        // ---- mask + scale ----
        const bool diag = (kt == qt);
#pragma unroll
        for (int mt = 0; mt < 2; mt++)
#pragma unroll
            for (int nt = 0; nt < 8; nt++)
#pragma unroll
                for (int e = 0; e < 4; e++) {
                    int rl = m0 + mt * 16 + (lane >> 2) + (e >> 1) * 8;
                    int cl = n0q + nt * 8 + (lane & 3) * 2 + (e & 1);
                    float s = accS[mt][nt][e] * 0.125f + pmm[cl];
                    if (diag && cl > rl) s = NEGV;
                    accS[mt][nt][e] = s;
                }

        // ---- row max ----
#pragma unroll
        for (int mt = 0; mt < 2; mt++)
#pragma unroll
            for (int hh = 0; hh < 2; hh++) {
                float mx = -1e30f;
#pragma unroll
                for (int nt = 0; nt < 8; nt++) {
                    mx = fmaxf(mx, accS[mt][nt][hh * 2]);
                    mx = fmaxf(mx, accS[mt][nt][hh * 2 + 1]);
                }
                mx = fmaxf(mx, __shfl_xor_sync(0xffffffff, mx, 1));
                mx = fmaxf(mx, __shfl_xor_sync(0xffffffff, mx, 2));
                if ((lane & 3) == 0)
                    rmax[(wid & 1) * 128 + m0 + mt * 16 + (lane >> 2) + hh * 8] = mx;
            }
        __syncthreads();

        // ---- softmax + P (fp16) + O rescale ----
        float alpha[2][2], mnew[2][2];
#pragma unroll
        for (int mt = 0; mt < 2; mt++)
#pragma unroll
            for (int hh = 0; hh < 2; hh++) {
                int rl = m0 + mt * 16 + (lane >> 2) + hh * 8;
                float mo = msm[rl];
                float mx = fmaxf(fmaxf(rmax[rl], rmax[128 + rl]), mo);
                mnew[mt][hh] = mx;
                alpha[mt][hh] = __expf(mo - mx);
                float ps = 0.0f;
#pragma unroll
                for (int nt = 0; nt < 8; nt++) {
                    float p0 = __expf(accS[mt][nt][hh * 2] - mx);
                    float p1 = __expf(accS[mt][nt][hh * 2 + 1] - mx);
                    ps += p0 + p1;
                    int cl = n0q + nt * 8 + (lane & 3) * 2;
                    *(__half2*)(sm + OFF_P + rl * PROWB + cl * 2) =
                        __halves2half2(__float2half_rn(p0), __float2half_rn(p1));
                }
                ps += __shfl_xor_sync(0xffffffff, ps, 1);
                ps += __shfl_xor_sync(0xffffffff, ps, 2);
                if ((lane & 3) == 0) rsum[(wid & 1) * 128 + rl] = ps;
#pragma unroll
                for (int nt = 0; nt < 4; nt++) {
                    accO[mt][nt][hh * 2]     *= alpha[mt][hh];
                    accO[mt][nt][hh * 2 + 1] *= alpha[mt][hh];
                }
            }
        CP_WAIT0();
        __syncthreads();

        if ((wid & 1) == 0 && (lane & 3) == 0) {
#pragma unroll
            for (int mt = 0; mt < 2; mt++)
#pragma unroll
                for (int hh = 0; hh < 2; hh++) {
                    int rl = m0 + mt * 16 + (lane >> 2) + hh * 8;
                    lsm[rl] = lsm[rl] * alpha[mt][hh] + rsum[rl] + rsum[128 + rl];
                    msm[rl] = mnew[mt][hh];
                }
        }

        // ---- PV: P*Vh ----
        const uint32_t arow = lane & 15, akk = (lane >> 4) * 8;
#pragma unroll
        for (int kc = 0; kc < 8; kc++) {
            uint32_t pf[2][4], vf[2][4];
#pragma unroll
            for (int mt = 0; mt < 2; mt++)
                ldsm4(pf[mt], sb + OFF_P + (m0 + mt * 16 + arow) * PROWB + (kc * 16 + akk) * 2);
#pragma unroll
            for (int ng = 0; ng < 2; ng++)
                ldsm4_t(vf[ng], sb + OFF_VH + (kc * 16 + arow) * KROWB + (n0v + ng * 16 + akk) * 2);
#pragma unroll
            for (int mt = 0; mt < 2; mt++)
#pragma unroll
                for (int nt = 0; nt < 4; nt++)
                    mma16816h(accO[mt][nt], pf[mt], &vf[nt >> 1][(nt & 1) * 2]);
        }
    }

    __syncthreads();
#pragma unroll
    for (int mt = 0; mt < 2; mt++)
#pragma unroll
        for (int hh = 0; hh < 2; hh++) {
            int rl = m0 + mt * 16 + (lane >> 2) + hh * 8;
            float inv = 1.0f / lsm[rl];
            size_t orow = (size_t)(b * S_ + q0 + rl) * 1024 + h * 64;
#pragma unroll
            for (int nt = 0; nt < 4; nt++) {
                float x = accO[mt][nt][hh * 2] * inv;
                float y = accO[mt][nt][hh * 2 + 1] * inv;
                int col = n0v + nt * 8 + (lane & 3) * 2;
                *(__half2*)(ctx + orow + col) =
                    __halves2half2(__float2half_rn(x), __float2half_rn(y));
            }
        }
}

// ================= launch =================
extern "C" void kernel_launch(void* const* d_in, const int* in_sizes, int n_in,
                              void* d_out, int out_size)
{
    const float* q    = (const float*)d_in[0];
    const float* k    = (const float*)d_in[1];
    const float* v    = (const float*)d_in[2];
    const int*   mask = (const int*)d_in[3];
    const float* Wq   = (const float*)d_in[4];
    const float* Wk   = (const float*)d_in[5];
    const float* Wv   = (const float*)d_in[6];
    const float* Wo   = (const float*)d_in[7];
    float* out = (float*)d_out;

    const int ME = B_ * S_ * D_;
    const int WE = D_ * D_;

    float *gQ, *gK, *gV, *gctx;
    cudaGetSymbolAddress((void**)&gQ,  g_Q);
    cudaGetSymbolAddress((void**)&gK,  g_K);
    cudaGetSymbolAddress((void**)&gV,  g_V);
    cudaGetSymbolAddress((void**)&gctx, g_ctx);
    __half* Qhd = (__half*)gQ;  __half* Qld = Qhd + ME;
    __half* Khd = (__half*)gK;  __half* Kld = Khd + ME;
    __half* Vhd = (__half*)gV;  __half* Vld = Vhd + ME;
    __half* Chd = (__half*)gctx;

    __half *qf, *kf, *vf;
    __half *wqh,*wql,*wkh,*wkl,*wvh,*wvl,*woh,*wol;
    cudaGetSymbolAddress((void**)&qf, g_qhi);
    cudaGetSymbolAddress((void**)&kf, g_khi);
    cudaGetSymbolAddress((void**)&vf, g_vhi);
    cudaGetSymbolAddress((void**)&wqh, g_wqhi); cudaGetSymbolAddress((void**)&wql, g_wqlo);
    cudaGetSymbolAddress((void**)&wkh, g_wkhi); cudaGetSymbolAddress((void**)&wkl, g_wklo);
    cudaGetSymbolAddress((void**)&wvh, g_wvhi); cudaGetSymbolAddress((void**)&wvl, g_wvlo);
    cudaGetSymbolAddress((void**)&woh, g_wohi); cudaGetSymbolAddress((void**)&wol, g_wolo);

    {
        CastArgs a0{q, qf}, a1{k, kf}, a2{v, vf};
        dim3 gr(ME / 1024, 1, 3);
        convert_f16<<<gr, 256>>>(a0, a1, a2);
    }
    {
        ConvW a0{Wq, wqh, wql}, a1{Wk, wkh, wkl}, a2{Wv, wvh, wvl}, a3{Wo, woh, wol};
        dim3 gr(WE / 1024, 1, 4);
        convert_hilo16<<<gr, 256>>>(a0, a1, a2, a3);
    }

    cudaFuncSetAttribute(gemm_mma, cudaFuncAttributeMaxDynamicSharedMemorySize,
                         GEMM_SMEM_BYTES);

    {
        GemmArgs g0{qf, wqh, wql, nullptr, Qhd, Qld, 1};
        GemmArgs g1{kf, wkh, wkl, nullptr, Khd, Kld, 1};
        GemmArgs g2{vf, wvh, wvl, nullptr, Vhd, Vld, 1};
        dim3 gr(D_ / 128, (B_ * S_) / 128, 3);
        gemm_mma<<<gr, 256, GEMM_SMEM_BYTES>>>(g0, g1, g2);
    }

    {
        cudaFuncSetAttribute(attn_tc, cudaFuncAttributeMaxDynamicSharedMemorySize,
                             ATTN_SMEM);
        dim3 ga(S_ / 128, H_, B_);
        attn_tc<<<ga, 256, ATTN_SMEM>>>(Qhd, Khd, Kld, Vhd, mask, Chd);
    }

    {
        GemmArgs g0{Chd, woh, wol, out, nullptr, nullptr, 0};
        dim3 gr(D_ / 128, (B_ * S_) / 128, 1);
        gemm_mma<<<gr, 256, GEMM_SMEM_BYTES>>>(g0, g0, g0);
    }
}

// round 13
// speedup vs baseline: 4.8943x; 1.1236x over previous
#include <cuda_runtime.h>
#include <cuda_bf16.h>
#include <cuda_fp16.h>
#include <cstdint>
#include <math.h>

#define B_  2
#define S_  2048
#define D_  1024
#define H_  16
#define DH_ 64
#define NEGV -1000000000.0f

// ================= helpers =================
__device__ __forceinline__ uint32_t smem_to_u32(const void* p) {
    uint32_t a;
    asm("{ .reg .u64 t; cvta.to.shared.u64 t, %1; cvt.u32.u64 %0, t; }"
        : "=r"(a) : "l"(p));
    return a;
}
__device__ __forceinline__ void ldsm4(uint32_t* r, uint32_t addr) {
    asm volatile("ldmatrix.sync.aligned.m8n8.x4.shared.b16 {%0,%1,%2,%3}, [%4];"
        : "=r"(r[0]), "=r"(r[1]), "=r"(r[2]), "=r"(r[3]) : "r"(addr));
}
__device__ __forceinline__ void ldsm4_t(uint32_t* r, uint32_t addr) {
    asm volatile("ldmatrix.sync.aligned.m8n8.x4.trans.shared.b16 {%0,%1,%2,%3}, [%4];"
        : "=r"(r[0]), "=r"(r[1]), "=r"(r[2]), "=r"(r[3]) : "r"(addr));
}
__device__ __forceinline__ void mma16816h(float* d, const uint32_t* a, const uint32_t* b) {
    asm volatile("mma.sync.aligned.m16n8k16.row.col.f32.f16.f16.f32 "
        "{%0,%1,%2,%3}, {%4,%5,%6,%7}, {%8,%9}, {%0,%1,%2,%3};"
        : "+f"(d[0]), "+f"(d[1]), "+f"(d[2]), "+f"(d[3])
        : "r"(a[0]), "r"(a[1]), "r"(a[2]), "r"(a[3]), "r"(b[0]), "r"(b[1]));
}
__device__ __forceinline__ void cp16(uint32_t smem, const void* g) {
    asm volatile("cp.async.cg.shared.global [%0], [%1], 16;" :: "r"(smem), "l"(g));
}
#define CP_COMMIT() asm volatile("cp.async.commit_group;" ::: "memory")
#define CP_WAIT0()  asm volatile("cp.async.wait_group 0;" ::: "memory")

// ================= scratch =================
__device__ float g_Q[B_ * S_ * D_];     // Q head-major fp16 (half used)
__device__ float g_K[B_ * S_ * D_];
__device__ float g_V[B_ * S_ * D_];
__device__ float g_ctx[B_ * S_ * D_];   // ctx fp16 (half used)

__device__ __nv_bfloat16 g_qhi[B_ * S_ * D_];   // input fp16 casts
__device__ __nv_bfloat16 g_khi[B_ * S_ * D_];
__device__ __nv_bfloat16 g_vhi[B_ * S_ * D_];
__device__ __nv_bfloat16 g_wqhi[D_ * D_], g_wqlo[D_ * D_];
__device__ __nv_bfloat16 g_wkhi[D_ * D_], g_wklo[D_ * D_];
__device__ __nv_bfloat16 g_wvhi[D_ * D_], g_wvlo[D_ * D_];
__device__ __nv_bfloat16 g_wohi[D_ * D_], g_wolo[D_ * D_];

// ================= fp32 -> fp16 cast (inputs) =================
struct CastArgs { const float* s; __half* d; };

__global__ __launch_bounds__(256) void convert_f16(CastArgs a0, CastArgs a1, CastArgs a2) {
    CastArgs a = (blockIdx.z == 0) ? a0 : (blockIdx.z == 1) ? a1 : a2;
    size_t i4 = (size_t)blockIdx.x * 256 + threadIdx.x;
    float4 x = ((const float4*)a.s)[i4];
    __half2 p0 = __halves2half2(__float2half_rn(x.x), __float2half_rn(x.y));
    __half2 p1 = __halves2half2(__float2half_rn(x.z), __float2half_rn(x.w));
    uint2 v;
    v.x = reinterpret_cast<uint32_t&>(p0); v.y = reinterpret_cast<uint32_t&>(p1);
    ((uint2*)a.d)[i4] = v;
}

// ================= fp32 -> fp16 hi/lo (weights) =================
struct ConvW { const float* s; __half* h; __half* l; };

__global__ __launch_bounds__(256) void convert_hilo16(ConvW a0, ConvW a1,
                                                      ConvW a2, ConvW a3) {
    ConvW a = (blockIdx.z == 0) ? a0 : (blockIdx.z == 1) ? a1
            : (blockIdx.z == 2) ? a2 : a3;
    size_t i4 = (size_t)blockIdx.x * 256 + threadIdx.x;
    float4 x = ((const float4*)a.s)[i4];
    __half h0 = __float2half_rn(x.x), h1 = __float2half_rn(x.y);
    __half h2 = __float2half_rn(x.z), h3 = __float2half_rn(x.w);
    __half2 hp0 = __halves2half2(h0, h1);
    __half2 hp1 = __halves2half2(h2, h3);
    __half2 lp0 = __halves2half2(__float2half_rn(x.x - __half2float(h0)),
                                 __float2half_rn(x.y - __half2float(h1)));
    __half2 lp1 = __halves2half2(__float2half_rn(x.z - __half2float(h2)),
                                 __float2half_rn(x.w - __half2float(h3)));
    uint2 hv, lv;
    hv.x = reinterpret_cast<uint32_t&>(hp0); hv.y = reinterpret_cast<uint32_t&>(hp1);
    lv.x = reinterpret_cast<uint32_t&>(lp0); lv.y = reinterpret_cast<uint32_t&>(lp1);
    ((uint2*)a.h)[i4] = hv;
    ((uint2*)a.l)[i4] = lv;
}

// ================= mma.sync GEMM (fp16, 2 passes: Ah*Bh + Ah*Bl) =================
struct GemmArgs {
    const __half *ah, *bh, *bl;
    float* c;          // fp32 output (mode 0)
    __half *chi;       // head-major fp16 output (mode 1)
    int headmajor;
};

#define GEMM_SMEM_BYTES (2 * 3 * 10240)   // 61440
#define ROWB 80

__global__ __launch_bounds__(256) void gemm_mma(GemmArgs ga0, GemmArgs ga1, GemmArgs ga2) {
    extern __shared__ char smx[];
    const GemmArgs g = (blockIdx.z == 0) ? ga0 : (blockIdx.z == 1) ? ga1 : ga2;

    const int tid  = threadIdx.x;
    const int lane = tid & 31;
    const int wid  = tid >> 5;
    const int bm = blockIdx.y * 128;
    const int bn = blockIdx.x * 128;
    const uint32_t sbase = smem_to_u32(smx);

    const int m0 = (wid >> 1) * 32;
    const int n0 = (wid & 1) * 64;

    float acc[2][8][4];
#pragma unroll
    for (int mt = 0; mt < 2; mt++)
#pragma unroll
        for (int nt = 0; nt < 8; nt++)
#pragma unroll
            for (int i = 0; i < 4; i++) acc[mt][nt][i] = 0.0f;

    const uint32_t aRow = lane & 15;
    const uint32_t aK   = (lane >> 4) * 8;
    const uint32_t bN   = (lane & 7) + ((lane >> 4) & 1) * 8;
    const uint32_t bK   = ((lane >> 3) & 1) * 8;

    auto load_chunk = [&](int c, int st) {
        const int k0 = c * 32;
#pragma unroll
        for (int p = 0; p < 6; p++) {
            int idx = tid + p * 256;
            int arr = idx >> 9;
            int r   = (idx >> 2) & 127;
            int c8  = (idx & 3) * 8;
            const __half* src = (arr == 0) ? g.ah : (arr == 1) ? g.bh : g.bl;
            int grow = ((arr == 0) ? bm : bn) + r;
            cp16(sbase + (uint32_t)(st * 3 + arr) * 10240 + r * ROWB + c8 * 2,
                 src + (size_t)grow * 1024 + k0 + c8);
        }
        CP_COMMIT();
    };

    load_chunk(0, 0);

    for (int c = 0; c < 32; c++) {
        const int st = c & 1;
        CP_WAIT0();
        __syncthreads();
        if (c < 31) load_chunk(c + 1, st ^ 1);

        const uint32_t aH = sbase + (uint32_t)(st * 3) * 10240;
        const uint32_t bH = aH + 10240;
        const uint32_t bL = bH + 10240;

#pragma unroll
        for (int ks = 0; ks < 2; ks++) {
            uint32_t af[2][4];
#pragma unroll
            for (int mt = 0; mt < 2; mt++)
                ldsm4(af[mt], aH + (m0 + mt * 16 + aRow) * ROWB + (ks * 16 + aK) * 2);
#pragma unroll
            for (int pass = 0; pass < 2; pass++) {
                const uint32_t bb = pass ? bL : bH;
                uint32_t bf[4][4];
#pragma unroll
                for (int np = 0; np < 4; np++)
                    ldsm4(bf[np], bb + (n0 + np * 16 + bN) * ROWB + (ks * 16 + bK) * 2);
#pragma unroll
                for (int mt = 0; mt < 2; mt++)
#pragma unroll
                    for (int nt = 0; nt < 8; nt++)
                        mma16816h(acc[mt][nt], af[mt], &bf[nt >> 1][(nt & 1) * 2]);
            }
        }
    }

    if (!g.headmajor) {
#pragma unroll
        for (int mt = 0; mt < 2; mt++)
#pragma unroll
            for (int nt = 0; nt < 8; nt++) {
                int row = bm + m0 + mt * 16 + (lane >> 2);
                int col = bn + n0 + nt * 8 + (lane & 3) * 2;
                *(float2*)(g.c + (size_t)row * 1024 + col) =
                    make_float2(acc[mt][nt][0], acc[mt][nt][1]);
                *(float2*)(g.c + (size_t)(row + 8) * 1024 + col) =
                    make_float2(acc[mt][nt][2], acc[mt][nt][3]);
            }
    } else {
#pragma unroll
        for (int mt = 0; mt < 2; mt++)
#pragma unroll
            for (int nt = 0; nt < 8; nt++) {
                int row = bm + m0 + mt * 16 + (lane >> 2);
                int col = bn + n0 + nt * 8 + (lane & 3) * 2;
                int bb2 = row >> 11, s = row & 2047, hh = col >> 6, dh = col & 63;
                size_t dst = ((size_t)(bb2 * H_ + hh) * S_ + s) * 64 + dh;
#pragma unroll
                for (int half = 0; half < 2; half++) {
                    float x = acc[mt][nt][half * 2], y = acc[mt][nt][half * 2 + 1];
                    size_t d2 = dst + half * 8 * 64;
                    *(__half2*)(g.chi + d2) =
                        __halves2half2(__float2half_rn(x), __float2half_rn(y));
                }
            }
    }
}

// ================= tensor-core flash attention (fp16, double-buffered K/V) =================
// QK: Qh*Kh 1-pass. PV: P*Vh 1-pass. K/V prefetched one tile ahead.
#define KROWB 144
#define PROWB 272
#define KHBUF(st) ((st) * 18432)
#define VHBUF(st) (36864 + (st) * 18432)
#define OFF_P    73728
#define OFF_PM   108544   // float[2][128]
#define OFF_MS   109568
#define OFF_LS   110080
#define OFF_RMAX 110592
#define OFF_RSUM 111616
#define ATTN_SMEM 112640

__global__ __launch_bounds__(256, 1) void attn_tc(
    const __half* __restrict__ Qh,
    const __half* __restrict__ Kh,
    const __half* __restrict__ Vh,
    const int* __restrict__ mask,
    __half* __restrict__ ctx)
{
    extern __shared__ char sm[];
    const uint32_t sb = smem_to_u32(sm);
    const int qt = (gridDim.x - 1) - blockIdx.x;
    const int h = blockIdx.y, b = blockIdx.z;
    const int tid = threadIdx.x, lane = tid & 31, wid = tid >> 5;
    const int m0  = (wid >> 1) * 32;
    const int n0q = (wid & 1) * 64;
    const int n0v = (wid & 1) * 32;
    const int q0 = qt * 128;
    const size_t bh = (size_t)(b * H_ + h) * S_;

    float* msm  = (float*)(sm + OFF_MS);
    float* lsm  = (float*)(sm + OFF_LS);
    float* pmm  = (float*)(sm + OFF_PM);    // [2][128]
    float* rmax = (float*)(sm + OFF_RMAX);
    float* rsum = (float*)(sm + OFF_RSUM);

    const int* mbase = mask + b * S_;

    auto load_tile = [&](int kt2, int st) {
        const int kk0 = kt2 * 128;
#pragma unroll
        for (int p = 0; p < 4; p++) {
            int i = tid + p * 256;
            int row = i >> 3, c16 = i & 7;
            cp16(sb + KHBUF(st) + row * KROWB + c16 * 16,
                 Kh + (bh + kk0 + row) * 64 + c16 * 8);
        }
#pragma unroll
        for (int p = 0; p < 4; p++) {
            int i = tid + p * 256;
            int row = i >> 3, c16 = i & 7;
            cp16(sb + VHBUF(st) + row * KROWB + c16 * 16,
                 Vh + (bh + kk0 + row) * 64 + c16 * 8);
        }
        CP_COMMIT();
    };

    // prologue: tile 0 + Q staging (into P region)
    load_tile(0, 0);
#pragma unroll
    for (int p = 0; p < 4; p++) {
        int i = tid + p * 256;
        int row = i >> 3, c16 = i & 7;
        cp16(sb + OFF_P + row * KROWB + c16 * 16,
             Qh + (bh + q0 + row) * 64 + c16 * 8);
    }
    CP_COMMIT();
    if (tid < 128) {
        msm[tid] = -1e30f; lsm[tid] = 0.0f;
        pmm[tid] = (mbase[tid] == 0) ? NEGV : 0.0f;   // tile 0 -> slot 0
    }
    CP_WAIT0();
    __syncthreads();

    uint32_t qfh[2][4][4];
    {
        const uint32_t arow = lane & 15, akk = (lane >> 4) * 8;
#pragma unroll
        for (int mt = 0; mt < 2; mt++)
#pragma unroll
            for (int kc = 0; kc < 4; kc++)
                ldsm4(qfh[mt][kc], sb + OFF_P + (m0 + mt * 16 + arow) * KROWB + (kc * 16 + akk) * 2);
    }

    float accO[2][4][4];
#pragma unroll
    for (int mt = 0; mt < 2; mt++)
#pragma unroll
        for (int nt = 0; nt < 4; nt++)
#pragma unroll
            for (int e = 0; e < 4; e++) accO[mt][nt][e] = 0.0f;

    for (int kt = 0; kt <= qt; kt++) {
        const int st = kt & 1;
        CP_WAIT0();
        __syncthreads();      // tile kt visible to all; prior iter fully done

        // prefetch tile kt+1 (overlaps all of this tile's compute)
        if (kt < qt) {
            load_tile(kt + 1, st ^ 1);
            if (tid < 128)
                pmm[(st ^ 1) * 128 + tid] =
                    (mbase[(kt + 1) * 128 + tid] == 0) ? NEGV : 0.0f;
        }

        // ---- QK: Qh*Kh (1 pass) ----
        float accS[2][8][4];
#pragma unroll
        for (int mt = 0; mt < 2; mt++)
#pragma unroll
            for (int nt = 0; nt < 8; nt++)
#pragma unroll
                for (int e = 0; e < 4; e++) accS[mt][nt][e] = 0.0f;

        const uint32_t bN = (lane & 7) + ((lane >> 4) & 1) * 8;
        const uint32_t bK = ((lane >> 3) & 1) * 8;
        const uint32_t kbase = sb + KHBUF(st);
#pragma unroll
        for (int kc = 0; kc < 4; kc++) {
            uint32_t bf[4][4];
#pragma unroll
            for (int np = 0; np < 4; np++)
                ldsm4(bf[np], kbase + (n0q + np * 16 + bN) * KROWB + (kc * 16 + bK) * 2);
#pragma unroll
            for (int mt = 0; mt < 2; mt++)
#pragma unroll
                for (int nt = 0; nt < 8; nt++)
                    mma16816h(accS[mt][nt], qfh[mt][kc], &bf[nt >> 1][(nt & 1) * 2]);
        }

        // ---- mask + scale ----
        const bool diag = (kt == qt);
        const float* pmt = pmm + st * 128;
#pragma unroll
        for (int mt = 0; mt < 2; mt++)
#pragma unroll
            for (int nt = 0; nt < 8; nt++)
#pragma unroll
                for (int e = 0; e < 4; e++) {
                    int rl = m0 + mt * 16 + (lane >> 2) + (e >> 1) * 8;
                    int cl = n0q + nt * 8 + (lane & 3) * 2 + (e & 1);
                    float s = accS[mt][nt][e] * 0.125f + pmt[cl];
                    if (diag && cl > rl) s = NEGV;
                    accS[mt][nt][e] = s;
                }

        // ---- row max ----
#pragma unroll
        for (int mt = 0; mt < 2; mt++)
#pragma unroll
            for (int hh = 0; hh < 2; hh++) {
                float mx = -1e30f;
#pragma unroll
                for (int nt = 0; nt < 8; nt++) {
                    mx = fmaxf(mx, accS[mt][nt][hh * 2]);
                    mx = fmaxf(mx, accS[mt][nt][hh * 2 + 1]);
                }
                mx = fmaxf(mx, __shfl_xor_sync(0xffffffff, mx, 1));
                mx = fmaxf(mx, __shfl_xor_sync(0xffffffff, mx, 2));
                if ((lane & 3) == 0)
                    rmax[(wid & 1) * 128 + m0 + mt * 16 + (lane >> 2) + hh * 8] = mx;
            }
        __syncthreads();

        // ---- softmax + P (fp16) + O rescale ----
        float alpha[2][2], mnew[2][2];
#pragma unroll
        for (int mt = 0; mt < 2; mt++)
#pragma unroll
            for (int hh = 0; hh < 2; hh++) {
                int rl = m0 + mt * 16 + (lane >> 2) + hh * 8;
                float mo = msm[rl];
                float mx = fmaxf(fmaxf(rmax[rl], rmax[128 + rl]), mo);
                mnew[mt][hh] = mx;
                alpha[mt][hh] = __expf(mo - mx);
                float ps = 0.0f;
#pragma unroll
                for (int nt = 0; nt < 8; nt++) {
                    float p0 = __expf(accS[mt][nt][hh * 2] - mx);
                    float p1 = __expf(accS[mt][nt][hh * 2 + 1] - mx);
                    ps += p0 + p1;
                    int cl = n0q + nt * 8 + (lane & 3) * 2;
                    *(__half2*)(sm + OFF_P + rl * PROWB + cl * 2) =
                        __halves2half2(__float2half_rn(p0), __float2half_rn(p1));
                }
                ps += __shfl_xor_sync(0xffffffff, ps, 1);
                ps += __shfl_xor_sync(0xffffffff, ps, 2);
                if ((lane & 3) == 0) rsum[(wid & 1) * 128 + rl] = ps;
#pragma unroll
                for (int nt = 0; nt < 4; nt++) {
                    accO[mt][nt][hh * 2]     *= alpha[mt][hh];
                    accO[mt][nt][hh * 2 + 1] *= alpha[mt][hh];
                }
            }
        __syncthreads();      // P + rsum visible

        if ((wid & 1) == 0 && (lane & 3) == 0) {
#pragma unroll
            for (int mt = 0; mt < 2; mt++)
#pragma unroll
                for (int hh = 0; hh < 2; hh++) {
                    int rl = m0 + mt * 16 + (lane >> 2) + hh * 8;
                    lsm[rl] = lsm[rl] * alpha[mt][hh] + rsum[rl] + rsum[128 + rl];
                    msm[rl] = mnew[mt][hh];
                }
        }

        // ---- PV: P*Vh ----
        const uint32_t arow = lane & 15, akk = (lane >> 4) * 8;
        const uint32_t vbase = sb + VHBUF(st);
#pragma unroll
        for (int kc = 0; kc < 8; kc++) {
            uint32_t pf[2][4], vf[2][4];
#pragma unroll
            for (int mt = 0; mt < 2; mt++)
                ldsm4(pf[mt], sb + OFF_P + (m0 + mt * 16 + arow) * PROWB + (kc * 16 + akk) * 2);
#pragma unroll
            for (int ng = 0; ng < 2; ng++)
                ldsm4_t(vf[ng], vbase + (kc * 16 + arow) * KROWB + (n0v + ng * 16 + akk) * 2);
#pragma unroll
            for (int mt = 0; mt < 2; mt++)
#pragma unroll
                for (int nt = 0; nt < 4; nt++)
                    mma16816h(accO[mt][nt], pf[mt], &vf[nt >> 1][(nt & 1) * 2]);
        }
    }

    __syncthreads();
#pragma unroll
    for (int mt = 0; mt < 2; mt++)
#pragma unroll
        for (int hh = 0; hh < 2; hh++) {
            int rl = m0 + mt * 16 + (lane >> 2) + hh * 8;
            float inv = 1.0f / lsm[rl];
            size_t orow = (size_t)(b * S_ + q0 + rl) * 1024 + h * 64;
#pragma unroll
            for (int nt = 0; nt < 4; nt++) {
                float x = accO[mt][nt][hh * 2] * inv;
                float y = accO[mt][nt][hh * 2 + 1] * inv;
                int col = n0v + nt * 8 + (lane & 3) * 2;
                *(__half2*)(ctx + orow + col) =
                    __halves2half2(__float2half_rn(x), __float2half_rn(y));
            }
        }
}

// ================= launch =================
extern "C" void kernel_launch(void* const* d_in, const int* in_sizes, int n_in,
                              void* d_out, int out_size)
{
    const float* q    = (const float*)d_in[0];
    const float* k    = (const float*)d_in[1];
    const float* v    = (const float*)d_in[2];
    const int*   mask = (const int*)d_in[3];
    const float* Wq   = (const float*)d_in[4];
    const float* Wk   = (const float*)d_in[5];
    const float* Wv   = (const float*)d_in[6];
    const float* Wo   = (const float*)d_in[7];
    float* out = (float*)d_out;

    const int ME = B_ * S_ * D_;
    const int WE = D_ * D_;

    float *gQ, *gK, *gV, *gctx;
    cudaGetSymbolAddress((void**)&gQ,  g_Q);
    cudaGetSymbolAddress((void**)&gK,  g_K);
    cudaGetSymbolAddress((void**)&gV,  g_V);
    cudaGetSymbolAddress((void**)&gctx, g_ctx);
    __half* Qhd = (__half*)gQ;
    __half* Khd = (__half*)gK;
    __half* Vhd = (__half*)gV;
    __half* Chd = (__half*)gctx;

    __half *qf, *kf, *vf;
    __half *wqh,*wql,*wkh,*wkl,*wvh,*wvl,*woh,*wol;
    cudaGetSymbolAddress((void**)&qf, g_qhi);
    cudaGetSymbolAddress((void**)&kf, g_khi);
    cudaGetSymbolAddress((void**)&vf, g_vhi);
    cudaGetSymbolAddress((void**)&wqh, g_wqhi); cudaGetSymbolAddress((void**)&wql, g_wqlo);
    cudaGetSymbolAddress((void**)&wkh, g_wkhi); cudaGetSymbolAddress((void**)&wkl, g_wklo);
    cudaGetSymbolAddress((void**)&wvh, g_wvhi); cudaGetSymbolAddress((void**)&wvl, g_wvlo);
    cudaGetSymbolAddress((void**)&woh, g_wohi); cudaGetSymbolAddress((void**)&wol, g_wolo);

    {
        CastArgs a0{q, qf}, a1{k, kf}, a2{v, vf};
        dim3 gr(ME / 1024, 1, 3);
        convert_f16<<<gr, 256>>>(a0, a1, a2);
    }
    {
        ConvW a0{Wq, wqh, wql}, a1{Wk, wkh, wkl}, a2{Wv, wvh, wvl}, a3{Wo, woh, wol};
        dim3 gr(WE / 1024, 1, 4);
        convert_hilo16<<<gr, 256>>>(a0, a1, a2, a3);
    }

    cudaFuncSetAttribute(gemm_mma, cudaFuncAttributeMaxDynamicSharedMemorySize,
                         GEMM_SMEM_BYTES);

    {
        GemmArgs g0{qf, wqh, wql, nullptr, Qhd, 1};
        GemmArgs g1{kf, wkh, wkl, nullptr, Khd, 1};
        GemmArgs g2{vf, wvh, wvl, nullptr, Vhd, 1};
        dim3 gr(D_ / 128, (B_ * S_) / 128, 3);
        gemm_mma<<<gr, 256, GEMM_SMEM_BYTES>>>(g0, g1, g2);
    }

    {
        cudaFuncSetAttribute(attn_tc, cudaFuncAttributeMaxDynamicSharedMemorySize,
                             ATTN_SMEM);
        dim3 ga(S_ / 128, H_, B_);
        attn_tc<<<ga, 256, ATTN_SMEM>>>(Qhd, Khd, Vhd, mask, Chd);
    }

    {
        GemmArgs g0{Chd, woh, wol, out, nullptr, 0};
        dim3 gr(D_ / 128, (B_ * S_) / 128, 1);
        gemm_mma<<<gr, 256, GEMM_SMEM_BYTES>>>(g0, g0, g0);
    }
}

// round 14
// speedup vs baseline: 5.8560x; 1.1965x over previous
#include <cuda_runtime.h>
#include <cuda_bf16.h>
#include <cuda_fp16.h>
#include <cstdint>
#include <math.h>

#define B_  2
#define S_  2048
#define D_  1024
#define H_  16
#define DH_ 64
#define NEGV -1000000000.0f

// ================= helpers =================
__device__ __forceinline__ uint32_t smem_to_u32(const void* p) {
    uint32_t a;
    asm("{ .reg .u64 t; cvta.to.shared.u64 t, %1; cvt.u32.u64 %0, t; }"
        : "=r"(a) : "l"(p));
    return a;
}
__device__ __forceinline__ void ldsm4(uint32_t* r, uint32_t addr) {
    asm volatile("ldmatrix.sync.aligned.m8n8.x4.shared.b16 {%0,%1,%2,%3}, [%4];"
        : "=r"(r[0]), "=r"(r[1]), "=r"(r[2]), "=r"(r[3]) : "r"(addr));
}
__device__ __forceinline__ void ldsm4_t(uint32_t* r, uint32_t addr) {
    asm volatile("ldmatrix.sync.aligned.m8n8.x4.trans.shared.b16 {%0,%1,%2,%3}, [%4];"
        : "=r"(r[0]), "=r"(r[1]), "=r"(r[2]), "=r"(r[3]) : "r"(addr));
}
__device__ __forceinline__ void mma16816h(float* d, const uint32_t* a, const uint32_t* b) {
    asm volatile("mma.sync.aligned.m16n8k16.row.col.f32.f16.f16.f32 "
        "{%0,%1,%2,%3}, {%4,%5,%6,%7}, {%8,%9}, {%0,%1,%2,%3};"
        : "+f"(d[0]), "+f"(d[1]), "+f"(d[2]), "+f"(d[3])
        : "r"(a[0]), "r"(a[1]), "r"(a[2]), "r"(a[3]), "r"(b[0]), "r"(b[1]));
}
__device__ __forceinline__ void cp16(uint32_t smem, const void* g) {
    asm volatile("cp.async.cg.shared.global [%0], [%1], 16;" :: "r"(smem), "l"(g));
}
#define CP_COMMIT() asm volatile("cp.async.commit_group;" ::: "memory")
#define CP_WAIT0()  asm volatile("cp.async.wait_group 0;" ::: "memory")

// ================= scratch =================
__device__ float g_Q[B_ * S_ * D_];
__device__ float g_K[B_ * S_ * D_];
__device__ float g_V[B_ * S_ * D_];
__device__ float g_ctx[B_ * S_ * D_];

__device__ __nv_bfloat16 g_qhi[B_ * S_ * D_];
__device__ __nv_bfloat16 g_khi[B_ * S_ * D_];
__device__ __nv_bfloat16 g_vhi[B_ * S_ * D_];
__device__ __nv_bfloat16 g_wqhi[D_ * D_], g_wqlo[D_ * D_];
__device__ __nv_bfloat16 g_wkhi[D_ * D_], g_wklo[D_ * D_];
__device__ __nv_bfloat16 g_wvhi[D_ * D_], g_wvlo[D_ * D_];
__device__ __nv_bfloat16 g_wohi[D_ * D_], g_wolo[D_ * D_];

// ================= fp32 -> fp16 cast (inputs) =================
struct CastArgs { const float* s; __half* d; };

__global__ __launch_bounds__(256) void convert_f16(CastArgs a0, CastArgs a1, CastArgs a2) {
    CastArgs a = (blockIdx.z == 0) ? a0 : (blockIdx.z == 1) ? a1 : a2;
    size_t i4 = (size_t)blockIdx.x * 256 + threadIdx.x;
    float4 x = ((const float4*)a.s)[i4];
    __half2 p0 = __halves2half2(__float2half_rn(x.x), __float2half_rn(x.y));
    __half2 p1 = __halves2half2(__float2half_rn(x.z), __float2half_rn(x.w));
    uint2 v;
    v.x = reinterpret_cast<uint32_t&>(p0); v.y = reinterpret_cast<uint32_t&>(p1);
    ((uint2*)a.d)[i4] = v;
}

// ================= fp32 -> fp16 hi/lo (weights) =================
struct ConvW { const float* s; __half* h; __half* l; };

__global__ __launch_bounds__(256) void convert_hilo16(ConvW a0, ConvW a1,
                                                      ConvW a2, ConvW a3) {
    ConvW a = (blockIdx.z == 0) ? a0 : (blockIdx.z == 1) ? a1
            : (blockIdx.z == 2) ? a2 : a3;
    size_t i4 = (size_t)blockIdx.x * 256 + threadIdx.x;
    float4 x = ((const float4*)a.s)[i4];
    __half h0 = __float2half_rn(x.x), h1 = __float2half_rn(x.y);
    __half h2 = __float2half_rn(x.z), h3 = __float2half_rn(x.w);
    __half2 hp0 = __halves2half2(h0, h1);
    __half2 hp1 = __halves2half2(h2, h3);
    __half2 lp0 = __halves2half2(__float2half_rn(x.x - __half2float(h0)),
                                 __float2half_rn(x.y - __half2float(h1)));
    __half2 lp1 = __halves2half2(__float2half_rn(x.z - __half2float(h2)),
                                 __float2half_rn(x.w - __half2float(h3)));
    uint2 hv, lv;
    hv.x = reinterpret_cast<uint32_t&>(hp0); hv.y = reinterpret_cast<uint32_t&>(hp1);
    lv.x = reinterpret_cast<uint32_t&>(lp0); lv.y = reinterpret_cast<uint32_t&>(lp1);
    ((uint2*)a.h)[i4] = hv;
    ((uint2*)a.l)[i4] = lv;
}

// ================= mma.sync GEMM (fp16, npass passes) =================
struct GemmArgs {
    const __half *ah, *bh, *bl;
    float* c;          // fp32 output (mode 0)
    __half *chi;       // head-major fp16 output (mode 1)
    int headmajor;
    int npass;         // 1: Ah*Bh only; 2: + Ah*Bl
    float oscale;
};

#define GEMM_SMEM_BYTES (2 * 3 * 10240)
#define ROWB 80

__global__ __launch_bounds__(256) void gemm_mma(GemmArgs ga0, GemmArgs ga1, GemmArgs ga2) {
    extern __shared__ char smx[];
    const GemmArgs g = (blockIdx.z == 0) ? ga0 : (blockIdx.z == 1) ? ga1 : ga2;

    const int tid  = threadIdx.x;
    const int lane = tid & 31;
    const int wid  = tid >> 5;
    const int bm = blockIdx.y * 128;
    const int bn = blockIdx.x * 128;
    const uint32_t sbase = smem_to_u32(smx);

    const int m0 = (wid >> 1) * 32;
    const int n0 = (wid & 1) * 64;
    const int pmax = (g.npass == 2) ? 6 : 4;

    float acc[2][8][4];
#pragma unroll
    for (int mt = 0; mt < 2; mt++)
#pragma unroll
        for (int nt = 0; nt < 8; nt++)
#pragma unroll
            for (int i = 0; i < 4; i++) acc[mt][nt][i] = 0.0f;

    const uint32_t aRow = lane & 15;
    const uint32_t aK   = (lane >> 4) * 8;
    const uint32_t bN   = (lane & 7) + ((lane >> 4) & 1) * 8;
    const uint32_t bK   = ((lane >> 3) & 1) * 8;

    auto load_chunk = [&](int c, int st) {
        const int k0 = c * 32;
#pragma unroll
        for (int p = 0; p < 6; p++) {
            if (p >= pmax) break;
            int idx = tid + p * 256;
            int arr = idx >> 9;
            int r   = (idx >> 2) & 127;
            int c8  = (idx & 3) * 8;
            const __half* src = (arr == 0) ? g.ah : (arr == 1) ? g.bh : g.bl;
            int grow = ((arr == 0) ? bm : bn) + r;
            cp16(sbase + (uint32_t)(st * 3 + arr) * 10240 + r * ROWB + c8 * 2,
                 src + (size_t)grow * 1024 + k0 + c8);
        }
        CP_COMMIT();
    };

    load_chunk(0, 0);

    for (int c = 0; c < 32; c++) {
        const int st = c & 1;
        CP_WAIT0();
        __syncthreads();
        if (c < 31) load_chunk(c + 1, st ^ 1);

        const uint32_t aH = sbase + (uint32_t)(st * 3) * 10240;
        const uint32_t bH = aH + 10240;
        const uint32_t bL = bH + 10240;

#pragma unroll
        for (int ks = 0; ks < 2; ks++) {
            uint32_t af[2][4];
#pragma unroll
            for (int mt = 0; mt < 2; mt++)
                ldsm4(af[mt], aH + (m0 + mt * 16 + aRow) * ROWB + (ks * 16 + aK) * 2);
#pragma unroll
            for (int pass = 0; pass < 2; pass++) {
                if (pass && g.npass < 2) break;
                const uint32_t bb = pass ? bL : bH;
                uint32_t bf[4][4];
#pragma unroll
                for (int np = 0; np < 4; np++)
                    ldsm4(bf[np], bb + (n0 + np * 16 + bN) * ROWB + (ks * 16 + bK) * 2);
#pragma unroll
                for (int mt = 0; mt < 2; mt++)
#pragma unroll
                    for (int nt = 0; nt < 8; nt++)
                        mma16816h(acc[mt][nt], af[mt], &bf[nt >> 1][(nt & 1) * 2]);
            }
        }
    }

    if (!g.headmajor) {
#pragma unroll
        for (int mt = 0; mt < 2; mt++)
#pragma unroll
            for (int nt = 0; nt < 8; nt++) {
                int row = bm + m0 + mt * 16 + (lane >> 2);
                int col = bn + n0 + nt * 8 + (lane & 3) * 2;
                *(float2*)(g.c + (size_t)row * 1024 + col) =
                    make_float2(acc[mt][nt][0], acc[mt][nt][1]);
                *(float2*)(g.c + (size_t)(row + 8) * 1024 + col) =
                    make_float2(acc[mt][nt][2], acc[mt][nt][3]);
            }
    } else {
        const float sc = g.oscale;
#pragma unroll
        for (int mt = 0; mt < 2; mt++)
#pragma unroll
            for (int nt = 0; nt < 8; nt++) {
                int row = bm + m0 + mt * 16 + (lane >> 2);
                int col = bn + n0 + nt * 8 + (lane & 3) * 2;
                int bb2 = row >> 11, s = row & 2047, hh = col >> 6, dh = col & 63;
                size_t dst = ((size_t)(bb2 * H_ + hh) * S_ + s) * 64 + dh;
#pragma unroll
                for (int half = 0; half < 2; half++) {
                    float x = acc[mt][nt][half * 2] * sc;
                    float y = acc[mt][nt][half * 2 + 1] * sc;
                    size_t d2 = dst + half * 8 * 64;
                    *(__half2*)(g.chi + d2) =
                        __halves2half2(__float2half_rn(x), __float2half_rn(y));
                }
            }
    }
}

// ================= tensor-core flash attention =================
// Register-resident P (FA2 layout identity); each warp's PV covers its own
// 64-key slice x all 64 V cols; cross-warp-pair accO reduction at the end.
#define KROWB 144
#define KHBUF(st) ((st) * 18432)
#define VHBUF(st) (36864 + (st) * 18432)
#define OFF_QSTAGE VHBUF(1)
#define OFF_PM   73728     // float[2][128]
#define OFF_MS   74752
#define OFF_LS   75264
#define OFF_RMAX 75776     // float[2][128]
#define OFF_RSUM 76800     // float[2][128]
#define OFF_RED  0         // reduction buffer (reuses K area after loop)
#define ATTN_SMEM 77824

__global__ __launch_bounds__(256, 1) void attn_tc(
    const __half* __restrict__ Qh,
    const __half* __restrict__ Kh,
    const __half* __restrict__ Vh,
    const int* __restrict__ mask,
    __half* __restrict__ ctx)
{
    extern __shared__ char sm[];
    const uint32_t sb = smem_to_u32(sm);
    const int qt = (gridDim.x - 1) - blockIdx.x;
    const int h = blockIdx.y, b = blockIdx.z;
    const int tid = threadIdx.x, lane = tid & 31, wid = tid >> 5;
    const int m0  = (wid >> 1) * 32;
    const int n0q = (wid & 1) * 64;     // this warp's 64-key slice
    const int q0 = qt * 128;
    const size_t bh = (size_t)(b * H_ + h) * S_;

    float* msm  = (float*)(sm + OFF_MS);
    float* lsm  = (float*)(sm + OFF_LS);
    float* pmm  = (float*)(sm + OFF_PM);
    float* rmax = (float*)(sm + OFF_RMAX);
    float* rsum = (float*)(sm + OFF_RSUM);

    const int* mbase = mask + b * S_;

    auto load_tile = [&](int kt2, int st) {
        const int kk0 = kt2 * 128;
#pragma unroll
        for (int p = 0; p < 4; p++) {
            int i = tid + p * 256;
            int row = i >> 3, c16 = i & 7;
            cp16(sb + KHBUF(st) + row * KROWB + c16 * 16,
                 Kh + (bh + kk0 + row) * 64 + c16 * 8);
        }
#pragma unroll
        for (int p = 0; p < 4; p++) {
            int i = tid + p * 256;
            int row = i >> 3, c16 = i & 7;
            cp16(sb + VHBUF(st) + row * KROWB + c16 * 16,
                 Vh + (bh + kk0 + row) * 64 + c16 * 8);
        }
        CP_COMMIT();
    };

    // prologue: tile 0 + Q staging (into VHBUF(1), free until tile-1 prefetch)
    load_tile(0, 0);
#pragma unroll
    for (int p = 0; p < 4; p++) {
        int i = tid + p * 256;
        int row = i >> 3, c16 = i & 7;
        cp16(sb + OFF_QSTAGE + row * KROWB + c16 * 16,
             Qh + (bh + q0 + row) * 64 + c16 * 8);
    }
    CP_COMMIT();
    if (tid < 128) {
        msm[tid] = -1e30f; lsm[tid] = 0.0f;
        pmm[tid] = (mbase[tid] == 0) ? NEGV : 0.0f;
    }
    CP_WAIT0();
    __syncthreads();

    uint32_t qfh[2][4][4];
    {
        const uint32_t arow = lane & 15, akk = (lane >> 4) * 8;
#pragma unroll
        for (int mt = 0; mt < 2; mt++)
#pragma unroll
            for (int kc = 0; kc < 4; kc++)
                ldsm4(qfh[mt][kc], sb + OFF_QSTAGE + (m0 + mt * 16 + arow) * KROWB + (kc * 16 + akk) * 2);
    }

    float accO[2][8][4];
#pragma unroll
    for (int mt = 0; mt < 2; mt++)
#pragma unroll
        for (int nt = 0; nt < 8; nt++)
#pragma unroll
            for (int e = 0; e < 4; e++) accO[mt][nt][e] = 0.0f;

    for (int kt = 0; kt <= qt; kt++) {
        const int st = kt & 1;
        CP_WAIT0();
        __syncthreads();   // tile kt visible; Q frags already in regs

        if (kt < qt) {
            load_tile(kt + 1, st ^ 1);
            if (tid < 128)
                pmm[(st ^ 1) * 128 + tid] =
                    (mbase[(kt + 1) * 128 + tid] == 0) ? NEGV : 0.0f;
        }

        // ---- QK: Qh*Kh (scale pre-folded into Q) ----
        float accS[2][8][4];
#pragma unroll
        for (int mt = 0; mt < 2; mt++)
#pragma unroll
            for (int nt = 0; nt < 8; nt++)
#pragma unroll
                for (int e = 0; e < 4; e++) accS[mt][nt][e] = 0.0f;

        const uint32_t bN = (lane & 7) + ((lane >> 4) & 1) * 8;
        const uint32_t bK = ((lane >> 3) & 1) * 8;
        const uint32_t kbase = sb + KHBUF(st);
#pragma unroll
        for (int kc = 0; kc < 4; kc++) {
            uint32_t bf[4][4];
#pragma unroll
            for (int np = 0; np < 4; np++)
                ldsm4(bf[np], kbase + (n0q + np * 16 + bN) * KROWB + (kc * 16 + bK) * 2);
#pragma unroll
            for (int mt = 0; mt < 2; mt++)
#pragma unroll
                for (int nt = 0; nt < 8; nt++)
                    mma16816h(accS[mt][nt], qfh[mt][kc], &bf[nt >> 1][(nt & 1) * 2]);
        }

        // ---- mask ----
        const bool diag = (kt == qt);
        const float* pmt = pmm + st * 128;
#pragma unroll
        for (int mt = 0; mt < 2; mt++)
#pragma unroll
            for (int nt = 0; nt < 8; nt++)
#pragma unroll
                for (int e = 0; e < 4; e++) {
                    int rl = m0 + mt * 16 + (lane >> 2) + (e >> 1) * 8;
                    int cl = n0q + nt * 8 + (lane & 3) * 2 + (e & 1);
                    float s = accS[mt][nt][e] + pmt[cl];
                    if (diag && cl > rl) s = NEGV;
                    accS[mt][nt][e] = s;
                }

        // ---- row max (cross warp-pair via smem) ----
#pragma unroll
        for (int mt = 0; mt < 2; mt++)
#pragma unroll
            for (int hh = 0; hh < 2; hh++) {
                float mx = -1e30f;
#pragma unroll
                for (int nt = 0; nt < 8; nt++) {
                    mx = fmaxf(mx, accS[mt][nt][hh * 2]);
                    mx = fmaxf(mx, accS[mt][nt][hh * 2 + 1]);
                }
                mx = fmaxf(mx, __shfl_xor_sync(0xffffffff, mx, 1));
                mx = fmaxf(mx, __shfl_xor_sync(0xffffffff, mx, 2));
                if ((lane & 3) == 0)
                    rmax[(wid & 1) * 128 + m0 + mt * 16 + (lane >> 2) + hh * 8] = mx;
            }
        __syncthreads();

        // ---- softmax: exp into register P fragments ----
        uint32_t pfrag[2][4][4];
        float alpha[2][2], mnew[2][2];
#pragma unroll
        for (int mt = 0; mt < 2; mt++)
#pragma unroll
            for (int hh = 0; hh < 2; hh++) {
                int rl = m0 + mt * 16 + (lane >> 2) + hh * 8;
                float mo = msm[rl];
                float mx = fmaxf(fmaxf(rmax[rl], rmax[128 + rl]), mo);
                mnew[mt][hh] = mx;
                alpha[mt][hh] = __expf(mo - mx);
                float ps = 0.0f;
#pragma unroll
                for (int nt = 0; nt < 8; nt++) {
                    float p0 = __expf(accS[mt][nt][hh * 2] - mx);
                    float p1 = __expf(accS[mt][nt][hh * 2 + 1] - mx);
                    ps += p0 + p1;
                    __half2 ph = __halves2half2(__float2half_rn(p0), __float2half_rn(p1));
                    pfrag[mt][nt >> 1][(nt & 1) * 2 + hh] = reinterpret_cast<uint32_t&>(ph);
                }
                ps += __shfl_xor_sync(0xffffffff, ps, 1);
                ps += __shfl_xor_sync(0xffffffff, ps, 2);
                if ((lane & 3) == 0) rsum[(wid & 1) * 128 + rl] = ps;
#pragma unroll
                for (int nt = 0; nt < 8; nt++) {
                    accO[mt][nt][hh * 2]     *= alpha[mt][hh];
                    accO[mt][nt][hh * 2 + 1] *= alpha[mt][hh];
                }
            }
        __syncthreads();   // rsum visible

        if ((wid & 1) == 0 && (lane & 3) == 0) {
#pragma unroll
            for (int mt = 0; mt < 2; mt++)
#pragma unroll
                for (int hh = 0; hh < 2; hh++) {
                    int rl = m0 + mt * 16 + (lane >> 2) + hh * 8;
                    lsm[rl] = lsm[rl] * alpha[mt][hh] + rsum[rl] + rsum[128 + rl];
                    msm[rl] = mnew[mt][hh];
                }
        }

        // ---- PV: register P x V (this warp's 64-key slice, all 64 cols) ----
        const uint32_t arow = lane & 15, akk = (lane >> 4) * 8;
        const uint32_t vbase = sb + VHBUF(st);
#pragma unroll
        for (int kc = 0; kc < 4; kc++) {
            uint32_t vf[4][4];
#pragma unroll
            for (int ng = 0; ng < 4; ng++)
                ldsm4_t(vf[ng], vbase + (n0q + kc * 16 + arow) * KROWB + (ng * 16 + akk) * 2);
#pragma unroll
            for (int mt = 0; mt < 2; mt++)
#pragma unroll
                for (int nt = 0; nt < 8; nt++)
                    mma16816h(accO[mt][nt], pfrag[mt][kc], &vf[nt >> 1][(nt & 1) * 2]);
        }
    }

    // ---- cross-warp-pair accO reduction + epilogue ----
    __syncthreads();
    float* red = (float*)(sm + OFF_RED);
    const int pairIdx = wid >> 1;
    if (wid & 1) {
#pragma unroll
        for (int mt = 0; mt < 2; mt++)
#pragma unroll
            for (int nt = 0; nt < 8; nt++)
#pragma unroll
                for (int e = 0; e < 4; e++) {
                    int r = mt * 16 + (lane >> 2) + (e >> 1) * 8;
                    int cl = nt * 8 + (lane & 3) * 2 + (e & 1);
                    red[pairIdx * 2048 + r * 64 + cl] = accO[mt][nt][e];
                }
    }
    __syncthreads();
    if ((wid & 1) == 0) {
#pragma unroll
        for (int mt = 0; mt < 2; mt++)
#pragma unroll
            for (int hh = 0; hh < 2; hh++) {
                int r  = mt * 16 + (lane >> 2) + hh * 8;
                int rl = m0 + r;
                float inv = 1.0f / lsm[rl];
                size_t orow = (size_t)(b * S_ + q0 + rl) * 1024 + h * 64;
#pragma unroll
                for (int nt = 0; nt < 8; nt++) {
                    int cl = nt * 8 + (lane & 3) * 2;
                    float x = (accO[mt][nt][hh * 2]     + red[pairIdx * 2048 + r * 64 + cl])     * inv;
                    float y = (accO[mt][nt][hh * 2 + 1] + red[pairIdx * 2048 + r * 64 + cl + 1]) * inv;
                    *(__half2*)(ctx + orow + cl) =
                        __halves2half2(__float2half_rn(x), __float2half_rn(y));
                }
            }
    }
}

// ================= launch =================
extern "C" void kernel_launch(void* const* d_in, const int* in_sizes, int n_in,
                              void* d_out, int out_size)
{
    const float* q    = (const float*)d_in[0];
    const float* k    = (const float*)d_in[1];
    const float* v    = (const float*)d_in[2];
    const int*   mask = (const int*)d_in[3];
    const float* Wq   = (const float*)d_in[4];
    const float* Wk   = (const float*)d_in[5];
    const float* Wv   = (const float*)d_in[6];
    const float* Wo   = (const float*)d_in[7];
    float* out = (float*)d_out;

    const int ME = B_ * S_ * D_;
    const int WE = D_ * D_;

    float *gQ, *gK, *gV, *gctx;
    cudaGetSymbolAddress((void**)&gQ,  g_Q);
    cudaGetSymbolAddress((void**)&gK,  g_K);
    cudaGetSymbolAddress((void**)&gV,  g_V);
    cudaGetSymbolAddress((void**)&gctx, g_ctx);
    __half* Qhd = (__half*)gQ;
    __half* Khd = (__half*)gK;
    __half* Vhd = (__half*)gV;
    __half* Chd = (__half*)gctx;

    __half *qf, *kf, *vf;
    __half *wqh,*wql,*wkh,*wkl,*wvh,*wvl,*woh,*wol;
    cudaGetSymbolAddress((void**)&qf, g_qhi);
    cudaGetSymbolAddress((void**)&kf, g_khi);
    cudaGetSymbolAddress((void**)&vf, g_vhi);
    cudaGetSymbolAddress((void**)&wqh, g_wqhi); cudaGetSymbolAddress((void**)&wql, g_wqlo);
    cudaGetSymbolAddress((void**)&wkh, g_wkhi); cudaGetSymbolAddress((void**)&wkl, g_wklo);
    cudaGetSymbolAddress((void**)&wvh, g_wvhi); cudaGetSymbolAddress((void**)&wvl, g_wvlo);
    cudaGetSymbolAddress((void**)&woh, g_wohi); cudaGetSymbolAddress((void**)&wol, g_wolo);

    {
        CastArgs a0{q, qf}, a1{k, kf}, a2{v, vf};
        dim3 gr(ME / 1024, 1, 3);
        convert_f16<<<gr, 256>>>(a0, a1, a2);
    }
    {
        ConvW a0{Wq, wqh, wql}, a1{Wk, wkh, wkl}, a2{Wv, wvh, wvl}, a3{Wo, woh, wol};
        dim3 gr(WE / 1024, 1, 4);
        convert_hilo16<<<gr, 256>>>(a0, a1, a2, a3);
    }

    cudaFuncSetAttribute(gemm_mma, cudaFuncAttributeMaxDynamicSharedMemorySize,
                         GEMM_SMEM_BYTES);

    {
        GemmArgs g0{qf, wqh, wql, nullptr, Qhd, 1, 2, 0.125f};
        GemmArgs g1{kf, wkh, wkl, nullptr, Khd, 1, 2, 1.0f};
        GemmArgs g2{vf, wvh, wvl, nullptr, Vhd, 1, 1, 1.0f};
        dim3 gr(D_ / 128, (B_ * S_) / 128, 3);
        gemm_mma<<<gr, 256, GEMM_SMEM_BYTES>>>(g0, g1, g2);
    }

    {
        cudaFuncSetAttribute(attn_tc, cudaFuncAttributeMaxDynamicSharedMemorySize,
                             ATTN_SMEM);
        dim3 ga(S_ / 128, H_, B_);
        attn_tc<<<ga, 256, ATTN_SMEM>>>(Qhd, Khd, Vhd, mask, Chd);
    }

    {
        GemmArgs g0{Chd, woh, wol, out, nullptr, 0, 1, 1.0f};
        dim3 gr(D_ / 128, (B_ * S_) / 128, 1);
        gemm_mma<<<gr, 256, GEMM_SMEM_BYTES>>>(g0, g0, g0);
    }
}

// round 15
// speedup vs baseline: 6.2610x; 1.0692x over previous
#include <cuda_runtime.h>
#include <cuda_bf16.h>
#include <cuda_fp16.h>
#include <cstdint>
#include <math.h>

#define B_  2
#define S_  2048
#define D_  1024
#define H_  16
#define DH_ 64
#define NEGV -1000000000.0f

// ================= helpers =================
__device__ __forceinline__ uint32_t smem_to_u32(const void* p) {
    uint32_t a;
    asm("{ .reg .u64 t; cvta.to.shared.u64 t, %1; cvt.u32.u64 %0, t; }"
        : "=r"(a) : "l"(p));
    return a;
}
__device__ __forceinline__ void ldsm4(uint32_t* r, uint32_t addr) {
    asm volatile("ldmatrix.sync.aligned.m8n8.x4.shared.b16 {%0,%1,%2,%3}, [%4];"
        : "=r"(r[0]), "=r"(r[1]), "=r"(r[2]), "=r"(r[3]) : "r"(addr));
}
__device__ __forceinline__ void ldsm4_t(uint32_t* r, uint32_t addr) {
    asm volatile("ldmatrix.sync.aligned.m8n8.x4.trans.shared.b16 {%0,%1,%2,%3}, [%4];"
        : "=r"(r[0]), "=r"(r[1]), "=r"(r[2]), "=r"(r[3]) : "r"(addr));
}
__device__ __forceinline__ void mma16816h(float* d, const uint32_t* a, const uint32_t* b) {
    asm volatile("mma.sync.aligned.m16n8k16.row.col.f32.f16.f16.f32 "
        "{%0,%1,%2,%3}, {%4,%5,%6,%7}, {%8,%9}, {%0,%1,%2,%3};"
        : "+f"(d[0]), "+f"(d[1]), "+f"(d[2]), "+f"(d[3])
        : "r"(a[0]), "r"(a[1]), "r"(a[2]), "r"(a[3]), "r"(b[0]), "r"(b[1]));
}
__device__ __forceinline__ void cp16(uint32_t smem, const void* g) {
    asm volatile("cp.async.cg.shared.global [%0], [%1], 16;" :: "r"(smem), "l"(g));
}
#define CP_COMMIT() asm volatile("cp.async.commit_group;" ::: "memory")
#define CP_WAIT0()  asm volatile("cp.async.wait_group 0;" ::: "memory")

// ================= scratch =================
__device__ float g_Q[B_ * S_ * D_];
__device__ float g_K[B_ * S_ * D_];
__device__ float g_V[B_ * S_ * D_];
__device__ float g_ctx[B_ * S_ * D_];

__device__ __nv_bfloat16 g_qhi[B_ * S_ * D_];
__device__ __nv_bfloat16 g_khi[B_ * S_ * D_];
__device__ __nv_bfloat16 g_vhi[B_ * S_ * D_];
__device__ __nv_bfloat16 g_wqhi[D_ * D_], g_wqlo[D_ * D_];
__device__ __nv_bfloat16 g_wkhi[D_ * D_], g_wklo[D_ * D_];
__device__ __nv_bfloat16 g_wvhi[D_ * D_], g_wvlo[D_ * D_];
__device__ __nv_bfloat16 g_wohi[D_ * D_], g_wolo[D_ * D_];

// ================= fp32 -> fp16 cast (inputs) =================
struct CastArgs { const float* s; __half* d; };

__global__ __launch_bounds__(256) void convert_f16(CastArgs a0, CastArgs a1, CastArgs a2) {
    CastArgs a = (blockIdx.z == 0) ? a0 : (blockIdx.z == 1) ? a1 : a2;
    size_t i4 = (size_t)blockIdx.x * 256 + threadIdx.x;
    float4 x = ((const float4*)a.s)[i4];
    __half2 p0 = __halves2half2(__float2half_rn(x.x), __float2half_rn(x.y));
    __half2 p1 = __halves2half2(__float2half_rn(x.z), __float2half_rn(x.w));
    uint2 v;
    v.x = reinterpret_cast<uint32_t&>(p0); v.y = reinterpret_cast<uint32_t&>(p1);
    ((uint2*)a.d)[i4] = v;
}

// ================= fp32 -> fp16 hi/lo (weights) =================
struct ConvW { const float* s; __half* h; __half* l; };

__global__ __launch_bounds__(256) void convert_hilo16(ConvW a0, ConvW a1,
                                                      ConvW a2, ConvW a3) {
    ConvW a = (blockIdx.z == 0) ? a0 : (blockIdx.z == 1) ? a1
            : (blockIdx.z == 2) ? a2 : a3;
    size_t i4 = (size_t)blockIdx.x * 256 + threadIdx.x;
    float4 x = ((const float4*)a.s)[i4];
    __half h0 = __float2half_rn(x.x), h1 = __float2half_rn(x.y);
    __half h2 = __float2half_rn(x.z), h3 = __float2half_rn(x.w);
    __half2 hp0 = __halves2half2(h0, h1);
    __half2 hp1 = __halves2half2(h2, h3);
    __half2 lp0 = __halves2half2(__float2half_rn(x.x - __half2float(h0)),
                                 __float2half_rn(x.y - __half2float(h1)));
    __half2 lp1 = __halves2half2(__float2half_rn(x.z - __half2float(h2)),
                                 __float2half_rn(x.w - __half2float(h3)));
    uint2 hv, lv;
    hv.x = reinterpret_cast<uint32_t&>(hp0); hv.y = reinterpret_cast<uint32_t&>(hp1);
    lv.x = reinterpret_cast<uint32_t&>(lp0); lv.y = reinterpret_cast<uint32_t&>(lp1);
    ((uint2*)a.h)[i4] = hv;
    ((uint2*)a.l)[i4] = lv;
}

// ================= mma.sync GEMM (fp16, npass passes) =================
struct GemmArgs {
    const __half *ah, *bh, *bl;
    float* c;
    __half *chi;
    int headmajor;
    int npass;
    float oscale;
};

#define GEMM_SMEM_BYTES (2 * 3 * 10240)
#define ROWB 80

__global__ __launch_bounds__(256) void gemm_mma(GemmArgs ga0, GemmArgs ga1, GemmArgs ga2) {
    extern __shared__ char smx[];
    const GemmArgs g = (blockIdx.z == 0) ? ga0 : (blockIdx.z == 1) ? ga1 : ga2;

    const int tid  = threadIdx.x;
    const int lane = tid & 31;
    const int wid  = tid >> 5;
    const int bm = blockIdx.y * 128;
    const int bn = blockIdx.x * 128;
    const uint32_t sbase = smem_to_u32(smx);

    const int m0 = (wid >> 1) * 32;
    const int n0 = (wid & 1) * 64;
    const int pmax = (g.npass == 2) ? 6 : 4;

    float acc[2][8][4];
#pragma unroll
    for (int mt = 0; mt < 2; mt++)
#pragma unroll
        for (int nt = 0; nt < 8; nt++)
#pragma unroll
            for (int i = 0; i < 4; i++) acc[mt][nt][i] = 0.0f;

    const uint32_t aRow = lane & 15;
    const uint32_t aK   = (lane >> 4) * 8;
    const uint32_t bN   = (lane & 7) + ((lane >> 4) & 1) * 8;
    const uint32_t bK   = ((lane >> 3) & 1) * 8;

    auto load_chunk = [&](int c, int st) {
        const int k0 = c * 32;
#pragma unroll
        for (int p = 0; p < 6; p++) {
            if (p >= pmax) break;
            int idx = tid + p * 256;
            int arr = idx >> 9;
            int r   = (idx >> 2) & 127;
            int c8  = (idx & 3) * 8;
            const __half* src = (arr == 0) ? g.ah : (arr == 1) ? g.bh : g.bl;
            int grow = ((arr == 0) ? bm : bn) + r;
            cp16(sbase + (uint32_t)(st * 3 + arr) * 10240 + r * ROWB + c8 * 2,
                 src + (size_t)grow * 1024 + k0 + c8);
        }
        CP_COMMIT();
    };

    load_chunk(0, 0);

    for (int c = 0; c < 32; c++) {
        const int st = c & 1;
        CP_WAIT0();
        __syncthreads();
        if (c < 31) load_chunk(c + 1, st ^ 1);

        const uint32_t aH = sbase + (uint32_t)(st * 3) * 10240;
        const uint32_t bH = aH + 10240;
        const uint32_t bL = bH + 10240;

#pragma unroll
        for (int ks = 0; ks < 2; ks++) {
            uint32_t af[2][4];
#pragma unroll
            for (int mt = 0; mt < 2; mt++)
                ldsm4(af[mt], aH + (m0 + mt * 16 + aRow) * ROWB + (ks * 16 + aK) * 2);
#pragma unroll
            for (int pass = 0; pass < 2; pass++) {
                if (pass && g.npass < 2) break;
                const uint32_t bb = pass ? bL : bH;
                uint32_t bf[4][4];
#pragma unroll
                for (int np = 0; np < 4; np++)
                    ldsm4(bf[np], bb + (n0 + np * 16 + bN) * ROWB + (ks * 16 + bK) * 2);
#pragma unroll
                for (int mt = 0; mt < 2; mt++)
#pragma unroll
                    for (int nt = 0; nt < 8; nt++)
                        mma16816h(acc[mt][nt], af[mt], &bf[nt >> 1][(nt & 1) * 2]);
            }
        }
    }

    if (!g.headmajor) {
#pragma unroll
        for (int mt = 0; mt < 2; mt++)
#pragma unroll
            for (int nt = 0; nt < 8; nt++) {
                int row = bm + m0 + mt * 16 + (lane >> 2);
                int col = bn + n0 + nt * 8 + (lane & 3) * 2;
                *(float2*)(g.c + (size_t)row * 1024 + col) =
                    make_float2(acc[mt][nt][0], acc[mt][nt][1]);
                *(float2*)(g.c + (size_t)(row + 8) * 1024 + col) =
                    make_float2(acc[mt][nt][2], acc[mt][nt][3]);
            }
    } else {
        const float sc = g.oscale;
#pragma unroll
        for (int mt = 0; mt < 2; mt++)
#pragma unroll
            for (int nt = 0; nt < 8; nt++) {
                int row = bm + m0 + mt * 16 + (lane >> 2);
                int col = bn + n0 + nt * 8 + (lane & 3) * 2;
                int bb2 = row >> 11, s = row & 2047, hh = col >> 6, dh = col & 63;
                size_t dst = ((size_t)(bb2 * H_ + hh) * S_ + s) * 64 + dh;
#pragma unroll
                for (int half = 0; half < 2; half++) {
                    float x = acc[mt][nt][half * 2] * sc;
                    float y = acc[mt][nt][half * 2 + 1] * sc;
                    size_t d2 = dst + half * 8 * 64;
                    *(__half2*)(g.chi + d2) =
                        __halves2half2(__float2half_rn(x), __float2half_rn(y));
                }
            }
    }
}

// ================= tensor-core flash attention (warp-row-stripe FA2) =================
// Each warp owns 16 q-rows x ALL 128 keys: softmax fully warp-local (shfl only),
// m/l in registers, register-resident P, 1 __syncthreads per tile.
// Q pre-scaled by 0.125*log2(e) in projection -> exp2f softmax.
#define KROWB 144
#define KHBUF(st) ((st) * 18432)
#define VHBUF(st) (36864 + (st) * 18432)
#define OFF_QSTAGE VHBUF(1)
#define OFF_PM   73728     // float[2][128]
#define ATTN_SMEM 74752

__global__ __launch_bounds__(256, 1) void attn_tc(
    const __half* __restrict__ Qh,
    const __half* __restrict__ Kh,
    const __half* __restrict__ Vh,
    const int* __restrict__ mask,
    __half* __restrict__ ctx)
{
    extern __shared__ char sm[];
    const uint32_t sb = smem_to_u32(sm);
    const int qt = (gridDim.x - 1) - blockIdx.x;
    const int h = blockIdx.y, b = blockIdx.z;
    const int tid = threadIdx.x, lane = tid & 31, wid = tid >> 5;
    const int m0 = wid * 16;            // this warp's 16 q-rows
    const int q0 = qt * 128;
    const size_t bh = (size_t)(b * H_ + h) * S_;

    float* pmm = (float*)(sm + OFF_PM);
    const int* mbase = mask + b * S_;

    auto load_tile = [&](int kt2, int st) {
        const int kk0 = kt2 * 128;
#pragma unroll
        for (int p = 0; p < 4; p++) {
            int i = tid + p * 256;
            int row = i >> 3, c16 = i & 7;
            cp16(sb + KHBUF(st) + row * KROWB + c16 * 16,
                 Kh + (bh + kk0 + row) * 64 + c16 * 8);
        }
#pragma unroll
        for (int p = 0; p < 4; p++) {
            int i = tid + p * 256;
            int row = i >> 3, c16 = i & 7;
            cp16(sb + VHBUF(st) + row * KROWB + c16 * 16,
                 Vh + (bh + kk0 + row) * 64 + c16 * 8);
        }
        CP_COMMIT();
    };

    // prologue
    load_tile(0, 0);
#pragma unroll
    for (int p = 0; p < 4; p++) {
        int i = tid + p * 256;
        int row = i >> 3, c16 = i & 7;
        cp16(sb + OFF_QSTAGE + row * KROWB + c16 * 16,
             Qh + (bh + q0 + row) * 64 + c16 * 8);
    }
    CP_COMMIT();
    if (tid < 128) pmm[tid] = (mbase[tid] == 0) ? NEGV : 0.0f;
    CP_WAIT0();
    __syncthreads();

    uint32_t qfh[4][4];
    {
        const uint32_t arow = lane & 15, akk = (lane >> 4) * 8;
#pragma unroll
        for (int kc = 0; kc < 4; kc++)
            ldsm4(qfh[kc], sb + OFF_QSTAGE + (m0 + arow) * KROWB + (kc * 16 + akk) * 2);
    }

    float accO[8][4];
#pragma unroll
    for (int nt = 0; nt < 8; nt++)
#pragma unroll
        for (int e = 0; e < 4; e++) accO[nt][e] = 0.0f;
    float mreg[2] = {-1e30f, -1e30f};
    float lreg[2] = {0.0f, 0.0f};

    const uint32_t bN = (lane & 7) + ((lane >> 4) & 1) * 8;
    const uint32_t bK = ((lane >> 3) & 1) * 8;
    const uint32_t arow = lane & 15, akk = (lane >> 4) * 8;

    for (int kt = 0; kt <= qt; kt++) {
        const int st = kt & 1;
        CP_WAIT0();
        __syncthreads();     // tile kt ready; all warps past previous tile

        if (kt < qt) {
            load_tile(kt + 1, st ^ 1);
            if (tid < 128)
                pmm[(st ^ 1) * 128 + tid] =
                    (mbase[(kt + 1) * 128 + tid] == 0) ? NEGV : 0.0f;
        }

        // ---- QK: 16 rows x 128 keys ----
        float accS[16][4];
#pragma unroll
        for (int nt = 0; nt < 16; nt++)
#pragma unroll
            for (int e = 0; e < 4; e++) accS[nt][e] = 0.0f;

        const uint32_t kbase = sb + KHBUF(st);
#pragma unroll
        for (int kc = 0; kc < 4; kc++) {
            uint32_t bf[8][4];
#pragma unroll
            for (int np = 0; np < 8; np++)
                ldsm4(bf[np], kbase + (np * 16 + bN) * KROWB + (kc * 16 + bK) * 2);
#pragma unroll
            for (int nt = 0; nt < 16; nt++)
                mma16816h(accS[nt], qfh[kc], &bf[nt >> 1][(nt & 1) * 2]);
        }

        // ---- mask (scores already in log2 domain via Q pre-scale) ----
        const bool diag = (kt == qt);
        const float* pmt = pmm + st * 128;
        const int r0 = m0 + (lane >> 2);
#pragma unroll
        for (int nt = 0; nt < 16; nt++) {
            int cl = nt * 8 + (lane & 3) * 2;
            float pm0 = pmt[cl], pm1 = pmt[cl + 1];
            accS[nt][0] += pm0; accS[nt][1] += pm1;
            accS[nt][2] += pm0; accS[nt][3] += pm1;
            if (diag) {
                if (cl     > r0)     accS[nt][0] = NEGV;
                if (cl + 1 > r0)     accS[nt][1] = NEGV;
                if (cl     > r0 + 8) accS[nt][2] = NEGV;
                if (cl + 1 > r0 + 8) accS[nt][3] = NEGV;
            }
        }

        // ---- warp-local softmax (exp2) ----
        uint32_t pfrag[8][4];
#pragma unroll
        for (int hh = 0; hh < 2; hh++) {
            float mx = -1e30f;
#pragma unroll
            for (int nt = 0; nt < 16; nt++) {
                mx = fmaxf(mx, accS[nt][hh * 2]);
                mx = fmaxf(mx, accS[nt][hh * 2 + 1]);
            }
            mx = fmaxf(mx, __shfl_xor_sync(0xffffffff, mx, 1));
            mx = fmaxf(mx, __shfl_xor_sync(0xffffffff, mx, 2));
            mx = fmaxf(mx, mreg[hh]);
            float alpha = exp2f(mreg[hh] - mx);
            mreg[hh] = mx;
            float ps = 0.0f;
#pragma unroll
            for (int nt = 0; nt < 16; nt++) {
                float p0 = exp2f(accS[nt][hh * 2] - mx);
                float p1 = exp2f(accS[nt][hh * 2 + 1] - mx);
                ps += p0 + p1;
                __half2 ph = __halves2half2(__float2half_rn(p0), __float2half_rn(p1));
                pfrag[nt >> 1][(nt & 1) * 2 + hh] = reinterpret_cast<uint32_t&>(ph);
            }
            ps += __shfl_xor_sync(0xffffffff, ps, 1);
            ps += __shfl_xor_sync(0xffffffff, ps, 2);
            lreg[hh] = lreg[hh] * alpha + ps;
#pragma unroll
            for (int nt = 0; nt < 8; nt++) {
                accO[nt][hh * 2]     *= alpha;
                accO[nt][hh * 2 + 1] *= alpha;
            }
        }

        // ---- PV: P(16x128) x V(128x64) ----
        const uint32_t vbase = sb + VHBUF(st);
#pragma unroll
        for (int kc = 0; kc < 8; kc++) {
            uint32_t vf[4][4];
#pragma unroll
            for (int ng = 0; ng < 4; ng++)
                ldsm4_t(vf[ng], vbase + (kc * 16 + arow) * KROWB + (ng * 16 + akk) * 2);
#pragma unroll
            for (int nt = 0; nt < 8; nt++)
                mma16816h(accO[nt], pfrag[kc], &vf[nt >> 1][(nt & 1) * 2]);
        }
    }

    // ---- epilogue: each warp writes its own 16 rows ----
#pragma unroll
    for (int hh = 0; hh < 2; hh++) {
        int rl = m0 + (lane >> 2) + hh * 8;
        float inv = 1.0f / lreg[hh];
        size_t orow = (size_t)(b * S_ + q0 + rl) * 1024 + h * 64;
#pragma unroll
        for (int nt = 0; nt < 8; nt++) {
            int cl = nt * 8 + (lane & 3) * 2;
            float x = accO[nt][hh * 2] * inv;
            float y = accO[nt][hh * 2 + 1] * inv;
            *(__half2*)(ctx + orow + cl) =
                __halves2half2(__float2half_rn(x), __float2half_rn(y));
        }
    }
}

// ================= launch =================
extern "C" void kernel_launch(void* const* d_in, const int* in_sizes, int n_in,
                              void* d_out, int out_size)
{
    const float* q    = (const float*)d_in[0];
    const float* k    = (const float*)d_in[1];
    const float* v    = (const float*)d_in[2];
    const int*   mask = (const int*)d_in[3];
    const float* Wq   = (const float*)d_in[4];
    const float* Wk   = (const float*)d_in[5];
    const float* Wv   = (const float*)d_in[6];
    const float* Wo   = (const float*)d_in[7];
    float* out = (float*)d_out;

    const int ME = B_ * S_ * D_;
    const int WE = D_ * D_;

    float *gQ, *gK, *gV, *gctx;
    cudaGetSymbolAddress((void**)&gQ,  g_Q);
    cudaGetSymbolAddress((void**)&gK,  g_K);
    cudaGetSymbolAddress((void**)&gV,  g_V);
    cudaGetSymbolAddress((void**)&gctx, g_ctx);
    __half* Qhd = (__half*)gQ;
    __half* Khd = (__half*)gK;
    __half* Vhd = (__half*)gV;
    __half* Chd = (__half*)gctx;

    __half *qf, *kf, *vf;
    __half *wqh,*wql,*wkh,*wkl,*wvh,*wvl,*woh,*wol;
    cudaGetSymbolAddress((void**)&qf, g_qhi);
    cudaGetSymbolAddress((void**)&kf, g_khi);
    cudaGetSymbolAddress((void**)&vf, g_vhi);
    cudaGetSymbolAddress((void**)&wqh, g_wqhi); cudaGetSymbolAddress((void**)&wql, g_wqlo);
    cudaGetSymbolAddress((void**)&wkh, g_wkhi); cudaGetSymbolAddress((void**)&wkl, g_wklo);
    cudaGetSymbolAddress((void**)&wvh, g_wvhi); cudaGetSymbolAddress((void**)&wvl, g_wvlo);
    cudaGetSymbolAddress((void**)&woh, g_wohi); cudaGetSymbolAddress((void**)&wol, g_wolo);

    {
        CastArgs a0{q, qf}, a1{k, kf}, a2{v, vf};
        dim3 gr(ME / 1024, 1, 3);
        convert_f16<<<gr, 256>>>(a0, a1, a2);
    }
    {
        ConvW a0{Wq, wqh, wql}, a1{Wk, wkh, wkl}, a2{Wv, wvh, wvl}, a3{Wo, woh, wol};
        dim3 gr(WE / 1024, 1, 4);
        convert_hilo16<<<gr, 256>>>(a0, a1, a2, a3);
    }

    cudaFuncSetAttribute(gemm_mma, cudaFuncAttributeMaxDynamicSharedMemorySize,
                         GEMM_SMEM_BYTES);

    {
        // Q scaled by 0.125 * log2(e) so softmax runs in exp2 domain
        GemmArgs g0{qf, wqh, wql, nullptr, Qhd, 1, 2, 0.1803368801111244f};
        GemmArgs g1{kf, wkh, wkl, nullptr, Khd, 1, 2, 1.0f};
        GemmArgs g2{vf, wvh, wvl, nullptr, Vhd, 1, 1, 1.0f};
        dim3 gr(D_ / 128, (B_ * S_) / 128, 3);
        gemm_mma<<<gr, 256, GEMM_SMEM_BYTES>>>(g0, g1, g2);
    }

    {
        cudaFuncSetAttribute(attn_tc, cudaFuncAttributeMaxDynamicSharedMemorySize,
                             ATTN_SMEM);
        dim3 ga(S_ / 128, H_, B_);
        attn_tc<<<ga, 256, ATTN_SMEM>>>(Qhd, Khd, Vhd, mask, Chd);
    }

    {
        GemmArgs g0{Chd, woh, wol, out, nullptr, 0, 1, 1.0f};
        dim3 gr(D_ / 128, (B_ * S_) / 128, 1);
        gemm_mma<<<gr, 256, GEMM_SMEM_BYTES>>>(g0, g0, g0);
    }
}

// round 16
// speedup vs baseline: 7.9610x; 1.2715x over previous
#include <cuda_runtime.h>
#include <cuda_bf16.h>
#include <cuda_fp16.h>
#include <cstdint>
#include <math.h>

#define B_  2
#define S_  2048
#define D_  1024
#define H_  16
#define DH_ 64
#define NEGV -1000000000.0f

// ================= helpers =================
__device__ __forceinline__ uint32_t smem_to_u32(const void* p) {
    uint32_t a;
    asm("{ .reg .u64 t; cvta.to.shared.u64 t, %1; cvt.u32.u64 %0, t; }"
        : "=r"(a) : "l"(p));
    return a;
}
__device__ __forceinline__ void ldsm4(uint32_t* r, uint32_t addr) {
    asm volatile("ldmatrix.sync.aligned.m8n8.x4.shared.b16 {%0,%1,%2,%3}, [%4];"
        : "=r"(r[0]), "=r"(r[1]), "=r"(r[2]), "=r"(r[3]) : "r"(addr));
}
__device__ __forceinline__ void ldsm4_t(uint32_t* r, uint32_t addr) {
    asm volatile("ldmatrix.sync.aligned.m8n8.x4.trans.shared.b16 {%0,%1,%2,%3}, [%4];"
        : "=r"(r[0]), "=r"(r[1]), "=r"(r[2]), "=r"(r[3]) : "r"(addr));
}
__device__ __forceinline__ void mma16816h(float* d, const uint32_t* a, const uint32_t* b) {
    asm volatile("mma.sync.aligned.m16n8k16.row.col.f32.f16.f16.f32 "
        "{%0,%1,%2,%3}, {%4,%5,%6,%7}, {%8,%9}, {%0,%1,%2,%3};"
        : "+f"(d[0]), "+f"(d[1]), "+f"(d[2]), "+f"(d[3])
        : "r"(a[0]), "r"(a[1]), "r"(a[2]), "r"(a[3]), "r"(b[0]), "r"(b[1]));
}
__device__ __forceinline__ void cp16(uint32_t smem, const void* g) {
    asm volatile("cp.async.cg.shared.global [%0], [%1], 16;" :: "r"(smem), "l"(g));
}
#define CP_COMMIT() asm volatile("cp.async.commit_group;" ::: "memory")
#define CP_WAIT0()  asm volatile("cp.async.wait_group 0;" ::: "memory")

// ================= scratch =================
__device__ float g_Q[B_ * S_ * D_];
__device__ float g_K[B_ * S_ * D_];
__device__ float g_V[B_ * S_ * D_];
__device__ float g_ctx[B_ * S_ * D_];

__device__ __nv_bfloat16 g_qhi[B_ * S_ * D_];
__device__ __nv_bfloat16 g_khi[B_ * S_ * D_];
__device__ __nv_bfloat16 g_vhi[B_ * S_ * D_];
__device__ __nv_bfloat16 g_wqhi[D_ * D_];
__device__ __nv_bfloat16 g_wkhi[D_ * D_];
__device__ __nv_bfloat16 g_wvhi[D_ * D_];
__device__ __nv_bfloat16 g_wohi[D_ * D_];

// ================= fp32 -> fp16 cast =================
struct CastArgs { const float* s; __half* d; };

__global__ __launch_bounds__(256) void convert_f16_3(CastArgs a0, CastArgs a1, CastArgs a2) {
    CastArgs a = (blockIdx.z == 0) ? a0 : (blockIdx.z == 1) ? a1 : a2;
    size_t i4 = (size_t)blockIdx.x * 256 + threadIdx.x;
    float4 x = ((const float4*)a.s)[i4];
    __half2 p0 = __halves2half2(__float2half_rn(x.x), __float2half_rn(x.y));
    __half2 p1 = __halves2half2(__float2half_rn(x.z), __float2half_rn(x.w));
    uint2 v;
    v.x = reinterpret_cast<uint32_t&>(p0); v.y = reinterpret_cast<uint32_t&>(p1);
    ((uint2*)a.d)[i4] = v;
}

__global__ __launch_bounds__(256) void convert_f16_4(CastArgs a0, CastArgs a1,
                                                     CastArgs a2, CastArgs a3) {
    CastArgs a = (blockIdx.z == 0) ? a0 : (blockIdx.z == 1) ? a1
               : (blockIdx.z == 2) ? a2 : a3;
    size_t i4 = (size_t)blockIdx.x * 256 + threadIdx.x;
    float4 x = ((const float4*)a.s)[i4];
    __half2 p0 = __halves2half2(__float2half_rn(x.x), __float2half_rn(x.y));
    __half2 p1 = __halves2half2(__float2half_rn(x.z), __float2half_rn(x.w));
    uint2 v;
    v.x = reinterpret_cast<uint32_t&>(p0); v.y = reinterpret_cast<uint32_t&>(p1);
    ((uint2*)a.d)[i4] = v;
}

// ================= mma.sync GEMM (pure fp16, 1 pass) =================
struct GemmArgs {
    const __half *ah, *bh;
    float* c;          // fp32 output (mode 0)
    __half *chi;       // head-major fp16 output (mode 1)
    int headmajor;
    float oscale;
};

#define GEMM_SMEM_BYTES (2 * 2 * 10240)   // 40960
#define ROWB 80

__global__ __launch_bounds__(256, 2) void gemm_mma(GemmArgs ga0, GemmArgs ga1, GemmArgs ga2) {
    extern __shared__ char smx[];
    const GemmArgs g = (blockIdx.z == 0) ? ga0 : (blockIdx.z == 1) ? ga1 : ga2;

    const int tid  = threadIdx.x;
    const int lane = tid & 31;
    const int wid  = tid >> 5;
    const int bm = blockIdx.y * 128;
    const int bn = blockIdx.x * 128;
    const uint32_t sbase = smem_to_u32(smx);

    const int m0 = (wid >> 1) * 32;
    const int n0 = (wid & 1) * 64;

    float acc[2][8][4];
#pragma unroll
    for (int mt = 0; mt < 2; mt++)
#pragma unroll
        for (int nt = 0; nt < 8; nt++)
#pragma unroll
            for (int i = 0; i < 4; i++) acc[mt][nt][i] = 0.0f;

    const uint32_t aRow = lane & 15;
    const uint32_t aK   = (lane >> 4) * 8;
    const uint32_t bN   = (lane & 7) + ((lane >> 4) & 1) * 8;
    const uint32_t bK   = ((lane >> 3) & 1) * 8;

    auto load_chunk = [&](int c, int st) {
        const int k0 = c * 32;
#pragma unroll
        for (int p = 0; p < 4; p++) {
            int idx = tid + p * 256;          // 0..1023
            int arr = idx >> 9;               // 0..1
            int r   = (idx >> 2) & 127;
            int c8  = (idx & 3) * 8;
            const __half* src = (arr == 0) ? g.ah : g.bh;
            int grow = ((arr == 0) ? bm : bn) + r;
            cp16(sbase + (uint32_t)(st * 2 + arr) * 10240 + r * ROWB + c8 * 2,
                 src + (size_t)grow * 1024 + k0 + c8);
        }
        CP_COMMIT();
    };

    load_chunk(0, 0);

    for (int c = 0; c < 32; c++) {
        const int st = c & 1;
        CP_WAIT0();
        __syncthreads();
        if (c < 31) load_chunk(c + 1, st ^ 1);

        const uint32_t aH = sbase + (uint32_t)(st * 2) * 10240;
        const uint32_t bH = aH + 10240;

#pragma unroll
        for (int ks = 0; ks < 2; ks++) {
            uint32_t af[2][4];
#pragma unroll
            for (int mt = 0; mt < 2; mt++)
                ldsm4(af[mt], aH + (m0 + mt * 16 + aRow) * ROWB + (ks * 16 + aK) * 2);
            uint32_t bf[4][4];
#pragma unroll
            for (int np = 0; np < 4; np++)
                ldsm4(bf[np], bH + (n0 + np * 16 + bN) * ROWB + (ks * 16 + bK) * 2);
#pragma unroll
            for (int mt = 0; mt < 2; mt++)
#pragma unroll
                for (int nt = 0; nt < 8; nt++)
                    mma16816h(acc[mt][nt], af[mt], &bf[nt >> 1][(nt & 1) * 2]);
        }
    }

    if (!g.headmajor) {
#pragma unroll
        for (int mt = 0; mt < 2; mt++)
#pragma unroll
            for (int nt = 0; nt < 8; nt++) {
                int row = bm + m0 + mt * 16 + (lane >> 2);
                int col = bn + n0 + nt * 8 + (lane & 3) * 2;
                *(float2*)(g.c + (size_t)row * 1024 + col) =
                    make_float2(acc[mt][nt][0], acc[mt][nt][1]);
                *(float2*)(g.c + (size_t)(row + 8) * 1024 + col) =
                    make_float2(acc[mt][nt][2], acc[mt][nt][3]);
            }
    } else {
        const float sc = g.oscale;
#pragma unroll
        for (int mt = 0; mt < 2; mt++)
#pragma unroll
            for (int nt = 0; nt < 8; nt++) {
                int row = bm + m0 + mt * 16 + (lane >> 2);
                int col = bn + n0 + nt * 8 + (lane & 3) * 2;
                int bb2 = row >> 11, s = row & 2047, hh = col >> 6, dh = col & 63;
                size_t dst = ((size_t)(bb2 * H_ + hh) * S_ + s) * 64 + dh;
#pragma unroll
                for (int half = 0; half < 2; half++) {
                    float x = acc[mt][nt][half * 2] * sc;
                    float y = acc[mt][nt][half * 2 + 1] * sc;
                    size_t d2 = dst + half * 8 * 64;
                    *(__half2*)(g.chi + d2) =
                        __halves2half2(__float2half_rn(x), __float2half_rn(y));
                }
            }
    }
}

// ================= tensor-core flash attention (warp-row-stripe FA2) =================
#define KROWB 144
#define KHBUF(st) ((st) * 18432)
#define VHBUF(st) (36864 + (st) * 18432)
#define OFF_QSTAGE VHBUF(1)
#define OFF_PM   73728     // float[2][128]
#define ATTN_SMEM 74752

__global__ __launch_bounds__(256, 1) void attn_tc(
    const __half* __restrict__ Qh,
    const __half* __restrict__ Kh,
    const __half* __restrict__ Vh,
    const int* __restrict__ mask,
    __half* __restrict__ ctx)
{
    extern __shared__ char sm[];
    const uint32_t sb = smem_to_u32(sm);
    const int qt = (gridDim.x - 1) - blockIdx.x;
    const int h = blockIdx.y, b = blockIdx.z;
    const int tid = threadIdx.x, lane = tid & 31, wid = tid >> 5;
    const int m0 = wid * 16;
    const int q0 = qt * 128;
    const size_t bh = (size_t)(b * H_ + h) * S_;

    float* pmm = (float*)(sm + OFF_PM);
    const int* mbase = mask + b * S_;

    auto load_tile = [&](int kt2, int st) {
        const int kk0 = kt2 * 128;
#pragma unroll
        for (int p = 0; p < 4; p++) {
            int i = tid + p * 256;
            int row = i >> 3, c16 = i & 7;
            cp16(sb + KHBUF(st) + row * KROWB + c16 * 16,
                 Kh + (bh + kk0 + row) * 64 + c16 * 8);
        }
#pragma unroll
        for (int p = 0; p < 4; p++) {
            int i = tid + p * 256;
            int row = i >> 3, c16 = i & 7;
            cp16(sb + VHBUF(st) + row * KROWB + c16 * 16,
                 Vh + (bh + kk0 + row) * 64 + c16 * 8);
        }
        CP_COMMIT();
    };

    // prologue
    load_tile(0, 0);
#pragma unroll
    for (int p = 0; p < 4; p++) {
        int i = tid + p * 256;
        int row = i >> 3, c16 = i & 7;
        cp16(sb + OFF_QSTAGE + row * KROWB + c16 * 16,
             Qh + (bh + q0 + row) * 64 + c16 * 8);
    }
    CP_COMMIT();
    if (tid < 128) pmm[tid] = (mbase[tid] == 0) ? NEGV : 0.0f;
    CP_WAIT0();
    __syncthreads();

    uint32_t qfh[4][4];
    {
        const uint32_t arow = lane & 15, akk = (lane >> 4) * 8;
#pragma unroll
        for (int kc = 0; kc < 4; kc++)
            ldsm4(qfh[kc], sb + OFF_QSTAGE + (m0 + arow) * KROWB + (kc * 16 + akk) * 2);
    }

    float accO[8][4];
#pragma unroll
    for (int nt = 0; nt < 8; nt++)
#pragma unroll
        for (int e = 0; e < 4; e++) accO[nt][e] = 0.0f;
    float mreg[2] = {-1e30f, -1e30f};
    float lreg[2] = {0.0f, 0.0f};

    const uint32_t bN = (lane & 7) + ((lane >> 4) & 1) * 8;
    const uint32_t bK = ((lane >> 3) & 1) * 8;
    const uint32_t arow = lane & 15, akk = (lane >> 4) * 8;

    for (int kt = 0; kt <= qt; kt++) {
        const int st = kt & 1;
        CP_WAIT0();
        __syncthreads();

        if (kt < qt) {
            load_tile(kt + 1, st ^ 1);
            if (tid < 128)
                pmm[(st ^ 1) * 128 + tid] =
                    (mbase[(kt + 1) * 128 + tid] == 0) ? NEGV : 0.0f;
        }

        // ---- QK ----
        float accS[16][4];
#pragma unroll
        for (int nt = 0; nt < 16; nt++)
#pragma unroll
            for (int e = 0; e < 4; e++) accS[nt][e] = 0.0f;

        const uint32_t kbase = sb + KHBUF(st);
#pragma unroll
        for (int kc = 0; kc < 4; kc++) {
            uint32_t bf[8][4];
#pragma unroll
            for (int np = 0; np < 8; np++)
                ldsm4(bf[np], kbase + (np * 16 + bN) * KROWB + (kc * 16 + bK) * 2);
#pragma unroll
            for (int nt = 0; nt < 16; nt++)
                mma16816h(accS[nt], qfh[kc], &bf[nt >> 1][(nt & 1) * 2]);
        }

        // ---- mask ----
        const bool diag = (kt == qt);
        const float* pmt = pmm + st * 128;
        const int r0 = m0 + (lane >> 2);
#pragma unroll
        for (int nt = 0; nt < 16; nt++) {
            int cl = nt * 8 + (lane & 3) * 2;
            float pm0 = pmt[cl], pm1 = pmt[cl + 1];
            accS[nt][0] += pm0; accS[nt][1] += pm1;
            accS[nt][2] += pm0; accS[nt][3] += pm1;
            if (diag) {
                if (cl     > r0)     accS[nt][0] = NEGV;
                if (cl + 1 > r0)     accS[nt][1] = NEGV;
                if (cl     > r0 + 8) accS[nt][2] = NEGV;
                if (cl + 1 > r0 + 8) accS[nt][3] = NEGV;
            }
        }

        // ---- warp-local softmax (exp2 domain) ----
        uint32_t pfrag[8][4];
#pragma unroll
        for (int hh = 0; hh < 2; hh++) {
            float mx = -1e30f;
#pragma unroll
            for (int nt = 0; nt < 16; nt++) {
                mx = fmaxf(mx, accS[nt][hh * 2]);
                mx = fmaxf(mx, accS[nt][hh * 2 + 1]);
            }
            mx = fmaxf(mx, __shfl_xor_sync(0xffffffff, mx, 1));
            mx = fmaxf(mx, __shfl_xor_sync(0xffffffff, mx, 2));
            mx = fmaxf(mx, mreg[hh]);
            float alpha = exp2f(mreg[hh] - mx);
            mreg[hh] = mx;
            float ps = 0.0f;
#pragma unroll
            for (int nt = 0; nt < 16; nt++) {
                float p0 = exp2f(accS[nt][hh * 2] - mx);
                float p1 = exp2f(accS[nt][hh * 2 + 1] - mx);
                ps += p0 + p1;
                __half2 ph = __halves2half2(__float2half_rn(p0), __float2half_rn(p1));
                pfrag[nt >> 1][(nt & 1) * 2 + hh] = reinterpret_cast<uint32_t&>(ph);
            }
            ps += __shfl_xor_sync(0xffffffff, ps, 1);
            ps += __shfl_xor_sync(0xffffffff, ps, 2);
            lreg[hh] = lreg[hh] * alpha + ps;
#pragma unroll
            for (int nt = 0; nt < 8; nt++) {
                accO[nt][hh * 2]     *= alpha;
                accO[nt][hh * 2 + 1] *= alpha;
            }
        }

        // ---- PV ----
        const uint32_t vbase = sb + VHBUF(st);
#pragma unroll
        for (int kc = 0; kc < 8; kc++) {
            uint32_t vf[4][4];
#pragma unroll
            for (int ng = 0; ng < 4; ng++)
                ldsm4_t(vf[ng], vbase + (kc * 16 + arow) * KROWB + (ng * 16 + akk) * 2);
#pragma unroll
            for (int nt = 0; nt < 8; nt++)
                mma16816h(accO[nt], pfrag[kc], &vf[nt >> 1][(nt & 1) * 2]);
        }
    }

    // ---- epilogue ----
#pragma unroll
    for (int hh = 0; hh < 2; hh++) {
        int rl = m0 + (lane >> 2) + hh * 8;
        float inv = 1.0f / lreg[hh];
        size_t orow = (size_t)(b * S_ + q0 + rl) * 1024 + h * 64;
#pragma unroll
        for (int nt = 0; nt < 8; nt++) {
            int cl = nt * 8 + (lane & 3) * 2;
            float x = accO[nt][hh * 2] * inv;
            float y = accO[nt][hh * 2 + 1] * inv;
            *(__half2*)(ctx + orow + cl) =
                __halves2half2(__float2half_rn(x), __float2half_rn(y));
        }
    }
}

// ================= launch =================
extern "C" void kernel_launch(void* const* d_in, const int* in_sizes, int n_in,
                              void* d_out, int out_size)
{
    const float* q    = (const float*)d_in[0];
    const float* k    = (const float*)d_in[1];
    const float* v    = (const float*)d_in[2];
    const int*   mask = (const int*)d_in[3];
    const float* Wq   = (const float*)d_in[4];
    const float* Wk   = (const float*)d_in[5];
    const float* Wv   = (const float*)d_in[6];
    const float* Wo   = (const float*)d_in[7];
    float* out = (float*)d_out;

    const int ME = B_ * S_ * D_;
    const int WE = D_ * D_;

    float *gQ, *gK, *gV, *gctx;
    cudaGetSymbolAddress((void**)&gQ,  g_Q);
    cudaGetSymbolAddress((void**)&gK,  g_K);
    cudaGetSymbolAddress((void**)&gV,  g_V);
    cudaGetSymbolAddress((void**)&gctx, g_ctx);
    __half* Qhd = (__half*)gQ;
    __half* Khd = (__half*)gK;
    __half* Vhd = (__half*)gV;
    __half* Chd = (__half*)gctx;

    __half *qf, *kf, *vf, *wq, *wk, *wv, *wo;
    cudaGetSymbolAddress((void**)&qf, g_qhi);
    cudaGetSymbolAddress((void**)&kf, g_khi);
    cudaGetSymbolAddress((void**)&vf, g_vhi);
    cudaGetSymbolAddress((void**)&wq, g_wqhi);
    cudaGetSymbolAddress((void**)&wk, g_wkhi);
    cudaGetSymbolAddress((void**)&wv, g_wvhi);
    cudaGetSymbolAddress((void**)&wo, g_wohi);

    {
        CastArgs a0{q, qf}, a1{k, kf}, a2{v, vf};
        dim3 gr(ME / 1024, 1, 3);
        convert_f16_3<<<gr, 256>>>(a0, a1, a2);
    }
    {
        CastArgs a0{Wq, wq}, a1{Wk, wk}, a2{Wv, wv}, a3{Wo, wo};
        dim3 gr(WE / 1024, 1, 4);
        convert_f16_4<<<gr, 256>>>(a0, a1, a2, a3);
    }

    cudaFuncSetAttribute(gemm_mma, cudaFuncAttributeMaxDynamicSharedMemorySize,
                         GEMM_SMEM_BYTES);

    {
        // Q scaled by 0.125 * log2(e) -> softmax in exp2 domain
        GemmArgs g0{qf, wq, nullptr, Qhd, 1, 0.1803368801111244f};
        GemmArgs g1{kf, wk, nullptr, Khd, 1, 1.0f};
        GemmArgs g2{vf, wv, nullptr, Vhd, 1, 1.0f};
        dim3 gr(D_ / 128, (B_ * S_) / 128, 3);
        gemm_mma<<<gr, 256, GEMM_SMEM_BYTES>>>(g0, g1, g2);
    }

    {
        cudaFuncSetAttribute(attn_tc, cudaFuncAttributeMaxDynamicSharedMemorySize,
                             ATTN_SMEM);
        dim3 ga(S_ / 128, H_, B_);
        attn_tc<<<ga, 256, ATTN_SMEM>>>(Qhd, Khd, Vhd, mask, Chd);
    }

    {
        GemmArgs g0{Chd, wo, out, nullptr, 0, 1.0f};
        dim3 gr(D_ / 128, (B_ * S_) / 128, 1);
        gemm_mma<<<gr, 256, GEMM_SMEM_BYTES>>>(g0, g0, g0);
    }
}

// round 17
// speedup vs baseline: 8.1691x; 1.0261x over previous
#include <cuda_runtime.h>
#include <cuda_bf16.h>
#include <cuda_fp16.h>
#include <cstdint>
#include <math.h>

#define B_  2
#define S_  2048
#define D_  1024
#define H_  16
#define DH_ 64
#define NEGV -1000000000.0f

// ================= helpers =================
__device__ __forceinline__ uint32_t smem_to_u32(const void* p) {
    uint32_t a;
    asm("{ .reg .u64 t; cvta.to.shared.u64 t, %1; cvt.u32.u64 %0, t; }"
        : "=r"(a) : "l"(p));
    return a;
}
__device__ __forceinline__ void ldsm4(uint32_t* r, uint32_t addr) {
    asm volatile("ldmatrix.sync.aligned.m8n8.x4.shared.b16 {%0,%1,%2,%3}, [%4];"
        : "=r"(r[0]), "=r"(r[1]), "=r"(r[2]), "=r"(r[3]) : "r"(addr));
}
__device__ __forceinline__ void ldsm4_t(uint32_t* r, uint32_t addr) {
    asm volatile("ldmatrix.sync.aligned.m8n8.x4.trans.shared.b16 {%0,%1,%2,%3}, [%4];"
        : "=r"(r[0]), "=r"(r[1]), "=r"(r[2]), "=r"(r[3]) : "r"(addr));
}
__device__ __forceinline__ void mma16816h(float* d, const uint32_t* a, const uint32_t* b) {
    asm volatile("mma.sync.aligned.m16n8k16.row.col.f32.f16.f16.f32 "
        "{%0,%1,%2,%3}, {%4,%5,%6,%7}, {%8,%9}, {%0,%1,%2,%3};"
        : "+f"(d[0]), "+f"(d[1]), "+f"(d[2]), "+f"(d[3])
        : "r"(a[0]), "r"(a[1]), "r"(a[2]), "r"(a[3]), "r"(b[0]), "r"(b[1]));
}
__device__ __forceinline__ void cp16(uint32_t smem, const void* g) {
    asm volatile("cp.async.cg.shared.global [%0], [%1], 16;" :: "r"(smem), "l"(g));
}
#define CP_COMMIT() asm volatile("cp.async.commit_group;" ::: "memory")
#define CP_WAIT0()  asm volatile("cp.async.wait_group 0;" ::: "memory")

// ================= scratch =================
__device__ float g_Q[B_ * S_ * D_];
__device__ float g_K[B_ * S_ * D_];
__device__ float g_V[B_ * S_ * D_];
__device__ float g_ctx[B_ * S_ * D_];

__device__ __nv_bfloat16 g_qhi[B_ * S_ * D_];
__device__ __nv_bfloat16 g_khi[B_ * S_ * D_];
__device__ __nv_bfloat16 g_vhi[B_ * S_ * D_];
__device__ __nv_bfloat16 g_wqhi[D_ * D_];
__device__ __nv_bfloat16 g_wkhi[D_ * D_];
__device__ __nv_bfloat16 g_wvhi[D_ * D_];
__device__ __nv_bfloat16 g_wohi[D_ * D_];

// ================= fp32 -> fp16 cast =================
struct CastArgs { const float* s; __half* d; };

__global__ __launch_bounds__(256) void convert_f16_3(CastArgs a0, CastArgs a1, CastArgs a2) {
    CastArgs a = (blockIdx.z == 0) ? a0 : (blockIdx.z == 1) ? a1 : a2;
    size_t i4 = (size_t)blockIdx.x * 256 + threadIdx.x;
    float4 x = ((const float4*)a.s)[i4];
    __half2 p0 = __halves2half2(__float2half_rn(x.x), __float2half_rn(x.y));
    __half2 p1 = __halves2half2(__float2half_rn(x.z), __float2half_rn(x.w));
    uint2 v;
    v.x = reinterpret_cast<uint32_t&>(p0); v.y = reinterpret_cast<uint32_t&>(p1);
    ((uint2*)a.d)[i4] = v;
}

__global__ __launch_bounds__(256) void convert_f16_4(CastArgs a0, CastArgs a1,
                                                     CastArgs a2, CastArgs a3) {
    CastArgs a = (blockIdx.z == 0) ? a0 : (blockIdx.z == 1) ? a1
               : (blockIdx.z == 2) ? a2 : a3;
    size_t i4 = (size_t)blockIdx.x * 256 + threadIdx.x;
    float4 x = ((const float4*)a.s)[i4];
    __half2 p0 = __halves2half2(__float2half_rn(x.x), __float2half_rn(x.y));
    __half2 p1 = __halves2half2(__float2half_rn(x.z), __float2half_rn(x.w));
    uint2 v;
    v.x = reinterpret_cast<uint32_t&>(p0); v.y = reinterpret_cast<uint32_t&>(p1);
    ((uint2*)a.d)[i4] = v;
}

// ================= mma.sync GEMM (pure fp16, 1 pass) =================
struct GemmArgs {
    const __half *ah, *bh;
    float* c;
    __half *chi;
    int headmajor;
    float oscale;
};

#define GEMM_SMEM_BYTES (2 * 2 * 10240)
#define ROWB 80

__global__ __launch_bounds__(256, 2) void gemm_mma(GemmArgs ga0, GemmArgs ga1, GemmArgs ga2) {
    extern __shared__ char smx[];
    const GemmArgs g = (blockIdx.z == 0) ? ga0 : (blockIdx.z == 1) ? ga1 : ga2;

    const int tid  = threadIdx.x;
    const int lane = tid & 31;
    const int wid  = tid >> 5;
    const int bm = blockIdx.y * 128;
    const int bn = blockIdx.x * 128;
    const uint32_t sbase = smem_to_u32(smx);

    const int m0 = (wid >> 1) * 32;
    const int n0 = (wid & 1) * 64;

    float acc[2][8][4];
#pragma unroll
    for (int mt = 0; mt < 2; mt++)
#pragma unroll
        for (int nt = 0; nt < 8; nt++)
#pragma unroll
            for (int i = 0; i < 4; i++) acc[mt][nt][i] = 0.0f;

    const uint32_t aRow = lane & 15;
    const uint32_t aK   = (lane >> 4) * 8;
    const uint32_t bN   = (lane & 7) + ((lane >> 4) & 1) * 8;
    const uint32_t bK   = ((lane >> 3) & 1) * 8;

    auto load_chunk = [&](int c, int st) {
        const int k0 = c * 32;
#pragma unroll
        for (int p = 0; p < 4; p++) {
            int idx = tid + p * 256;
            int arr = idx >> 9;
            int r   = (idx >> 2) & 127;
            int c8  = (idx & 3) * 8;
            const __half* src = (arr == 0) ? g.ah : g.bh;
            int grow = ((arr == 0) ? bm : bn) + r;
            cp16(sbase + (uint32_t)(st * 2 + arr) * 10240 + r * ROWB + c8 * 2,
                 src + (size_t)grow * 1024 + k0 + c8);
        }
        CP_COMMIT();
    };

    load_chunk(0, 0);

    for (int c = 0; c < 32; c++) {
        const int st = c & 1;
        CP_WAIT0();
        __syncthreads();
        if (c < 31) load_chunk(c + 1, st ^ 1);

        const uint32_t aH = sbase + (uint32_t)(st * 2) * 10240;
        const uint32_t bH = aH + 10240;

#pragma unroll
        for (int ks = 0; ks < 2; ks++) {
            uint32_t af[2][4];
#pragma unroll
            for (int mt = 0; mt < 2; mt++)
                ldsm4(af[mt], aH + (m0 + mt * 16 + aRow) * ROWB + (ks * 16 + aK) * 2);
            uint32_t bf[4][4];
#pragma unroll
            for (int np = 0; np < 4; np++)
                ldsm4(bf[np], bH + (n0 + np * 16 + bN) * ROWB + (ks * 16 + bK) * 2);
#pragma unroll
            for (int mt = 0; mt < 2; mt++)
#pragma unroll
                for (int nt = 0; nt < 8; nt++)
                    mma16816h(acc[mt][nt], af[mt], &bf[nt >> 1][(nt & 1) * 2]);
        }
    }

    if (!g.headmajor) {
#pragma unroll
        for (int mt = 0; mt < 2; mt++)
#pragma unroll
            for (int nt = 0; nt < 8; nt++) {
                int row = bm + m0 + mt * 16 + (lane >> 2);
                int col = bn + n0 + nt * 8 + (lane & 3) * 2;
                *(float2*)(g.c + (size_t)row * 1024 + col) =
                    make_float2(acc[mt][nt][0], acc[mt][nt][1]);
                *(float2*)(g.c + (size_t)(row + 8) * 1024 + col) =
                    make_float2(acc[mt][nt][2], acc[mt][nt][3]);
            }
    } else {
        const float sc = g.oscale;
#pragma unroll
        for (int mt = 0; mt < 2; mt++)
#pragma unroll
            for (int nt = 0; nt < 8; nt++) {
                int row = bm + m0 + mt * 16 + (lane >> 2);
                int col = bn + n0 + nt * 8 + (lane & 3) * 2;
                int bb2 = row >> 11, s = row & 2047, hh = col >> 6, dh = col & 63;
                size_t dst = ((size_t)(bb2 * H_ + hh) * S_ + s) * 64 + dh;
#pragma unroll
                for (int half = 0; half < 2; half++) {
                    float x = acc[mt][nt][half * 2] * sc;
                    float y = acc[mt][nt][half * 2 + 1] * sc;
                    size_t d2 = dst + half * 8 * 64;
                    *(__half2*)(g.chi + d2) =
                        __halves2half2(__float2half_rn(x), __float2half_rn(y));
                }
            }
    }
}

// ================= tensor-core flash attention =================
// 128 threads (4 warps), q-tile 64, k-tile 128; 2 CTAs/SM so softmax of one
// CTA overlaps MMA of the other. Warp-local softmax, register P, exp2 domain.
#define KROWB 144
#define KHBUF(st) ((st) * 18432)
#define VHBUF(st) (36864 + (st) * 18432)
#define OFF_QSTAGE VHBUF(1)
#define OFF_PM   73728     // float[2][128]
#define ATTN_SMEM 74752

__global__ __launch_bounds__(128, 2) void attn_tc(
    const __half* __restrict__ Qh,
    const __half* __restrict__ Kh,
    const __half* __restrict__ Vh,
    const int* __restrict__ mask,
    __half* __restrict__ ctx)
{
    extern __shared__ char sm[];
    const uint32_t sb = smem_to_u32(sm);
    const int qt = (gridDim.x - 1) - blockIdx.x;   // heavy first
    const int h = blockIdx.y, b = blockIdx.z;
    const int tid = threadIdx.x, lane = tid & 31, wid = tid >> 5;
    const int m0 = wid * 16;            // this warp's 16 q-rows (of 64)
    const int q0 = qt * 64;
    const int n_kt = ((q0 + 63) >> 7) + 1;
    const size_t bh = (size_t)(b * H_ + h) * S_;

    float* pmm = (float*)(sm + OFF_PM);
    const int* mbase = mask + b * S_;

    auto load_tile = [&](int kt2, int st) {
        const int kk0 = kt2 * 128;
#pragma unroll
        for (int p = 0; p < 8; p++) {
            int i = tid + p * 128;
            int row = i >> 3, c16 = i & 7;
            cp16(sb + KHBUF(st) + row * KROWB + c16 * 16,
                 Kh + (bh + kk0 + row) * 64 + c16 * 8);
        }
#pragma unroll
        for (int p = 0; p < 8; p++) {
            int i = tid + p * 128;
            int row = i >> 3, c16 = i & 7;
            cp16(sb + VHBUF(st) + row * KROWB + c16 * 16,
                 Vh + (bh + kk0 + row) * 64 + c16 * 8);
        }
        CP_COMMIT();
    };

    // prologue: tile 0 + Q stage (64 rows)
    load_tile(0, 0);
#pragma unroll
    for (int p = 0; p < 4; p++) {
        int i = tid + p * 128;
        int row = i >> 3, c16 = i & 7;
        cp16(sb + OFF_QSTAGE + row * KROWB + c16 * 16,
             Qh + (bh + q0 + row) * 64 + c16 * 8);
    }
    CP_COMMIT();
    pmm[tid] = (mbase[tid] == 0) ? NEGV : 0.0f;
    CP_WAIT0();
    __syncthreads();

    uint32_t qfh[4][4];
    {
        const uint32_t arow = lane & 15, akk = (lane >> 4) * 8;
#pragma unroll
        for (int kc = 0; kc < 4; kc++)
            ldsm4(qfh[kc], sb + OFF_QSTAGE + (m0 + arow) * KROWB + (kc * 16 + akk) * 2);
    }

    float accO[8][4];
#pragma unroll
    for (int nt = 0; nt < 8; nt++)
#pragma unroll
        for (int e = 0; e < 4; e++) accO[nt][e] = 0.0f;
    float mreg[2] = {-1e30f, -1e30f};
    float lreg[2] = {0.0f, 0.0f};

    const uint32_t bN = (lane & 7) + ((lane >> 4) & 1) * 8;
    const uint32_t bK = ((lane >> 3) & 1) * 8;
    const uint32_t arow = lane & 15, akk = (lane >> 4) * 8;

    for (int kt = 0; kt < n_kt; kt++) {
        const int st = kt & 1;
        const int km = kt * 128;
        CP_WAIT0();
        __syncthreads();

        if (kt + 1 < n_kt) {
            load_tile(kt + 1, st ^ 1);
            pmm[(st ^ 1) * 128 + tid] =
                (mbase[(kt + 1) * 128 + tid] == 0) ? NEGV : 0.0f;
        }

        // ---- QK ----
        float accS[16][4];
#pragma unroll
        for (int nt = 0; nt < 16; nt++)
#pragma unroll
            for (int e = 0; e < 4; e++) accS[nt][e] = 0.0f;

        const uint32_t kbase = sb + KHBUF(st);
#pragma unroll
        for (int kc = 0; kc < 4; kc++) {
            uint32_t bf[8][4];
#pragma unroll
            for (int np = 0; np < 8; np++)
                ldsm4(bf[np], kbase + (np * 16 + bN) * KROWB + (kc * 16 + bK) * 2);
#pragma unroll
            for (int nt = 0; nt < 16; nt++)
                mma16816h(accS[nt], qfh[kc], &bf[nt >> 1][(nt & 1) * 2]);
        }

        // ---- mask (global indices: key km+cl vs query q0+row) ----
        const bool diag = (km + 127 > q0);
        const float* pmt = pmm + st * 128;
        const int rg = q0 + m0 + (lane >> 2);
#pragma unroll
        for (int nt = 0; nt < 16; nt++) {
            int cl = nt * 8 + (lane & 3) * 2;
            float pm0 = pmt[cl], pm1 = pmt[cl + 1];
            accS[nt][0] += pm0; accS[nt][1] += pm1;
            accS[nt][2] += pm0; accS[nt][3] += pm1;
            if (diag) {
                int kg = km + cl;
                if (kg     > rg)     accS[nt][0] = NEGV;
                if (kg + 1 > rg)     accS[nt][1] = NEGV;
                if (kg     > rg + 8) accS[nt][2] = NEGV;
                if (kg + 1 > rg + 8) accS[nt][3] = NEGV;
            }
        }

        // ---- warp-local softmax (exp2 domain) ----
        uint32_t pfrag[8][4];
#pragma unroll
        for (int hh = 0; hh < 2; hh++) {
            float mx = -1e30f;
#pragma unroll
            for (int nt = 0; nt < 16; nt++) {
                mx = fmaxf(mx, accS[nt][hh * 2]);
                mx = fmaxf(mx, accS[nt][hh * 2 + 1]);
            }
            mx = fmaxf(mx, __shfl_xor_sync(0xffffffff, mx, 1));
            mx = fmaxf(mx, __shfl_xor_sync(0xffffffff, mx, 2));
            mx = fmaxf(mx, mreg[hh]);
            float alpha = exp2f(mreg[hh] - mx);
            mreg[hh] = mx;
            float ps = 0.0f;
#pragma unroll
            for (int nt = 0; nt < 16; nt++) {
                float p0 = exp2f(accS[nt][hh * 2] - mx);
                float p1 = exp2f(accS[nt][hh * 2 + 1] - mx);
                ps += p0 + p1;
                __half2 ph = __halves2half2(__float2half_rn(p0), __float2half_rn(p1));
                pfrag[nt >> 1][(nt & 1) * 2 + hh] = reinterpret_cast<uint32_t&>(ph);
            }
            ps += __shfl_xor_sync(0xffffffff, ps, 1);
            ps += __shfl_xor_sync(0xffffffff, ps, 2);
            lreg[hh] = lreg[hh] * alpha + ps;
#pragma unroll
            for (int nt = 0; nt < 8; nt++) {
                accO[nt][hh * 2]     *= alpha;
                accO[nt][hh * 2 + 1] *= alpha;
            }
        }

        // ---- PV ----
        const uint32_t vbase = sb + VHBUF(st);
#pragma unroll
        for (int kc = 0; kc < 8; kc++) {
            uint32_t vf[4][4];
#pragma unroll
            for (int ng = 0; ng < 4; ng++)
                ldsm4_t(vf[ng], vbase + (kc * 16 + arow) * KROWB + (ng * 16 + akk) * 2);
#pragma unroll
            for (int nt = 0; nt < 8; nt++)
                mma16816h(accO[nt], pfrag[kc], &vf[nt >> 1][(nt & 1) * 2]);
        }
    }

    // ---- epilogue ----
#pragma unroll
    for (int hh = 0; hh < 2; hh++) {
        int rl = m0 + (lane >> 2) + hh * 8;
        float inv = 1.0f / lreg[hh];
        size_t orow = (size_t)(b * S_ + q0 + rl) * 1024 + h * 64;
#pragma unroll
        for (int nt = 0; nt < 8; nt++) {
            int cl = nt * 8 + (lane & 3) * 2;
            float x = accO[nt][hh * 2] * inv;
            float y = accO[nt][hh * 2 + 1] * inv;
            *(__half2*)(ctx + orow + cl) =
                __halves2half2(__float2half_rn(x), __float2half_rn(y));
        }
    }
}

// ================= launch =================
extern "C" void kernel_launch(void* const* d_in, const int* in_sizes, int n_in,
                              void* d_out, int out_size)
{
    const float* q    = (const float*)d_in[0];
    const float* k    = (const float*)d_in[1];
    const float* v    = (const float*)d_in[2];
    const int*   mask = (const int*)d_in[3];
    const float* Wq   = (const float*)d_in[4];
    const float* Wk   = (const float*)d_in[5];
    const float* Wv   = (const float*)d_in[6];
    const float* Wo   = (const float*)d_in[7];
    float* out = (float*)d_out;

    const int ME = B_ * S_ * D_;
    const int WE = D_ * D_;

    float *gQ, *gK, *gV, *gctx;
    cudaGetSymbolAddress((void**)&gQ,  g_Q);
    cudaGetSymbolAddress((void**)&gK,  g_K);
    cudaGetSymbolAddress((void**)&gV,  g_V);
    cudaGetSymbolAddress((void**)&gctx, g_ctx);
    __half* Qhd = (__half*)gQ;
    __half* Khd = (__half*)gK;
    __half* Vhd = (__half*)gV;
    __half* Chd = (__half*)gctx;

    __half *qf, *kf, *vf, *wq, *wk, *wv, *wo;
    cudaGetSymbolAddress((void**)&qf, g_qhi);
    cudaGetSymbolAddress((void**)&kf, g_khi);
    cudaGetSymbolAddress((void**)&vf, g_vhi);
    cudaGetSymbolAddress((void**)&wq, g_wqhi);
    cudaGetSymbolAddress((void**)&wk, g_wkhi);
    cudaGetSymbolAddress((void**)&wv, g_wvhi);
    cudaGetSymbolAddress((void**)&wo, g_wohi);

    {
        CastArgs a0{q, qf}, a1{k, kf}, a2{v, vf};
        dim3 gr(ME / 1024, 1, 3);
        convert_f16_3<<<gr, 256>>>(a0, a1, a2);
    }
    {
        CastArgs a0{Wq, wq}, a1{Wk, wk}, a2{Wv, wv}, a3{Wo, wo};
        dim3 gr(WE / 1024, 1, 4);
        convert_f16_4<<<gr, 256>>>(a0, a1, a2, a3);
    }

    cudaFuncSetAttribute(gemm_mma, cudaFuncAttributeMaxDynamicSharedMemorySize,
                         GEMM_SMEM_BYTES);

    {
        // Q scaled by 0.125 * log2(e) -> softmax in exp2 domain
        GemmArgs g0{qf, wq, nullptr, Qhd, 1, 0.1803368801111244f};
        GemmArgs g1{kf, wk, nullptr, Khd, 1, 1.0f};
        GemmArgs g2{vf, wv, nullptr, Vhd, 1, 1.0f};
        dim3 gr(D_ / 128, (B_ * S_) / 128, 3);
        gemm_mma<<<gr, 256, GEMM_SMEM_BYTES>>>(g0, g1, g2);
    }

    {
        cudaFuncSetAttribute(attn_tc, cudaFuncAttributeMaxDynamicSharedMemorySize,
                             ATTN_SMEM);
        dim3 ga(S_ / 64, H_, B_);
        attn_tc<<<ga, 128, ATTN_SMEM>>>(Qhd, Khd, Vhd, mask, Chd);
    }

    {
        GemmArgs g0{Chd, wo, out, nullptr, 0, 1.0f};
        dim3 gr(D_ / 128, (B_ * S_) / 128, 1);
        gemm_mma<<<gr, 256, GEMM_SMEM_BYTES>>>(g0, g0, g0);
    }
}